// round 3
// baseline (speedup 1.0000x reference)
#include <cuda_runtime.h>
#include <math.h>
#include <stdint.h>

// ---------------------------------------------------------------------------
// Problem constants (Qwen3.5 GatedDeltaNet): B=2, T=4096, D=2048
// ---------------------------------------------------------------------------
#define BATCH   2
#define TLEN    4096
#define BT      8192
#define DMODEL  2048
#define NVH     32
#define NKH     16
#define DK      128
#define DV      128
#define KEYDIM  (NKH*DK)                 // 2048
#define VALDIM  (NVH*DV)                 // 4096
#define CONVDIM (2*KEYDIM + VALDIM)      // 8192

// ---------------------------------------------------------------------------
// Scratch (static device globals)
// ---------------------------------------------------------------------------
__device__ float g_mixed[(size_t)BT * CONVDIM];
__device__ float g_q[(size_t)BT * KEYDIM];
__device__ float g_k[(size_t)BT * KEYDIM];
__device__ float g_v[(size_t)BT * VALDIM];
__device__ float g_z[(size_t)BT * VALDIM];
__device__ float g_ba[BT * 64];
__device__ float g_beta[BT * NVH];
__device__ float g_decay[BT * NVH];
__device__ float g_o[(size_t)BT * VALDIM];
// tf32-rounded operands
__device__ float g_hs_t[(size_t)BT * DMODEL];
__device__ float g_wqkv_t[(size_t)DMODEL * CONVDIM];
__device__ float g_wz_t[(size_t)DMODEL * VALDIM];
__device__ float g_wout_t[(size_t)VALDIM * DMODEL];
__device__ float g_wba_t[DMODEL * 64];

__device__ __forceinline__ float f2tf_f(float x) {
    uint32_t r; asm("cvt.rna.tf32.f32 %0, %1;" : "=r"(r) : "f"(x));
    return __uint_as_float(r);
}

// ---------------------------------------------------------------------------
// TF32 tensor-core GEMM: C[M,N] = A[M,K] @ B[K,N], row-major.
// A and B must be pre-rounded to tf32. 128x128x16 tile, 256 thr, 4-stage cp.async.
// A smem: LDA_S=20 pad (conflict-free frag reads).
// B smem: 128-wide rows, float4 chunk XOR-3 swizzle (<=2-way frag reads).
// ---------------------------------------------------------------------------
#define TSTAGES 4
#define TBM 128
#define TBN 128
#define TBK 16
#define LDA_S 20
#define A_STAGE (TBM*LDA_S)   // 2560 floats
#define B_STAGE (TBK*TBN)     // 2048 floats
#define GEMM_SMEM (TSTAGES*(A_STAGE+B_STAGE)*4)   // 73728 bytes

__device__ __forceinline__ void cp16(float* dst, const float* src, bool pred) {
    uint32_t d = (uint32_t)__cvta_generic_to_shared(dst);
    int sz = pred ? 16 : 0;
    asm volatile("cp.async.cg.shared.global [%0], [%1], 16, %2;\n"
                 :: "r"(d), "l"(src), "r"(sz));
}

__device__ __forceinline__ void mma_tf32(float* c, const uint32_t* a, const uint32_t* b) {
    asm volatile(
        "mma.sync.aligned.m16n8k8.row.col.f32.tf32.tf32.f32 "
        "{%0,%1,%2,%3}, {%4,%5,%6,%7}, {%8,%9}, {%0,%1,%2,%3};"
        : "+f"(c[0]), "+f"(c[1]), "+f"(c[2]), "+f"(c[3])
        : "r"(a[0]), "r"(a[1]), "r"(a[2]), "r"(a[3]), "r"(b[0]), "r"(b[1]));
}

__global__ __launch_bounds__(256, 2) void gemm_tf32_kernel(
    const float* __restrict__ A, const float* __restrict__ B,
    float* __restrict__ C, int M, int N, int K)
{
    extern __shared__ float smem[];
    float* As = smem;
    float* Bs = smem + TSTAGES * A_STAGE;

    const int tid  = threadIdx.x;
    const int bm   = blockIdx.y;
    const int bn   = blockIdx.x;
    const int warp = tid >> 5;
    const int lane = tid & 31;
    const int g    = lane >> 2;
    const int tig  = lane & 3;
    const int wm   = (warp >> 2) * 64;
    const int wn   = (warp & 3) * 32;

    float acc[4][4][4];
#pragma unroll
    for (int i = 0; i < 4; i++)
#pragma unroll
        for (int j = 0; j < 4; j++)
#pragma unroll
            for (int r = 0; r < 4; r++) acc[i][j][r] = 0.f;

    const int KT = K / TBK;

    auto load_stage = [&](int s, int kt) {
        float* as = As + s * A_STAGE;
        float* bs = Bs + s * B_STAGE;
#pragma unroll
        for (int h = 0; h < 2; h++) {           // A: 128 rows x 4 float4
            int id  = tid + h * 256;
            int row = id >> 2, c = id & 3;
            const float* src = A + (size_t)(bm * TBM + row) * K + kt * TBK + c * 4;
            cp16(as + row * LDA_S + c * 4, src, true);
        }
#pragma unroll
        for (int h = 0; h < 2; h++) {           // B: 16 rows x 32 float4, XOR swizzle
            int id  = tid + h * 256;
            int row = id >> 5, c = id & 31;
            int col = bn * TBN + c * 4;
            bool ok = col < N;
            const float* src = B + (size_t)(kt * TBK + row) * N + (ok ? col : 0);
            int cs = c ^ (row & 7);
            cp16(bs + row * TBN + cs * 4, src, ok);
        }
        asm volatile("cp.async.commit_group;");
    };

    load_stage(0, 0);
    load_stage(1, 1);
    load_stage(2, 2);

    for (int kt = 0; kt < KT; kt++) {
        asm volatile("cp.async.wait_group 2;");
        __syncthreads();

        if (kt + 3 < KT) load_stage((kt + 3) % TSTAGES, kt + 3);
        else             asm volatile("cp.async.commit_group;");

        const float* as = As + (kt % TSTAGES) * A_STAGE;
        const float* bs = Bs + (kt % TSTAGES) * B_STAGE;

#pragma unroll
        for (int kk = 0; kk < 2; kk++) {
            const int k0 = kk * 8;
            uint32_t af[4][4], bf[4][2];
#pragma unroll
            for (int i = 0; i < 4; i++) {
                int r0 = wm + 16 * i + g;
                af[i][0] = *(const uint32_t*)&as[(r0    ) * LDA_S + k0 + tig    ];
                af[i][1] = *(const uint32_t*)&as[(r0 + 8) * LDA_S + k0 + tig    ];
                af[i][2] = *(const uint32_t*)&as[(r0    ) * LDA_S + k0 + tig + 4];
                af[i][3] = *(const uint32_t*)&as[(r0 + 8) * LDA_S + k0 + tig + 4];
            }
#pragma unroll
            for (int j = 0; j < 4; j++) {
                int n  = wn + 8 * j + g;
                int k0a = k0 + tig;         // (k&7) == tig for k0 in {0,8}
                int k0b = k0 + tig + 4;     // (k&7) == tig+4
                int ca = ((n >> 2) ^ tig) * 4 + (n & 3);
                int cb = ((n >> 2) ^ (tig + 4)) * 4 + (n & 3);
                bf[j][0] = *(const uint32_t*)&bs[k0a * TBN + ca];
                bf[j][1] = *(const uint32_t*)&bs[k0b * TBN + cb];
            }
#pragma unroll
            for (int i = 0; i < 4; i++)
#pragma unroll
                for (int j = 0; j < 4; j++)
                    mma_tf32(acc[i][j], af[i], bf[j]);
        }
    }

#pragma unroll
    for (int i = 0; i < 4; i++) {
        int r0 = bm * TBM + wm + 16 * i + g;
#pragma unroll
        for (int j = 0; j < 4; j++) {
            int cn = bn * TBN + wn + 8 * j + 2 * tig;
            if (cn < N) {
                *(float2*)(C + (size_t)r0 * N + cn)       = make_float2(acc[i][j][0], acc[i][j][1]);
                *(float2*)(C + (size_t)(r0 + 8) * N + cn) = make_float2(acc[i][j][2], acc[i][j][3]);
            }
        }
    }
}

static inline void launch_gemm(const float* A, const float* B, float* C,
                               int M, int N, int K)
{
    dim3 grid((N + TBN - 1) / TBN, M / TBM);
    gemm_tf32_kernel<<<grid, 256, GEMM_SMEM>>>(A, B, C, M, N, K);
}

// ---------------------------------------------------------------------------
// Elementwise tf32 rounding pre-pass (float4 vectorized)
// ---------------------------------------------------------------------------
__global__ void cvt_tf32_kernel(const float* __restrict__ src,
                                float* __restrict__ dst, size_t n4)
{
    size_t i = (size_t)blockIdx.x * blockDim.x + threadIdx.x;
    if (i >= n4) return;
    float4 x = ((const float4*)src)[i];
    x.x = f2tf_f(x.x); x.y = f2tf_f(x.y); x.z = f2tf_f(x.z); x.w = f2tf_f(x.w);
    ((float4*)dst)[i] = x;
}

// Pack W_b|W_a into [DMODEL, 64], tf32-rounded
__global__ void pack_wba_kernel(const float* __restrict__ Wb,
                                const float* __restrict__ Wa,
                                float* __restrict__ Wba)
{
    int idx = blockIdx.x * blockDim.x + threadIdx.x;
    if (idx >= DMODEL * 64) return;
    int k = idx >> 6, j = idx & 63;
    float v = (j < 32) ? Wb[k * 32 + j] : Wa[k * 32 + (j - 32)];
    Wba[idx] = f2tf_f(v);
}

// ---------------------------------------------------------------------------
// Causal depthwise conv (KC=4) + SiLU + split into q/k/v
// ---------------------------------------------------------------------------
__global__ void conv_silu_split_kernel(const float* __restrict__ mixed,
                                       const float* __restrict__ conv_w,
                                       float* __restrict__ q,
                                       float* __restrict__ k,
                                       float* __restrict__ v)
{
    size_t idx = (size_t)blockIdx.x * blockDim.x + threadIdx.x;
    if (idx >= (size_t)BT * CONVDIM) return;
    int c = (int)(idx & (CONVDIM - 1));
    size_t bt = idx >> 13;
    int t = (int)(bt & (TLEN - 1));

    float4 w = *(const float4*)(conv_w + (size_t)c * 4);
    const float* base = mixed + c;
    float x0 = (t >= 3) ? base[(bt - 3) * CONVDIM] : 0.f;
    float x1 = (t >= 2) ? base[(bt - 2) * CONVDIM] : 0.f;
    float x2 = (t >= 1) ? base[(bt - 1) * CONVDIM] : 0.f;
    float x3 = base[bt * CONVDIM];

    float acc = x0 * w.x + x1 * w.y + x2 * w.z + x3 * w.w;
    float s = acc / (1.f + expf(-acc));

    if (c < KEYDIM)           q[bt * KEYDIM + c] = s;
    else if (c < 2 * KEYDIM)  k[bt * KEYDIM + (c - KEYDIM)] = s;
    else                      v[bt * VALDIM + (c - 2 * KEYDIM)] = s;
}

// ---------------------------------------------------------------------------
// L2 norm over DK=128 (one warp per row); q gets extra DK^-0.5
// ---------------------------------------------------------------------------
__global__ void l2norm_qk_kernel(float* __restrict__ q, float* __restrict__ k)
{
    int wg   = (blockIdx.x * blockDim.x + threadIdx.x) >> 5;
    int lane = threadIdx.x & 31;
    const int nrows = BT * NKH;
    if (wg >= 2 * nrows) return;

    float* base;
    float extra;
    if (wg < nrows) { base = q + (size_t)wg * DK; extra = 0.08838834764831845f; }
    else            { base = k + (size_t)(wg - nrows) * DK; extra = 1.f; }

    float4 x = ((float4*)base)[lane];
    float ss = x.x*x.x + x.y*x.y + x.z*x.z + x.w*x.w;
#pragma unroll
    for (int off = 16; off > 0; off >>= 1)
        ss += __shfl_xor_sync(0xffffffffu, ss, off);
    float inv = rsqrtf(ss + 1e-6f) * extra;
    x.x *= inv; x.y *= inv; x.z *= inv; x.w *= inv;
    ((float4*)base)[lane] = x;
}

// ---------------------------------------------------------------------------
// beta = sigmoid(b); decay = exp(-exp(A_log)*softplus(a + dt_bias))
// ---------------------------------------------------------------------------
__global__ void beta_decay_kernel(const float* __restrict__ ba,
                                  const float* __restrict__ dt_bias,
                                  const float* __restrict__ A_log,
                                  float* __restrict__ beta,
                                  float* __restrict__ decay)
{
    int idx = blockIdx.x * blockDim.x + threadIdx.x;
    if (idx >= BT * NVH) return;
    int h = idx & (NVH - 1);
    int bt = idx >> 5;
    float b = ba[bt * 64 + h];
    beta[idx] = 1.f / (1.f + expf(-b));
    float a = ba[bt * 64 + 32 + h] + dt_bias[h];
    float sp = (a > 20.f) ? a : log1pf(expf(a));
    decay[idx] = expf(-expf(A_log[h]) * sp);
}

// ---------------------------------------------------------------------------
// Gated delta rule scan: 128 blocks x 256 threads.
// Block = (b, h, vseg). Thread: col = tid>>2 (0..63), quarter = tid&3.
// S[k = quarter*32 .. +32][col] in 32 registers. Quartet shfl reduction.
// Double-buffered q/k staging -> one __syncthreads per timestep.
// ---------------------------------------------------------------------------
__global__ void __launch_bounds__(256) scan_kernel(
    const float* __restrict__ qn, const float* __restrict__ kn,
    const float* __restrict__ v,  const float* __restrict__ decay,
    const float* __restrict__ beta, float* __restrict__ o)
{
    const int blk = blockIdx.x;
    const int b   = blk >> 6;
    const int rem = blk & 63;
    const int h   = rem >> 1;
    const int seg = rem & 1;
    const int h2  = h >> 1;
    const int tid = threadIdx.x;
    const int col  = tid >> 2;       // 0..63
    const int q4   = tid & 3;
    const int gcol = seg * 64 + col;
    const int koff = q4 * 32;

    __shared__ float sq[2][128];
    __shared__ float sk[2][128];

    float S[32];
#pragma unroll
    for (int i = 0; i < 32; i++) S[i] = 0.f;

    const size_t bt0 = (size_t)b * TLEN;
    const bool isQ = tid < 128;
    const int  idx = tid & 127;

    // stage t = 0
    {
        float val = isQ ? qn[(bt0 * NKH + h2) * DK + idx]
                        : kn[(bt0 * NKH + h2) * DK + idx];
        if (isQ) sq[0][idx] = val; else sk[0][idx] = val;
    }
    float pv = v[(bt0 * NVH + h) * DV + gcol];
    float pd = decay[bt0 * NVH + h];
    float pb = beta [bt0 * NVH + h];
    __syncthreads();

    for (int t = 0; t < TLEN; t++) {
        const int cur = t & 1;

        // prefetch t+1
        float nqk = 0.f, nv = 0.f, nd = 0.f, nb = 0.f;
        if (t + 1 < TLEN) {
            size_t bt = bt0 + t + 1;
            nqk = isQ ? qn[(bt * NKH + h2) * DK + idx]
                      : kn[(bt * NKH + h2) * DK + idx];
            nv = v[(bt * NVH + h) * DV + gcol];
            nd = decay[bt * NVH + h];
            nb = beta [bt * NVH + h];
        }

        const float cd = pd, cb = pb, cv = pv;
        const float* skc = &sk[cur][koff];
        const float* sqc = &sq[cur][koff];

        float a0 = 0.f, a1 = 0.f, a2 = 0.f, a3 = 0.f;
#pragma unroll
        for (int i = 0; i < 32; i += 4) {
            S[i+0] *= cd; a0 = fmaf(skc[i+0], S[i+0], a0);
            S[i+1] *= cd; a1 = fmaf(skc[i+1], S[i+1], a1);
            S[i+2] *= cd; a2 = fmaf(skc[i+2], S[i+2], a2);
            S[i+3] *= cd; a3 = fmaf(skc[i+3], S[i+3], a3);
        }
        float kS = (a0 + a1) + (a2 + a3);
        kS += __shfl_xor_sync(0xffffffffu, kS, 1);
        kS += __shfl_xor_sync(0xffffffffu, kS, 2);

        float upd = cb * (cv - kS);

        float o0 = 0.f, o1 = 0.f, o2 = 0.f, o3 = 0.f;
#pragma unroll
        for (int i = 0; i < 32; i += 4) {
            S[i+0] = fmaf(skc[i+0], upd, S[i+0]); o0 = fmaf(sqc[i+0], S[i+0], o0);
            S[i+1] = fmaf(skc[i+1], upd, S[i+1]); o1 = fmaf(sqc[i+1], S[i+1], o1);
            S[i+2] = fmaf(skc[i+2], upd, S[i+2]); o2 = fmaf(sqc[i+2], S[i+2], o2);
            S[i+3] = fmaf(skc[i+3], upd, S[i+3]); o3 = fmaf(sqc[i+3], S[i+3], o3);
        }
        float oa = (o0 + o1) + (o2 + o3);
        oa += __shfl_xor_sync(0xffffffffu, oa, 1);
        oa += __shfl_xor_sync(0xffffffffu, oa, 2);
        if (q4 == 0)
            o[((bt0 + t) * NVH + h) * DV + gcol] = oa;

        // stage t+1 into the other buffer
        if (t + 1 < TLEN) {
            if (isQ) sq[cur ^ 1][idx] = nqk; else sk[cur ^ 1][idx] = nqk;
        }
        pv = nv; pd = nd; pb = nb;
        __syncthreads();
    }
}

// ---------------------------------------------------------------------------
// Gated RMSNorm; output rounded to tf32 (feeds out-projection GEMM)
// ---------------------------------------------------------------------------
__global__ void gate_kernel(float* __restrict__ o, const float* __restrict__ z,
                            const float* __restrict__ norm_w)
{
    int wg   = (blockIdx.x * blockDim.x + threadIdx.x) >> 5;
    int lane = threadIdx.x & 31;
    if (wg >= BT * NVH) return;

    float4* orow = (float4*)(o + (size_t)wg * DV);
    float4 x = orow[lane];
    float ss = x.x*x.x + x.y*x.y + x.z*x.z + x.w*x.w;
#pragma unroll
    for (int off = 16; off > 0; off >>= 1)
        ss += __shfl_xor_sync(0xffffffffu, ss, off);
    float r = rsqrtf(ss * (1.f / DV) + 1e-6f);

    float4 zv = ((const float4*)(z + (size_t)wg * DV))[lane];
    float4 nw = ((const float4*)norm_w)[lane];

    float s0 = zv.x / (1.f + expf(-zv.x));
    float s1 = zv.y / (1.f + expf(-zv.y));
    float s2 = zv.z / (1.f + expf(-zv.z));
    float s3 = zv.w / (1.f + expf(-zv.w));

    x.x = f2tf_f(x.x * r * nw.x * s0);
    x.y = f2tf_f(x.y * r * nw.y * s1);
    x.z = f2tf_f(x.z * r * nw.z * s2);
    x.w = f2tf_f(x.w * r * nw.w * s3);
    orow[lane] = x;
}

// ---------------------------------------------------------------------------
// Launch
// ---------------------------------------------------------------------------
extern "C" void kernel_launch(void* const* d_in, const int* in_sizes, int n_in,
                              void* d_out, int out_size)
{
    const float* hs      = (const float*)d_in[0];
    const float* W_qkv   = (const float*)d_in[1];
    const float* W_z     = (const float*)d_in[2];
    const float* W_b     = (const float*)d_in[3];
    const float* W_a     = (const float*)d_in[4];
    const float* conv_w  = (const float*)d_in[5];
    const float* dt_bias = (const float*)d_in[6];
    const float* A_log   = (const float*)d_in[7];
    const float* norm_w  = (const float*)d_in[8];
    const float* W_out   = (const float*)d_in[9];
    float* out = (float*)d_out;

    float *mixed, *q, *k, *v, *z, *ba, *beta, *decay, *o;
    float *hs_t, *wqkv_t, *wz_t, *wout_t, *wba_t;
    cudaGetSymbolAddress((void**)&mixed,  g_mixed);
    cudaGetSymbolAddress((void**)&q,      g_q);
    cudaGetSymbolAddress((void**)&k,      g_k);
    cudaGetSymbolAddress((void**)&v,      g_v);
    cudaGetSymbolAddress((void**)&z,      g_z);
    cudaGetSymbolAddress((void**)&ba,     g_ba);
    cudaGetSymbolAddress((void**)&beta,   g_beta);
    cudaGetSymbolAddress((void**)&decay,  g_decay);
    cudaGetSymbolAddress((void**)&o,      g_o);
    cudaGetSymbolAddress((void**)&hs_t,   g_hs_t);
    cudaGetSymbolAddress((void**)&wqkv_t, g_wqkv_t);
    cudaGetSymbolAddress((void**)&wz_t,   g_wz_t);
    cudaGetSymbolAddress((void**)&wout_t, g_wout_t);
    cudaGetSymbolAddress((void**)&wba_t,  g_wba_t);

    cudaFuncSetAttribute(gemm_tf32_kernel,
                         cudaFuncAttributeMaxDynamicSharedMemorySize, GEMM_SMEM);

    // 0) tf32 rounding pre-passes
    {
        size_t n4;
        n4 = (size_t)BT * DMODEL / 4;
        cvt_tf32_kernel<<<(unsigned)((n4 + 255) / 256), 256>>>(hs, hs_t, n4);
        n4 = (size_t)DMODEL * CONVDIM / 4;
        cvt_tf32_kernel<<<(unsigned)((n4 + 255) / 256), 256>>>(W_qkv, wqkv_t, n4);
        n4 = (size_t)DMODEL * VALDIM / 4;
        cvt_tf32_kernel<<<(unsigned)((n4 + 255) / 256), 256>>>(W_z, wz_t, n4);
        n4 = (size_t)VALDIM * DMODEL / 4;
        cvt_tf32_kernel<<<(unsigned)((n4 + 255) / 256), 256>>>(W_out, wout_t, n4);
        pack_wba_kernel<<<(DMODEL * 64 + 255) / 256, 256>>>(W_b, W_a, wba_t);
    }

    // 1) projections (tensor cores, tf32)
    launch_gemm(hs_t, wqkv_t, mixed, BT, CONVDIM, DMODEL);
    launch_gemm(hs_t, wz_t,   z,     BT, VALDIM,  DMODEL);
    launch_gemm(hs_t, wba_t,  ba,    BT, 64,      DMODEL);

    // 2) conv + silu + split
    {
        size_t n = (size_t)BT * CONVDIM;
        conv_silu_split_kernel<<<(unsigned)((n + 255) / 256), 256>>>(mixed, conv_w, q, k, v);
    }

    // 3) l2 norm q/k
    {
        int rows = 2 * BT * NKH;
        l2norm_qk_kernel<<<(rows + 7) / 8, 256>>>(q, k);
    }

    // 4) beta/decay
    beta_decay_kernel<<<(BT * NVH + 255) / 256, 256>>>(ba, dt_bias, A_log, beta, decay);

    // 5) gated delta scan
    scan_kernel<<<BATCH * NVH * 2, 256>>>(q, k, v, decay, beta, o);

    // 6) gated rmsnorm (rounds o to tf32)
    {
        int rows = BT * NVH;
        gate_kernel<<<(rows + 7) / 8, 256>>>(o, z, norm_w);
    }

    // 7) output projection
    launch_gemm(o, wout_t, out, BT, DMODEL, VALDIM);
}

// round 4
// speedup vs baseline: 1.3869x; 1.3869x over previous
#include <cuda_runtime.h>
#include <math.h>
#include <stdint.h>

// ---------------------------------------------------------------------------
// Problem constants (Qwen3.5 GatedDeltaNet): B=2, T=4096, D=2048
// ---------------------------------------------------------------------------
#define BATCH   2
#define TLEN    4096
#define BT      8192
#define DMODEL  2048
#define NVH     32
#define NKH     16
#define DK      128
#define DV      128
#define KEYDIM  (NKH*DK)                 // 2048
#define VALDIM  (NVH*DV)                 // 4096
#define CONVDIM (2*KEYDIM + VALDIM)      // 8192

// ---------------------------------------------------------------------------
// Scratch (static device globals)
// ---------------------------------------------------------------------------
__device__ float g_mixed[(size_t)BT * CONVDIM];
__device__ float g_q[(size_t)BT * KEYDIM];
__device__ float g_k[(size_t)BT * KEYDIM];
__device__ float g_v[(size_t)BT * VALDIM];
__device__ float g_z[(size_t)BT * VALDIM];
__device__ float g_ba[BT * 64];
__device__ float g_beta[BT * NVH];
__device__ float g_decay[BT * NVH];
__device__ float g_o[(size_t)BT * VALDIM];
// tf32-rounded operands
__device__ float g_hs_t[(size_t)BT * DMODEL];
__device__ float g_wqkv_t[(size_t)DMODEL * CONVDIM];
__device__ float g_wz_t[(size_t)DMODEL * VALDIM];
__device__ float g_wout_t[(size_t)VALDIM * DMODEL];
__device__ float g_wba_t[DMODEL * 64];

__device__ __forceinline__ float f2tf_f(float x) {
    uint32_t r; asm("cvt.rna.tf32.f32 %0, %1;" : "=r"(r) : "f"(x));
    return __uint_as_float(r);
}

// ---------------------------------------------------------------------------
// TF32 tensor-core GEMM: C[M,N] = A[M,K] @ B[K,N], row-major fp32 in/out.
// Operands must be pre-rounded to tf32 (no cvt in the hot loop).
// 128x128 block tile, BK=16, 256 threads (8 warps of 64x32), 3-stage cp.async.
// Round-2 smem layouts: A pad LDA_S=20, B pad LDB_S=136.
// ---------------------------------------------------------------------------
#define TSTAGES 3
#define TBM 128
#define TBN 128
#define TBK 16
#define LDA_S 20
#define LDB_S 136
#define A_STAGE (TBM*LDA_S) // 2560 floats
#define B_STAGE (TBK*LDB_S) // 2176 floats
#define GEMM_SMEM (TSTAGES*(A_STAGE+B_STAGE)*4)   // 56832 bytes

__device__ __forceinline__ void cp16(float* dst, const float* src, bool pred) {
    uint32_t d = (uint32_t)__cvta_generic_to_shared(dst);
    int sz = pred ? 16 : 0;
    asm volatile("cp.async.cg.shared.global [%0], [%1], 16, %2;\n"
                 :: "r"(d), "l"(src), "r"(sz));
}

__device__ __forceinline__ void mma_tf32(float* c, const uint32_t* a, const uint32_t* b) {
    asm volatile(
        "mma.sync.aligned.m16n8k8.row.col.f32.tf32.tf32.f32 "
        "{%0,%1,%2,%3}, {%4,%5,%6,%7}, {%8,%9}, {%0,%1,%2,%3};"
        : "+f"(c[0]), "+f"(c[1]), "+f"(c[2]), "+f"(c[3])
        : "r"(a[0]), "r"(a[1]), "r"(a[2]), "r"(a[3]), "r"(b[0]), "r"(b[1]));
}

__global__ __launch_bounds__(256, 2) void gemm_tf32_kernel(
    const float* __restrict__ A, const float* __restrict__ B,
    float* __restrict__ C, int M, int N, int K)
{
    extern __shared__ float smem[];
    float* As = smem;
    float* Bs = smem + TSTAGES * A_STAGE;

    const int tid  = threadIdx.x;
    const int bm   = blockIdx.y;
    const int bn   = blockIdx.x;
    const int warp = tid >> 5;
    const int lane = tid & 31;
    const int g    = lane >> 2;   // group 0..7
    const int tig  = lane & 3;    // thread in group
    const int wm   = (warp >> 2) * 64;
    const int wn   = (warp & 3) * 32;

    float acc[4][4][4];
#pragma unroll
    for (int i = 0; i < 4; i++)
#pragma unroll
        for (int j = 0; j < 4; j++)
#pragma unroll
            for (int r = 0; r < 4; r++) acc[i][j][r] = 0.f;

    const int KT = K / TBK;

    auto load_stage = [&](int s, int kt) {
        float* as = As + s * A_STAGE;
        float* bs = Bs + s * B_STAGE;
#pragma unroll
        for (int h = 0; h < 2; h++) {           // A: 128 rows x 4 float4
            int id  = tid + h * 256;
            int row = id >> 2, c = id & 3;
            const float* src = A + (size_t)(bm * TBM + row) * K + kt * TBK + c * 4;
            cp16(as + row * LDA_S + c * 4, src, true);
        }
#pragma unroll
        for (int h = 0; h < 2; h++) {           // B: 16 rows x 32 float4
            int id  = tid + h * 256;
            int row = id >> 5, c = id & 31;
            int col = bn * TBN + c * 4;
            bool ok = col < N;
            const float* src = B + (size_t)(kt * TBK + row) * N + (ok ? col : 0);
            cp16(bs + row * LDB_S + c * 4, src, ok);
        }
        asm volatile("cp.async.commit_group;");
    };

    load_stage(0, 0);
    load_stage(1, 1);

    for (int kt = 0; kt < KT; kt++) {
        asm volatile("cp.async.wait_group 1;");
        __syncthreads();

        if (kt + 2 < KT) load_stage((kt + 2) % TSTAGES, kt + 2);
        else             asm volatile("cp.async.commit_group;");

        const float* as = As + (kt % TSTAGES) * A_STAGE;
        const float* bs = Bs + (kt % TSTAGES) * B_STAGE;

#pragma unroll
        for (int kk = 0; kk < 2; kk++) {
            const int k0 = kk * 8;
            uint32_t af[4][4], bf[4][2];
#pragma unroll
            for (int i = 0; i < 4; i++) {
                int r0 = wm + 16 * i + g;
                af[i][0] = *(const uint32_t*)&as[(r0    ) * LDA_S + k0 + tig    ];
                af[i][1] = *(const uint32_t*)&as[(r0 + 8) * LDA_S + k0 + tig    ];
                af[i][2] = *(const uint32_t*)&as[(r0    ) * LDA_S + k0 + tig + 4];
                af[i][3] = *(const uint32_t*)&as[(r0 + 8) * LDA_S + k0 + tig + 4];
            }
#pragma unroll
            for (int j = 0; j < 4; j++) {
                int cn = wn + 8 * j + g;
                bf[j][0] = *(const uint32_t*)&bs[(k0 + tig    ) * LDB_S + cn];
                bf[j][1] = *(const uint32_t*)&bs[(k0 + tig + 4) * LDB_S + cn];
            }
#pragma unroll
            for (int i = 0; i < 4; i++)
#pragma unroll
                for (int j = 0; j < 4; j++)
                    mma_tf32(acc[i][j], af[i], bf[j]);
        }
    }

#pragma unroll
    for (int i = 0; i < 4; i++) {
        int r0 = bm * TBM + wm + 16 * i + g;
#pragma unroll
        for (int j = 0; j < 4; j++) {
            int cn = bn * TBN + wn + 8 * j + 2 * tig;
            if (cn < N) {
                *(float2*)(C + (size_t)r0 * N + cn)       = make_float2(acc[i][j][0], acc[i][j][1]);
                *(float2*)(C + (size_t)(r0 + 8) * N + cn) = make_float2(acc[i][j][2], acc[i][j][3]);
            }
        }
    }
}

static inline void launch_gemm(const float* A, const float* B, float* C,
                               int M, int N, int K)
{
    dim3 grid((N + TBN - 1) / TBN, M / TBM);
    gemm_tf32_kernel<<<grid, 256, GEMM_SMEM>>>(A, B, C, M, N, K);
}

// ---------------------------------------------------------------------------
// Elementwise tf32 rounding pre-pass (float4 vectorized)
// ---------------------------------------------------------------------------
__global__ void cvt_tf32_kernel(const float* __restrict__ src,
                                float* __restrict__ dst, size_t n4)
{
    size_t i = (size_t)blockIdx.x * blockDim.x + threadIdx.x;
    if (i >= n4) return;
    float4 x = ((const float4*)src)[i];
    x.x = f2tf_f(x.x); x.y = f2tf_f(x.y); x.z = f2tf_f(x.z); x.w = f2tf_f(x.w);
    ((float4*)dst)[i] = x;
}

// Pack W_b|W_a into [DMODEL, 64], tf32-rounded
__global__ void pack_wba_kernel(const float* __restrict__ Wb,
                                const float* __restrict__ Wa,
                                float* __restrict__ Wba)
{
    int idx = blockIdx.x * blockDim.x + threadIdx.x;
    if (idx >= DMODEL * 64) return;
    int k = idx >> 6, j = idx & 63;
    float v = (j < 32) ? Wb[k * 32 + j] : Wa[k * 32 + (j - 32)];
    Wba[idx] = f2tf_f(v);
}

// ---------------------------------------------------------------------------
// Causal depthwise conv (KC=4) + SiLU + split into q/k/v
// ---------------------------------------------------------------------------
__global__ void conv_silu_split_kernel(const float* __restrict__ mixed,
                                       const float* __restrict__ conv_w,
                                       float* __restrict__ q,
                                       float* __restrict__ k,
                                       float* __restrict__ v)
{
    size_t idx = (size_t)blockIdx.x * blockDim.x + threadIdx.x;
    if (idx >= (size_t)BT * CONVDIM) return;
    int c = (int)(idx & (CONVDIM - 1));
    size_t bt = idx >> 13;
    int t = (int)(bt & (TLEN - 1));

    float4 w = *(const float4*)(conv_w + (size_t)c * 4);
    const float* base = mixed + c;
    float x0 = (t >= 3) ? base[(bt - 3) * CONVDIM] : 0.f;
    float x1 = (t >= 2) ? base[(bt - 2) * CONVDIM] : 0.f;
    float x2 = (t >= 1) ? base[(bt - 1) * CONVDIM] : 0.f;
    float x3 = base[bt * CONVDIM];

    float acc = x0 * w.x + x1 * w.y + x2 * w.z + x3 * w.w;
    float s = acc / (1.f + expf(-acc));

    if (c < KEYDIM)           q[bt * KEYDIM + c] = s;
    else if (c < 2 * KEYDIM)  k[bt * KEYDIM + (c - KEYDIM)] = s;
    else                      v[bt * VALDIM + (c - 2 * KEYDIM)] = s;
}

// ---------------------------------------------------------------------------
// L2 norm over DK=128 (one warp per row); q gets extra DK^-0.5
// ---------------------------------------------------------------------------
__global__ void l2norm_qk_kernel(float* __restrict__ q, float* __restrict__ k)
{
    int wg   = (blockIdx.x * blockDim.x + threadIdx.x) >> 5;
    int lane = threadIdx.x & 31;
    const int nrows = BT * NKH;
    if (wg >= 2 * nrows) return;

    float* base;
    float extra;
    if (wg < nrows) { base = q + (size_t)wg * DK; extra = 0.08838834764831845f; }
    else            { base = k + (size_t)(wg - nrows) * DK; extra = 1.f; }

    float4 x = ((float4*)base)[lane];
    float ss = x.x*x.x + x.y*x.y + x.z*x.z + x.w*x.w;
#pragma unroll
    for (int off = 16; off > 0; off >>= 1)
        ss += __shfl_xor_sync(0xffffffffu, ss, off);
    float inv = rsqrtf(ss + 1e-6f) * extra;
    x.x *= inv; x.y *= inv; x.z *= inv; x.w *= inv;
    ((float4*)base)[lane] = x;
}

// ---------------------------------------------------------------------------
// beta = sigmoid(b); decay = exp(-exp(A_log)*softplus(a + dt_bias))
// ---------------------------------------------------------------------------
__global__ void beta_decay_kernel(const float* __restrict__ ba,
                                  const float* __restrict__ dt_bias,
                                  const float* __restrict__ A_log,
                                  float* __restrict__ beta,
                                  float* __restrict__ decay)
{
    int idx = blockIdx.x * blockDim.x + threadIdx.x;
    if (idx >= BT * NVH) return;
    int h = idx & (NVH - 1);
    int bt = idx >> 5;
    float b = ba[bt * 64 + h];
    beta[idx] = 1.f / (1.f + expf(-b));
    float a = ba[bt * 64 + 32 + h] + dt_bias[h];
    float sp = (a > 20.f) ? a : log1pf(expf(a));
    decay[idx] = expf(-expf(A_log[h]) * sp);
}

// ---------------------------------------------------------------------------
// Gated delta rule scan (round-2 layout: 128 blocks x 128 threads,
// 64 state regs/thread, pair shfl reduction, 2 syncs/step)
// ---------------------------------------------------------------------------
__global__ void __launch_bounds__(128) scan_kernel(
    const float* __restrict__ qn, const float* __restrict__ kn,
    const float* __restrict__ v,  const float* __restrict__ decay,
    const float* __restrict__ beta, float* __restrict__ o)
{
    const int blk = blockIdx.x;
    const int b   = blk >> 6;
    const int rem = blk & 63;
    const int h   = rem >> 1;
    const int seg = rem & 1;
    const int h2  = h >> 1;
    const int tid = threadIdx.x;
    const int col  = tid >> 1;
    const int half = tid & 1;
    const int gcol = seg * 64 + col;
    const int koff = half * 64;

    __shared__ float sq[128];
    __shared__ float sk[128];

    float S[64];
#pragma unroll
    for (int i = 0; i < 64; i++) S[i] = 0.f;

    const size_t bt0 = (size_t)b * TLEN;

    float pq = qn[((bt0)*NKH + h2) * DK + tid];
    float pk = kn[((bt0)*NKH + h2) * DK + tid];
    float pv = v [((bt0)*NVH + h ) * DV + gcol];
    float pd = decay[bt0 * NVH + h];
    float pb = beta [bt0 * NVH + h];

    for (int t = 0; t < TLEN; t++) {
        __syncthreads();
        sq[tid] = pq;
        sk[tid] = pk;
        float cv = pv, cd = pd, cb = pb;
        __syncthreads();

        if (t + 1 < TLEN) {
            size_t bt = bt0 + t + 1;
            pq = qn[(bt*NKH + h2) * DK + tid];
            pk = kn[(bt*NKH + h2) * DK + tid];
            pv = v [(bt*NVH + h ) * DV + gcol];
            pd = decay[bt * NVH + h];
            pb = beta [bt * NVH + h];
        }

        float a0 = 0.f, a1 = 0.f, a2 = 0.f, a3 = 0.f;
#pragma unroll
        for (int i = 0; i < 64; i += 4) {
            S[i+0] *= cd; a0 = fmaf(sk[koff+i+0], S[i+0], a0);
            S[i+1] *= cd; a1 = fmaf(sk[koff+i+1], S[i+1], a1);
            S[i+2] *= cd; a2 = fmaf(sk[koff+i+2], S[i+2], a2);
            S[i+3] *= cd; a3 = fmaf(sk[koff+i+3], S[i+3], a3);
        }
        float kS = (a0 + a1) + (a2 + a3);
        kS += __shfl_xor_sync(0xffffffffu, kS, 1);

        float upd = cb * (cv - kS);

        float o0 = 0.f, o1 = 0.f, o2 = 0.f, o3 = 0.f;
#pragma unroll
        for (int i = 0; i < 64; i += 4) {
            S[i+0] = fmaf(sk[koff+i+0], upd, S[i+0]); o0 = fmaf(sq[koff+i+0], S[i+0], o0);
            S[i+1] = fmaf(sk[koff+i+1], upd, S[i+1]); o1 = fmaf(sq[koff+i+1], S[i+1], o1);
            S[i+2] = fmaf(sk[koff+i+2], upd, S[i+2]); o2 = fmaf(sq[koff+i+2], S[i+2], o2);
            S[i+3] = fmaf(sk[koff+i+3], upd, S[i+3]); o3 = fmaf(sq[koff+i+3], S[i+3], o3);
        }
        float oa = (o0 + o1) + (o2 + o3);
        oa += __shfl_xor_sync(0xffffffffu, oa, 1);
        if (!half)
            o[((bt0 + t)*NVH + h) * DV + gcol] = oa;
    }
}

// ---------------------------------------------------------------------------
// Gated RMSNorm; output rounded to tf32 (feeds out-projection GEMM)
// ---------------------------------------------------------------------------
__global__ void gate_kernel(float* __restrict__ o, const float* __restrict__ z,
                            const float* __restrict__ norm_w)
{
    int wg   = (blockIdx.x * blockDim.x + threadIdx.x) >> 5;
    int lane = threadIdx.x & 31;
    if (wg >= BT * NVH) return;

    float4* orow = (float4*)(o + (size_t)wg * DV);
    float4 x = orow[lane];
    float ss = x.x*x.x + x.y*x.y + x.z*x.z + x.w*x.w;
#pragma unroll
    for (int off = 16; off > 0; off >>= 1)
        ss += __shfl_xor_sync(0xffffffffu, ss, off);
    float r = rsqrtf(ss * (1.f / DV) + 1e-6f);

    float4 zv = ((const float4*)(z + (size_t)wg * DV))[lane];
    float4 nw = ((const float4*)norm_w)[lane];

    float s0 = zv.x / (1.f + expf(-zv.x));
    float s1 = zv.y / (1.f + expf(-zv.y));
    float s2 = zv.z / (1.f + expf(-zv.z));
    float s3 = zv.w / (1.f + expf(-zv.w));

    x.x = f2tf_f(x.x * r * nw.x * s0);
    x.y = f2tf_f(x.y * r * nw.y * s1);
    x.z = f2tf_f(x.z * r * nw.z * s2);
    x.w = f2tf_f(x.w * r * nw.w * s3);
    orow[lane] = x;
}

// ---------------------------------------------------------------------------
// Launch
// ---------------------------------------------------------------------------
extern "C" void kernel_launch(void* const* d_in, const int* in_sizes, int n_in,
                              void* d_out, int out_size)
{
    const float* hs      = (const float*)d_in[0];
    const float* W_qkv   = (const float*)d_in[1];
    const float* W_z     = (const float*)d_in[2];
    const float* W_b     = (const float*)d_in[3];
    const float* W_a     = (const float*)d_in[4];
    const float* conv_w  = (const float*)d_in[5];
    const float* dt_bias = (const float*)d_in[6];
    const float* A_log   = (const float*)d_in[7];
    const float* norm_w  = (const float*)d_in[8];
    const float* W_out   = (const float*)d_in[9];
    float* out = (float*)d_out;

    float *mixed, *q, *k, *v, *z, *ba, *beta, *decay, *o;
    float *hs_t, *wqkv_t, *wz_t, *wout_t, *wba_t;
    cudaGetSymbolAddress((void**)&mixed,  g_mixed);
    cudaGetSymbolAddress((void**)&q,      g_q);
    cudaGetSymbolAddress((void**)&k,      g_k);
    cudaGetSymbolAddress((void**)&v,      g_v);
    cudaGetSymbolAddress((void**)&z,      g_z);
    cudaGetSymbolAddress((void**)&ba,     g_ba);
    cudaGetSymbolAddress((void**)&beta,   g_beta);
    cudaGetSymbolAddress((void**)&decay,  g_decay);
    cudaGetSymbolAddress((void**)&o,      g_o);
    cudaGetSymbolAddress((void**)&hs_t,   g_hs_t);
    cudaGetSymbolAddress((void**)&wqkv_t, g_wqkv_t);
    cudaGetSymbolAddress((void**)&wz_t,   g_wz_t);
    cudaGetSymbolAddress((void**)&wout_t, g_wout_t);
    cudaGetSymbolAddress((void**)&wba_t,  g_wba_t);

    cudaFuncSetAttribute(gemm_tf32_kernel,
                         cudaFuncAttributeMaxDynamicSharedMemorySize, GEMM_SMEM);

    // 0) tf32 rounding pre-passes
    {
        size_t n4;
        n4 = (size_t)BT * DMODEL / 4;
        cvt_tf32_kernel<<<(unsigned)((n4 + 255) / 256), 256>>>(hs, hs_t, n4);
        n4 = (size_t)DMODEL * CONVDIM / 4;
        cvt_tf32_kernel<<<(unsigned)((n4 + 255) / 256), 256>>>(W_qkv, wqkv_t, n4);
        n4 = (size_t)DMODEL * VALDIM / 4;
        cvt_tf32_kernel<<<(unsigned)((n4 + 255) / 256), 256>>>(W_z, wz_t, n4);
        n4 = (size_t)VALDIM * DMODEL / 4;
        cvt_tf32_kernel<<<(unsigned)((n4 + 255) / 256), 256>>>(W_out, wout_t, n4);
        pack_wba_kernel<<<(DMODEL * 64 + 255) / 256, 256>>>(W_b, W_a, wba_t);
    }

    // 1) projections (tensor cores, tf32)
    launch_gemm(hs_t, wqkv_t, mixed, BT, CONVDIM, DMODEL);
    launch_gemm(hs_t, wz_t,   z,     BT, VALDIM,  DMODEL);
    launch_gemm(hs_t, wba_t,  ba,    BT, 64,      DMODEL);

    // 2) conv + silu + split
    {
        size_t n = (size_t)BT * CONVDIM;
        conv_silu_split_kernel<<<(unsigned)((n + 255) / 256), 256>>>(mixed, conv_w, q, k, v);
    }

    // 3) l2 norm q/k
    {
        int rows = 2 * BT * NKH;
        l2norm_qk_kernel<<<(rows + 7) / 8, 256>>>(q, k);
    }

    // 4) beta/decay
    beta_decay_kernel<<<(BT * NVH + 255) / 256, 256>>>(ba, dt_bias, A_log, beta, decay);

    // 5) gated delta scan
    scan_kernel<<<BATCH * NVH * 2, 128>>>(q, k, v, decay, beta, o);

    // 6) gated rmsnorm (rounds o to tf32)
    {
        int rows = BT * NVH;
        gate_kernel<<<(rows + 7) / 8, 256>>>(o, z, norm_w);
    }

    // 7) output projection
    launch_gemm(o, wout_t, out, BT, DMODEL, VALDIM);
}

// round 5
// speedup vs baseline: 1.3984x; 1.0083x over previous
#include <cuda_runtime.h>
#include <math.h>
#include <stdint.h>

// ---------------------------------------------------------------------------
// Problem constants (Qwen3.5 GatedDeltaNet): B=2, T=4096, D=2048
// ---------------------------------------------------------------------------
#define BATCH   2
#define TLEN    4096
#define BT      8192
#define DMODEL  2048
#define NVH     32
#define NKH     16
#define DK      128
#define DV      128
#define KEYDIM  (NKH*DK)                 // 2048
#define VALDIM  (NVH*DV)                 // 4096
#define CONVDIM (2*KEYDIM + VALDIM)      // 8192
#define PROJ_N  (CONVDIM + VALDIM + 64)  // 12352 : [qkv | z | b | a]
#define Z_OFF   CONVDIM                  // 8192
#define B_OFF   (CONVDIM + VALDIM)       // 12288
#define A_OFF   (B_OFF + 32)             // 12320

// ---------------------------------------------------------------------------
// Scratch (static device globals)
// ---------------------------------------------------------------------------
__device__ float g_proj[(size_t)BT * PROJ_N];      // fused projection output
__device__ float g_q[(size_t)BT * KEYDIM];
__device__ float g_k[(size_t)BT * KEYDIM];
__device__ float g_v[(size_t)BT * VALDIM];
__device__ float g_beta[BT * NVH];
__device__ float g_decay[BT * NVH];
__device__ float g_o[(size_t)BT * VALDIM];
// tf32-rounded operands
__device__ float g_hs_t[(size_t)BT * DMODEL];
__device__ float g_wproj[(size_t)DMODEL * PROJ_N]; // packed [Wqkv|Wz|Wb|Wa]
__device__ float g_wout_t[(size_t)VALDIM * DMODEL];

__device__ __forceinline__ float f2tf_f(float x) {
    uint32_t r; asm("cvt.rna.tf32.f32 %0, %1;" : "=r"(r) : "f"(x));
    return __uint_as_float(r);
}

// ---------------------------------------------------------------------------
// TF32 tensor-core GEMM: C[M,N] = A[M,K] @ B[K,N], row-major fp32 in/out.
// Operands pre-rounded to tf32. 128x128x16 tile, 256 thr, 3-stage cp.async.
// A fragments via ldmatrix.x4 (b16 trick on 32-bit data), B via scalar LDS.
// ---------------------------------------------------------------------------
#define TSTAGES 3
#define TBM 128
#define TBN 128
#define TBK 16
#define LDA_S 20
#define LDB_S 136
#define A_STAGE (TBM*LDA_S) // 2560 floats
#define B_STAGE (TBK*LDB_S) // 2176 floats
#define GEMM_SMEM (TSTAGES*(A_STAGE+B_STAGE)*4)   // 56832 bytes

__device__ __forceinline__ void cp16(float* dst, const float* src, bool pred) {
    uint32_t d = (uint32_t)__cvta_generic_to_shared(dst);
    int sz = pred ? 16 : 0;
    asm volatile("cp.async.cg.shared.global [%0], [%1], 16, %2;\n"
                 :: "r"(d), "l"(src), "r"(sz));
}

__device__ __forceinline__ void ldsm_x4(uint32_t* r, uint32_t addr) {
    asm volatile("ldmatrix.sync.aligned.m8n8.x4.shared.b16 {%0,%1,%2,%3}, [%4];"
        : "=r"(r[0]), "=r"(r[1]), "=r"(r[2]), "=r"(r[3]) : "r"(addr));
}

__device__ __forceinline__ void mma_tf32(float* c, const uint32_t* a, const uint32_t* b) {
    asm volatile(
        "mma.sync.aligned.m16n8k8.row.col.f32.tf32.tf32.f32 "
        "{%0,%1,%2,%3}, {%4,%5,%6,%7}, {%8,%9}, {%0,%1,%2,%3};"
        : "+f"(c[0]), "+f"(c[1]), "+f"(c[2]), "+f"(c[3])
        : "r"(a[0]), "r"(a[1]), "r"(a[2]), "r"(a[3]), "r"(b[0]), "r"(b[1]));
}

__global__ __launch_bounds__(256, 2) void gemm_tf32_kernel(
    const float* __restrict__ A, const float* __restrict__ B,
    float* __restrict__ C, int M, int N, int K)
{
    extern __shared__ float smem[];
    float* As = smem;
    float* Bs = smem + TSTAGES * A_STAGE;

    const int tid  = threadIdx.x;
    const int bm   = blockIdx.y;
    const int bn   = blockIdx.x;
    const int warp = tid >> 5;
    const int lane = tid & 31;
    const int g    = lane >> 2;
    const int tig  = lane & 3;
    const int wm   = (warp >> 2) * 64;
    const int wn   = (warp & 3) * 32;

    float acc[4][4][4];
#pragma unroll
    for (int i = 0; i < 4; i++)
#pragma unroll
        for (int j = 0; j < 4; j++)
#pragma unroll
            for (int r = 0; r < 4; r++) acc[i][j][r] = 0.f;

    const int KT = K / TBK;

    // ldmatrix per-lane source: row = wm + (lane&15) (+16i), col = 4*(lane>>4) (+k0)
    const uint32_t a_smem_u32 = (uint32_t)__cvta_generic_to_shared(As);
    const uint32_t a_lane_off = (((lane & 15) + wm) * LDA_S + 4 * (lane >> 4)) * 4;

    auto load_stage = [&](int s, int kt) {
        float* as = As + s * A_STAGE;
        float* bs = Bs + s * B_STAGE;
#pragma unroll
        for (int h = 0; h < 2; h++) {           // A: 128 rows x 4 float4
            int id  = tid + h * 256;
            int row = id >> 2, c = id & 3;
            const float* src = A + (size_t)(bm * TBM + row) * K + kt * TBK + c * 4;
            cp16(as + row * LDA_S + c * 4, src, true);
        }
#pragma unroll
        for (int h = 0; h < 2; h++) {           // B: 16 rows x 32 float4
            int id  = tid + h * 256;
            int row = id >> 5, c = id & 31;
            int col = bn * TBN + c * 4;
            bool ok = col < N;
            const float* src = B + (size_t)(kt * TBK + row) * N + (ok ? col : 0);
            cp16(bs + row * LDB_S + c * 4, src, ok);
        }
        asm volatile("cp.async.commit_group;");
    };

    load_stage(0, 0);
    load_stage(1, 1);

    for (int kt = 0; kt < KT; kt++) {
        asm volatile("cp.async.wait_group 1;");
        __syncthreads();

        if (kt + 2 < KT) load_stage((kt + 2) % TSTAGES, kt + 2);
        else             asm volatile("cp.async.commit_group;");

        const int st = kt % TSTAGES;
        const uint32_t as_u = a_smem_u32 + (uint32_t)(st * A_STAGE * 4) + a_lane_off;
        const float* bs = Bs + st * B_STAGE;

#pragma unroll
        for (int kk = 0; kk < 2; kk++) {
            const int k0 = kk * 8;
            uint32_t af[4][4], bf[4][2];
#pragma unroll
            for (int i = 0; i < 4; i++)
                ldsm_x4(af[i], as_u + (uint32_t)((k0 + 16 * i * LDA_S) * 4));
#pragma unroll
            for (int j = 0; j < 4; j++) {
                int cn = wn + 8 * j + g;
                bf[j][0] = *(const uint32_t*)&bs[(k0 + tig    ) * LDB_S + cn];
                bf[j][1] = *(const uint32_t*)&bs[(k0 + tig + 4) * LDB_S + cn];
            }
#pragma unroll
            for (int i = 0; i < 4; i++)
#pragma unroll
                for (int j = 0; j < 4; j++)
                    mma_tf32(acc[i][j], af[i], bf[j]);
        }
    }

#pragma unroll
    for (int i = 0; i < 4; i++) {
        int r0 = bm * TBM + wm + 16 * i + g;
#pragma unroll
        for (int j = 0; j < 4; j++) {
            int cn = bn * TBN + wn + 8 * j + 2 * tig;
            if (cn < N) {
                *(float2*)(C + (size_t)r0 * N + cn)       = make_float2(acc[i][j][0], acc[i][j][1]);
                *(float2*)(C + (size_t)(r0 + 8) * N + cn) = make_float2(acc[i][j][2], acc[i][j][3]);
            }
        }
    }
}

static inline void launch_gemm(const float* A, const float* B, float* C,
                               int M, int N, int K)
{
    dim3 grid((N + TBN - 1) / TBN, M / TBM);
    gemm_tf32_kernel<<<grid, 256, GEMM_SMEM>>>(A, B, C, M, N, K);
}

// ---------------------------------------------------------------------------
// Elementwise tf32 rounding pre-pass (float4 vectorized)
// ---------------------------------------------------------------------------
__global__ void cvt_tf32_kernel(const float* __restrict__ src,
                                float* __restrict__ dst, size_t n4)
{
    size_t i = (size_t)blockIdx.x * blockDim.x + threadIdx.x;
    if (i >= n4) return;
    float4 x = ((const float4*)src)[i];
    x.x = f2tf_f(x.x); x.y = f2tf_f(x.y); x.z = f2tf_f(x.z); x.w = f2tf_f(x.w);
    ((float4*)dst)[i] = x;
}

// Pack [W_qkv | W_z | W_b | W_a] into [DMODEL, PROJ_N], tf32-rounded
__global__ void pack_wproj_kernel(const float* __restrict__ Wqkv,
                                  const float* __restrict__ Wz,
                                  const float* __restrict__ Wb,
                                  const float* __restrict__ Wa,
                                  float* __restrict__ Wp)
{
    size_t idx = (size_t)blockIdx.x * blockDim.x + threadIdx.x;
    if (idx >= (size_t)DMODEL * PROJ_N) return;
    int k = (int)(idx / PROJ_N);
    int j = (int)(idx - (size_t)k * PROJ_N);
    float val;
    if      (j < Z_OFF) val = Wqkv[(size_t)k * CONVDIM + j];
    else if (j < B_OFF) val = Wz[(size_t)k * VALDIM + (j - Z_OFF)];
    else if (j < A_OFF) val = Wb[k * 32 + (j - B_OFF)];
    else                val = Wa[k * 32 + (j - A_OFF)];
    Wp[idx] = f2tf_f(val);
}

// ---------------------------------------------------------------------------
// Causal depthwise conv (KC=4) + SiLU + split into q/k/v
// reads the qkv region of the fused projection buffer (row stride PROJ_N)
// ---------------------------------------------------------------------------
__global__ void conv_silu_split_kernel(const float* __restrict__ proj,
                                       const float* __restrict__ conv_w,
                                       float* __restrict__ q,
                                       float* __restrict__ k,
                                       float* __restrict__ v)
{
    size_t idx = (size_t)blockIdx.x * blockDim.x + threadIdx.x;
    if (idx >= (size_t)BT * CONVDIM) return;
    int c = (int)(idx & (CONVDIM - 1));
    size_t bt = idx >> 13;
    int t = (int)(bt & (TLEN - 1));

    float4 w = *(const float4*)(conv_w + (size_t)c * 4);
    const float* base = proj + c;
    float x0 = (t >= 3) ? base[(bt - 3) * PROJ_N] : 0.f;
    float x1 = (t >= 2) ? base[(bt - 2) * PROJ_N] : 0.f;
    float x2 = (t >= 1) ? base[(bt - 1) * PROJ_N] : 0.f;
    float x3 = base[bt * PROJ_N];

    float acc = x0 * w.x + x1 * w.y + x2 * w.z + x3 * w.w;
    float s = acc / (1.f + expf(-acc));

    if (c < KEYDIM)           q[bt * KEYDIM + c] = s;
    else if (c < 2 * KEYDIM)  k[bt * KEYDIM + (c - KEYDIM)] = s;
    else                      v[bt * VALDIM + (c - 2 * KEYDIM)] = s;
}

// ---------------------------------------------------------------------------
// L2 norm over DK=128 (one warp per row); q gets extra DK^-0.5
// ---------------------------------------------------------------------------
__global__ void l2norm_qk_kernel(float* __restrict__ q, float* __restrict__ k)
{
    int wg   = (blockIdx.x * blockDim.x + threadIdx.x) >> 5;
    int lane = threadIdx.x & 31;
    const int nrows = BT * NKH;
    if (wg >= 2 * nrows) return;

    float* base;
    float extra;
    if (wg < nrows) { base = q + (size_t)wg * DK; extra = 0.08838834764831845f; }
    else            { base = k + (size_t)(wg - nrows) * DK; extra = 1.f; }

    float4 x = ((float4*)base)[lane];
    float ss = x.x*x.x + x.y*x.y + x.z*x.z + x.w*x.w;
#pragma unroll
    for (int off = 16; off > 0; off >>= 1)
        ss += __shfl_xor_sync(0xffffffffu, ss, off);
    float inv = rsqrtf(ss + 1e-6f) * extra;
    x.x *= inv; x.y *= inv; x.z *= inv; x.w *= inv;
    ((float4*)base)[lane] = x;
}

// ---------------------------------------------------------------------------
// beta = sigmoid(b); decay = exp(-exp(A_log)*softplus(a + dt_bias))
// reads b/a from the fused projection buffer
// ---------------------------------------------------------------------------
__global__ void beta_decay_kernel(const float* __restrict__ proj,
                                  const float* __restrict__ dt_bias,
                                  const float* __restrict__ A_log,
                                  float* __restrict__ beta,
                                  float* __restrict__ decay)
{
    int idx = blockIdx.x * blockDim.x + threadIdx.x;
    if (idx >= BT * NVH) return;
    int h = idx & (NVH - 1);
    size_t bt = (size_t)(idx >> 5);
    float b = proj[bt * PROJ_N + B_OFF + h];
    beta[idx] = 1.f / (1.f + expf(-b));
    float a = proj[bt * PROJ_N + A_OFF + h] + dt_bias[h];
    float sp = (a > 20.f) ? a : log1pf(expf(a));
    decay[idx] = expf(-expf(A_log[h]) * sp);
}

// ---------------------------------------------------------------------------
// Gated delta rule scan (128 blocks x 128 threads, 64 state regs/thread)
// ---------------------------------------------------------------------------
__global__ void __launch_bounds__(128) scan_kernel(
    const float* __restrict__ qn, const float* __restrict__ kn,
    const float* __restrict__ v,  const float* __restrict__ decay,
    const float* __restrict__ beta, float* __restrict__ o)
{
    const int blk = blockIdx.x;
    const int b   = blk >> 6;
    const int rem = blk & 63;
    const int h   = rem >> 1;
    const int seg = rem & 1;
    const int h2  = h >> 1;
    const int tid = threadIdx.x;
    const int col  = tid >> 1;
    const int half = tid & 1;
    const int gcol = seg * 64 + col;
    const int koff = half * 64;

    __shared__ float sq[128];
    __shared__ float sk[128];

    float S[64];
#pragma unroll
    for (int i = 0; i < 64; i++) S[i] = 0.f;

    const size_t bt0 = (size_t)b * TLEN;

    float pq = qn[((bt0)*NKH + h2) * DK + tid];
    float pk = kn[((bt0)*NKH + h2) * DK + tid];
    float pv = v [((bt0)*NVH + h ) * DV + gcol];
    float pd = decay[bt0 * NVH + h];
    float pb = beta [bt0 * NVH + h];

    for (int t = 0; t < TLEN; t++) {
        __syncthreads();
        sq[tid] = pq;
        sk[tid] = pk;
        float cv = pv, cd = pd, cb = pb;
        __syncthreads();

        if (t + 1 < TLEN) {
            size_t bt = bt0 + t + 1;
            pq = qn[(bt*NKH + h2) * DK + tid];
            pk = kn[(bt*NKH + h2) * DK + tid];
            pv = v [(bt*NVH + h ) * DV + gcol];
            pd = decay[bt * NVH + h];
            pb = beta [bt * NVH + h];
        }

        float a0 = 0.f, a1 = 0.f, a2 = 0.f, a3 = 0.f;
#pragma unroll
        for (int i = 0; i < 64; i += 4) {
            S[i+0] *= cd; a0 = fmaf(sk[koff+i+0], S[i+0], a0);
            S[i+1] *= cd; a1 = fmaf(sk[koff+i+1], S[i+1], a1);
            S[i+2] *= cd; a2 = fmaf(sk[koff+i+2], S[i+2], a2);
            S[i+3] *= cd; a3 = fmaf(sk[koff+i+3], S[i+3], a3);
        }
        float kS = (a0 + a1) + (a2 + a3);
        kS += __shfl_xor_sync(0xffffffffu, kS, 1);

        float upd = cb * (cv - kS);

        float o0 = 0.f, o1 = 0.f, o2 = 0.f, o3 = 0.f;
#pragma unroll
        for (int i = 0; i < 64; i += 4) {
            S[i+0] = fmaf(sk[koff+i+0], upd, S[i+0]); o0 = fmaf(sq[koff+i+0], S[i+0], o0);
            S[i+1] = fmaf(sk[koff+i+1], upd, S[i+1]); o1 = fmaf(sq[koff+i+1], S[i+1], o1);
            S[i+2] = fmaf(sk[koff+i+2], upd, S[i+2]); o2 = fmaf(sq[koff+i+2], S[i+2], o2);
            S[i+3] = fmaf(sk[koff+i+3], upd, S[i+3]); o3 = fmaf(sq[koff+i+3], S[i+3], o3);
        }
        float oa = (o0 + o1) + (o2 + o3);
        oa += __shfl_xor_sync(0xffffffffu, oa, 1);
        if (!half)
            o[((bt0 + t)*NVH + h) * DV + gcol] = oa;
    }
}

// ---------------------------------------------------------------------------
// Gated RMSNorm; z from fused projection buffer; output rounded to tf32
// ---------------------------------------------------------------------------
__global__ void gate_kernel(float* __restrict__ o, const float* __restrict__ proj,
                            const float* __restrict__ norm_w)
{
    int wg   = (blockIdx.x * blockDim.x + threadIdx.x) >> 5;
    int lane = threadIdx.x & 31;
    if (wg >= BT * NVH) return;

    float4* orow = (float4*)(o + (size_t)wg * DV);
    float4 x = orow[lane];
    float ss = x.x*x.x + x.y*x.y + x.z*x.z + x.w*x.w;
#pragma unroll
    for (int off = 16; off > 0; off >>= 1)
        ss += __shfl_xor_sync(0xffffffffu, ss, off);
    float r = rsqrtf(ss * (1.f / DV) + 1e-6f);

    size_t bt = (size_t)(wg >> 5);
    int h = wg & 31;
    const float* zrow = proj + bt * PROJ_N + Z_OFF + h * DV;
    float4 zv = ((const float4*)zrow)[lane];
    float4 nw = ((const float4*)norm_w)[lane];

    float s0 = zv.x / (1.f + expf(-zv.x));
    float s1 = zv.y / (1.f + expf(-zv.y));
    float s2 = zv.z / (1.f + expf(-zv.z));
    float s3 = zv.w / (1.f + expf(-zv.w));

    x.x = f2tf_f(x.x * r * nw.x * s0);
    x.y = f2tf_f(x.y * r * nw.y * s1);
    x.z = f2tf_f(x.z * r * nw.z * s2);
    x.w = f2tf_f(x.w * r * nw.w * s3);
    orow[lane] = x;
}

// ---------------------------------------------------------------------------
// Launch
// ---------------------------------------------------------------------------
extern "C" void kernel_launch(void* const* d_in, const int* in_sizes, int n_in,
                              void* d_out, int out_size)
{
    const float* hs      = (const float*)d_in[0];
    const float* W_qkv   = (const float*)d_in[1];
    const float* W_z     = (const float*)d_in[2];
    const float* W_b     = (const float*)d_in[3];
    const float* W_a     = (const float*)d_in[4];
    const float* conv_w  = (const float*)d_in[5];
    const float* dt_bias = (const float*)d_in[6];
    const float* A_log   = (const float*)d_in[7];
    const float* norm_w  = (const float*)d_in[8];
    const float* W_out   = (const float*)d_in[9];
    float* out = (float*)d_out;

    float *proj, *q, *k, *v, *beta, *decay, *o;
    float *hs_t, *wproj, *wout_t;
    cudaGetSymbolAddress((void**)&proj,   g_proj);
    cudaGetSymbolAddress((void**)&q,      g_q);
    cudaGetSymbolAddress((void**)&k,      g_k);
    cudaGetSymbolAddress((void**)&v,      g_v);
    cudaGetSymbolAddress((void**)&beta,   g_beta);
    cudaGetSymbolAddress((void**)&decay,  g_decay);
    cudaGetSymbolAddress((void**)&o,      g_o);
    cudaGetSymbolAddress((void**)&hs_t,   g_hs_t);
    cudaGetSymbolAddress((void**)&wproj,  g_wproj);
    cudaGetSymbolAddress((void**)&wout_t, g_wout_t);

    cudaFuncSetAttribute(gemm_tf32_kernel,
                         cudaFuncAttributeMaxDynamicSharedMemorySize, GEMM_SMEM);

    // 0) tf32 rounding pre-passes
    {
        size_t n4 = (size_t)BT * DMODEL / 4;
        cvt_tf32_kernel<<<(unsigned)((n4 + 255) / 256), 256>>>(hs, hs_t, n4);
        n4 = (size_t)VALDIM * DMODEL / 4;
        cvt_tf32_kernel<<<(unsigned)((n4 + 255) / 256), 256>>>(W_out, wout_t, n4);
        size_t n = (size_t)DMODEL * PROJ_N;
        pack_wproj_kernel<<<(unsigned)((n + 255) / 256), 256>>>(W_qkv, W_z, W_b, W_a, wproj);
    }

    // 1) fused projection GEMM (qkv | z | b | a)
    launch_gemm(hs_t, wproj, proj, BT, PROJ_N, DMODEL);

    // 2) conv + silu + split
    {
        size_t n = (size_t)BT * CONVDIM;
        conv_silu_split_kernel<<<(unsigned)((n + 255) / 256), 256>>>(proj, conv_w, q, k, v);
    }

    // 3) l2 norm q/k
    {
        int rows = 2 * BT * NKH;
        l2norm_qk_kernel<<<(rows + 7) / 8, 256>>>(q, k);
    }

    // 4) beta/decay
    beta_decay_kernel<<<(BT * NVH + 255) / 256, 256>>>(proj, dt_bias, A_log, beta, decay);

    // 5) gated delta scan
    scan_kernel<<<BATCH * NVH * 2, 128>>>(q, k, v, decay, beta, o);

    // 6) gated rmsnorm (rounds o to tf32)
    {
        int rows = BT * NVH;
        gate_kernel<<<(rows + 7) / 8, 256>>>(o, proj, norm_w);
    }

    // 7) output projection
    launch_gemm(o, wout_t, out, BT, DMODEL, VALDIM);
}

// round 6
// speedup vs baseline: 1.4212x; 1.0163x over previous
#include <cuda_runtime.h>
#include <math.h>
#include <stdint.h>

// ---------------------------------------------------------------------------
// Problem constants (Qwen3.5 GatedDeltaNet): B=2, T=4096, D=2048
// ---------------------------------------------------------------------------
#define BATCH   2
#define TLEN    4096
#define BT      8192
#define DMODEL  2048
#define NVH     32
#define NKH     16
#define DK      128
#define DV      128
#define KEYDIM  (NKH*DK)                 // 2048
#define VALDIM  (NVH*DV)                 // 4096
#define CONVDIM (2*KEYDIM + VALDIM)      // 8192
#define PROJ_N  (CONVDIM + VALDIM + 64)  // 12352 : [qkv | z | b | a]
#define Z_OFF   CONVDIM                  // 8192
#define B_OFF   (CONVDIM + VALDIM)       // 12288
#define A_OFF   (B_OFF + 32)             // 12320

// ---------------------------------------------------------------------------
// Scratch (static device globals)
// ---------------------------------------------------------------------------
__device__ float g_proj[(size_t)BT * PROJ_N];      // fused projection output
__device__ float g_q[(size_t)BT * KEYDIM];
__device__ float g_k[(size_t)BT * KEYDIM];
__device__ float g_v[(size_t)BT * VALDIM];
__device__ float g_beta[BT * NVH];
__device__ float g_decay[BT * NVH];
__device__ float g_o[(size_t)BT * VALDIM];
// tf32-rounded operands
__device__ float g_hs_t[(size_t)BT * DMODEL];
__device__ float g_wproj[(size_t)DMODEL * PROJ_N]; // packed [Wqkv|Wz|Wb|Wa]
__device__ float g_wout_t[(size_t)VALDIM * DMODEL];

__device__ __forceinline__ float f2tf_f(float x) {
    uint32_t r; asm("cvt.rna.tf32.f32 %0, %1;" : "=r"(r) : "f"(x));
    return __uint_as_float(r);
}

// ---------------------------------------------------------------------------
// TF32 tensor-core GEMM: C[M,N] = A[M,K] @ B[K,N], row-major fp32 in/out.
// Operands pre-rounded to tf32. 128x128x16 tile, 256 thr, 3-stage cp.async.
// A fragments via ldmatrix.x4, B via scalar LDS.
// 1-D grid + grouped rasterization (GROUP_M bm-rows per group) for L2 reuse.
// ---------------------------------------------------------------------------
#define TSTAGES 3
#define TBM 128
#define TBN 128
#define TBK 16
#define LDA_S 20
#define LDB_S 136
#define A_STAGE (TBM*LDA_S) // 2560 floats
#define B_STAGE (TBK*LDB_S) // 2176 floats
#define GEMM_SMEM (TSTAGES*(A_STAGE+B_STAGE)*4)   // 56832 bytes
#define GROUP_M 8

__device__ __forceinline__ void cp16(float* dst, const float* src, bool pred) {
    uint32_t d = (uint32_t)__cvta_generic_to_shared(dst);
    int sz = pred ? 16 : 0;
    asm volatile("cp.async.cg.shared.global [%0], [%1], 16, %2;\n"
                 :: "r"(d), "l"(src), "r"(sz));
}

__device__ __forceinline__ void ldsm_x4(uint32_t* r, uint32_t addr) {
    asm volatile("ldmatrix.sync.aligned.m8n8.x4.shared.b16 {%0,%1,%2,%3}, [%4];"
        : "=r"(r[0]), "=r"(r[1]), "=r"(r[2]), "=r"(r[3]) : "r"(addr));
}

__device__ __forceinline__ void mma_tf32(float* c, const uint32_t* a, const uint32_t* b) {
    asm volatile(
        "mma.sync.aligned.m16n8k8.row.col.f32.tf32.tf32.f32 "
        "{%0,%1,%2,%3}, {%4,%5,%6,%7}, {%8,%9}, {%0,%1,%2,%3};"
        : "+f"(c[0]), "+f"(c[1]), "+f"(c[2]), "+f"(c[3])
        : "r"(a[0]), "r"(a[1]), "r"(a[2]), "r"(a[3]), "r"(b[0]), "r"(b[1]));
}

__global__ __launch_bounds__(256, 2) void gemm_tf32_kernel(
    const float* __restrict__ A, const float* __restrict__ B,
    float* __restrict__ C, int M, int N, int K)
{
    extern __shared__ float smem[];
    float* As = smem;
    float* Bs = smem + TSTAGES * A_STAGE;

    // ---- grouped rasterization: linear pid -> (bm, bn) ----
    const int num_bm = M / TBM;
    const int num_bn = (N + TBN - 1) / TBN;
    const int pid    = blockIdx.x;
    const int pids_per_group = GROUP_M * num_bn;
    const int group_id  = pid / pids_per_group;
    const int first_bm  = group_id * GROUP_M;
    const int gsz       = min(GROUP_M, num_bm - first_bm);
    const int bm        = first_bm + (pid % pids_per_group) % gsz;
    const int bn        = (pid % pids_per_group) / gsz;

    const int tid  = threadIdx.x;
    const int warp = tid >> 5;
    const int lane = tid & 31;
    const int g    = lane >> 2;
    const int tig  = lane & 3;
    const int wm   = (warp >> 2) * 64;
    const int wn   = (warp & 3) * 32;

    float acc[4][4][4];
#pragma unroll
    for (int i = 0; i < 4; i++)
#pragma unroll
        for (int j = 0; j < 4; j++)
#pragma unroll
            for (int r = 0; r < 4; r++) acc[i][j][r] = 0.f;

    const int KT = K / TBK;

    const uint32_t a_smem_u32 = (uint32_t)__cvta_generic_to_shared(As);
    const uint32_t a_lane_off = (((lane & 15) + wm) * LDA_S + 4 * (lane >> 4)) * 4;

    auto load_stage = [&](int s, int kt) {
        float* as = As + s * A_STAGE;
        float* bs = Bs + s * B_STAGE;
#pragma unroll
        for (int h = 0; h < 2; h++) {           // A: 128 rows x 4 float4
            int id  = tid + h * 256;
            int row = id >> 2, c = id & 3;
            const float* src = A + (size_t)(bm * TBM + row) * K + kt * TBK + c * 4;
            cp16(as + row * LDA_S + c * 4, src, true);
        }
#pragma unroll
        for (int h = 0; h < 2; h++) {           // B: 16 rows x 32 float4
            int id  = tid + h * 256;
            int row = id >> 5, c = id & 31;
            int col = bn * TBN + c * 4;
            bool ok = col < N;
            const float* src = B + (size_t)(kt * TBK + row) * N + (ok ? col : 0);
            cp16(bs + row * LDB_S + c * 4, src, ok);
        }
        asm volatile("cp.async.commit_group;");
    };

    load_stage(0, 0);
    load_stage(1, 1);

    for (int kt = 0; kt < KT; kt++) {
        asm volatile("cp.async.wait_group 1;");
        __syncthreads();

        if (kt + 2 < KT) load_stage((kt + 2) % TSTAGES, kt + 2);
        else             asm volatile("cp.async.commit_group;");

        const int st = kt % TSTAGES;
        const uint32_t as_u = a_smem_u32 + (uint32_t)(st * A_STAGE * 4) + a_lane_off;
        const float* bs = Bs + st * B_STAGE;

#pragma unroll
        for (int kk = 0; kk < 2; kk++) {
            const int k0 = kk * 8;
            uint32_t af[4][4], bf[4][2];
#pragma unroll
            for (int i = 0; i < 4; i++)
                ldsm_x4(af[i], as_u + (uint32_t)((k0 + 16 * i * LDA_S) * 4));
#pragma unroll
            for (int j = 0; j < 4; j++) {
                int cn = wn + 8 * j + g;
                bf[j][0] = *(const uint32_t*)&bs[(k0 + tig    ) * LDB_S + cn];
                bf[j][1] = *(const uint32_t*)&bs[(k0 + tig + 4) * LDB_S + cn];
            }
#pragma unroll
            for (int i = 0; i < 4; i++)
#pragma unroll
                for (int j = 0; j < 4; j++)
                    mma_tf32(acc[i][j], af[i], bf[j]);
        }
    }

#pragma unroll
    for (int i = 0; i < 4; i++) {
        int r0 = bm * TBM + wm + 16 * i + g;
#pragma unroll
        for (int j = 0; j < 4; j++) {
            int cn = bn * TBN + wn + 8 * j + 2 * tig;
            if (cn < N) {
                *(float2*)(C + (size_t)r0 * N + cn)       = make_float2(acc[i][j][0], acc[i][j][1]);
                *(float2*)(C + (size_t)(r0 + 8) * N + cn) = make_float2(acc[i][j][2], acc[i][j][3]);
            }
        }
    }
}

static inline void launch_gemm(const float* A, const float* B, float* C,
                               int M, int N, int K)
{
    int num_bm = M / TBM;
    int num_bn = (N + TBN - 1) / TBN;
    gemm_tf32_kernel<<<num_bm * num_bn, 256, GEMM_SMEM>>>(A, B, C, M, N, K);
}

// ---------------------------------------------------------------------------
// Elementwise tf32 rounding pre-pass (float4 vectorized)
// ---------------------------------------------------------------------------
__global__ void cvt_tf32_kernel(const float* __restrict__ src,
                                float* __restrict__ dst, size_t n4)
{
    size_t i = (size_t)blockIdx.x * blockDim.x + threadIdx.x;
    if (i >= n4) return;
    float4 x = ((const float4*)src)[i];
    x.x = f2tf_f(x.x); x.y = f2tf_f(x.y); x.z = f2tf_f(x.z); x.w = f2tf_f(x.w);
    ((float4*)dst)[i] = x;
}

// Pack [W_qkv | W_z | W_b | W_a] into [DMODEL, PROJ_N], tf32-rounded
__global__ void pack_wproj_kernel(const float* __restrict__ Wqkv,
                                  const float* __restrict__ Wz,
                                  const float* __restrict__ Wb,
                                  const float* __restrict__ Wa,
                                  float* __restrict__ Wp)
{
    size_t idx = (size_t)blockIdx.x * blockDim.x + threadIdx.x;
    if (idx >= (size_t)DMODEL * PROJ_N) return;
    int k = (int)(idx / PROJ_N);
    int j = (int)(idx - (size_t)k * PROJ_N);
    float val;
    if      (j < Z_OFF) val = Wqkv[(size_t)k * CONVDIM + j];
    else if (j < B_OFF) val = Wz[(size_t)k * VALDIM + (j - Z_OFF)];
    else if (j < A_OFF) val = Wb[k * 32 + (j - B_OFF)];
    else                val = Wa[k * 32 + (j - A_OFF)];
    Wp[idx] = f2tf_f(val);
}

// ---------------------------------------------------------------------------
// Causal depthwise conv (KC=4) + SiLU + split into q/k/v
// ---------------------------------------------------------------------------
__global__ void conv_silu_split_kernel(const float* __restrict__ proj,
                                       const float* __restrict__ conv_w,
                                       float* __restrict__ q,
                                       float* __restrict__ k,
                                       float* __restrict__ v)
{
    size_t idx = (size_t)blockIdx.x * blockDim.x + threadIdx.x;
    if (idx >= (size_t)BT * CONVDIM) return;
    int c = (int)(idx & (CONVDIM - 1));
    size_t bt = idx >> 13;
    int t = (int)(bt & (TLEN - 1));

    float4 w = *(const float4*)(conv_w + (size_t)c * 4);
    const float* base = proj + c;
    float x0 = (t >= 3) ? base[(bt - 3) * PROJ_N] : 0.f;
    float x1 = (t >= 2) ? base[(bt - 2) * PROJ_N] : 0.f;
    float x2 = (t >= 1) ? base[(bt - 1) * PROJ_N] : 0.f;
    float x3 = base[bt * PROJ_N];

    float acc = x0 * w.x + x1 * w.y + x2 * w.z + x3 * w.w;
    float s = acc / (1.f + expf(-acc));

    if (c < KEYDIM)           q[bt * KEYDIM + c] = s;
    else if (c < 2 * KEYDIM)  k[bt * KEYDIM + (c - KEYDIM)] = s;
    else                      v[bt * VALDIM + (c - 2 * KEYDIM)] = s;
}

// ---------------------------------------------------------------------------
// L2 norm over DK=128 (one warp per row); q gets extra DK^-0.5
// ---------------------------------------------------------------------------
__global__ void l2norm_qk_kernel(float* __restrict__ q, float* __restrict__ k)
{
    int wg   = (blockIdx.x * blockDim.x + threadIdx.x) >> 5;
    int lane = threadIdx.x & 31;
    const int nrows = BT * NKH;
    if (wg >= 2 * nrows) return;

    float* base;
    float extra;
    if (wg < nrows) { base = q + (size_t)wg * DK; extra = 0.08838834764831845f; }
    else            { base = k + (size_t)(wg - nrows) * DK; extra = 1.f; }

    float4 x = ((float4*)base)[lane];
    float ss = x.x*x.x + x.y*x.y + x.z*x.z + x.w*x.w;
#pragma unroll
    for (int off = 16; off > 0; off >>= 1)
        ss += __shfl_xor_sync(0xffffffffu, ss, off);
    float inv = rsqrtf(ss + 1e-6f) * extra;
    x.x *= inv; x.y *= inv; x.z *= inv; x.w *= inv;
    ((float4*)base)[lane] = x;
}

// ---------------------------------------------------------------------------
// beta = sigmoid(b); decay = exp(-exp(A_log)*softplus(a + dt_bias))
// ---------------------------------------------------------------------------
__global__ void beta_decay_kernel(const float* __restrict__ proj,
                                  const float* __restrict__ dt_bias,
                                  const float* __restrict__ A_log,
                                  float* __restrict__ beta,
                                  float* __restrict__ decay)
{
    int idx = blockIdx.x * blockDim.x + threadIdx.x;
    if (idx >= BT * NVH) return;
    int h = idx & (NVH - 1);
    size_t bt = (size_t)(idx >> 5);
    float b = proj[bt * PROJ_N + B_OFF + h];
    beta[idx] = 1.f / (1.f + expf(-b));
    float a = proj[bt * PROJ_N + A_OFF + h] + dt_bias[h];
    float sp = (a > 20.f) ? a : log1pf(expf(a));
    decay[idx] = expf(-expf(A_log[h]) * sp);
}

// ---------------------------------------------------------------------------
// Gated delta rule scan (128 blocks x 128 threads, 64 state regs/thread)
// ---------------------------------------------------------------------------
__global__ void __launch_bounds__(128) scan_kernel(
    const float* __restrict__ qn, const float* __restrict__ kn,
    const float* __restrict__ v,  const float* __restrict__ decay,
    const float* __restrict__ beta, float* __restrict__ o)
{
    const int blk = blockIdx.x;
    const int b   = blk >> 6;
    const int rem = blk & 63;
    const int h   = rem >> 1;
    const int seg = rem & 1;
    const int h2  = h >> 1;
    const int tid = threadIdx.x;
    const int col  = tid >> 1;
    const int half = tid & 1;
    const int gcol = seg * 64 + col;
    const int koff = half * 64;

    __shared__ float sq[128];
    __shared__ float sk[128];

    float S[64];
#pragma unroll
    for (int i = 0; i < 64; i++) S[i] = 0.f;

    const size_t bt0 = (size_t)b * TLEN;

    float pq = qn[((bt0)*NKH + h2) * DK + tid];
    float pk = kn[((bt0)*NKH + h2) * DK + tid];
    float pv = v [((bt0)*NVH + h ) * DV + gcol];
    float pd = decay[bt0 * NVH + h];
    float pb = beta [bt0 * NVH + h];

    for (int t = 0; t < TLEN; t++) {
        __syncthreads();
        sq[tid] = pq;
        sk[tid] = pk;
        float cv = pv, cd = pd, cb = pb;
        __syncthreads();

        if (t + 1 < TLEN) {
            size_t bt = bt0 + t + 1;
            pq = qn[(bt*NKH + h2) * DK + tid];
            pk = kn[(bt*NKH + h2) * DK + tid];
            pv = v [(bt*NVH + h ) * DV + gcol];
            pd = decay[bt * NVH + h];
            pb = beta [bt * NVH + h];
        }

        float a0 = 0.f, a1 = 0.f, a2 = 0.f, a3 = 0.f;
#pragma unroll
        for (int i = 0; i < 64; i += 4) {
            S[i+0] *= cd; a0 = fmaf(sk[koff+i+0], S[i+0], a0);
            S[i+1] *= cd; a1 = fmaf(sk[koff+i+1], S[i+1], a1);
            S[i+2] *= cd; a2 = fmaf(sk[koff+i+2], S[i+2], a2);
            S[i+3] *= cd; a3 = fmaf(sk[koff+i+3], S[i+3], a3);
        }
        float kS = (a0 + a1) + (a2 + a3);
        kS += __shfl_xor_sync(0xffffffffu, kS, 1);

        float upd = cb * (cv - kS);

        float o0 = 0.f, o1 = 0.f, o2 = 0.f, o3 = 0.f;
#pragma unroll
        for (int i = 0; i < 64; i += 4) {
            S[i+0] = fmaf(sk[koff+i+0], upd, S[i+0]); o0 = fmaf(sq[koff+i+0], S[i+0], o0);
            S[i+1] = fmaf(sk[koff+i+1], upd, S[i+1]); o1 = fmaf(sq[koff+i+1], S[i+1], o1);
            S[i+2] = fmaf(sk[koff+i+2], upd, S[i+2]); o2 = fmaf(sq[koff+i+2], S[i+2], o2);
            S[i+3] = fmaf(sk[koff+i+3], upd, S[i+3]); o3 = fmaf(sq[koff+i+3], S[i+3], o3);
        }
        float oa = (o0 + o1) + (o2 + o3);
        oa += __shfl_xor_sync(0xffffffffu, oa, 1);
        if (!half)
            o[((bt0 + t)*NVH + h) * DV + gcol] = oa;
    }
}

// ---------------------------------------------------------------------------
// Gated RMSNorm; z from fused projection buffer; output rounded to tf32
// ---------------------------------------------------------------------------
__global__ void gate_kernel(float* __restrict__ o, const float* __restrict__ proj,
                            const float* __restrict__ norm_w)
{
    int wg   = (blockIdx.x * blockDim.x + threadIdx.x) >> 5;
    int lane = threadIdx.x & 31;
    if (wg >= BT * NVH) return;

    float4* orow = (float4*)(o + (size_t)wg * DV);
    float4 x = orow[lane];
    float ss = x.x*x.x + x.y*x.y + x.z*x.z + x.w*x.w;
#pragma unroll
    for (int off = 16; off > 0; off >>= 1)
        ss += __shfl_xor_sync(0xffffffffu, ss, off);
    float r = rsqrtf(ss * (1.f / DV) + 1e-6f);

    size_t bt = (size_t)(wg >> 5);
    int h = wg & 31;
    const float* zrow = proj + bt * PROJ_N + Z_OFF + h * DV;
    float4 zv = ((const float4*)zrow)[lane];
    float4 nw = ((const float4*)norm_w)[lane];

    float s0 = zv.x / (1.f + expf(-zv.x));
    float s1 = zv.y / (1.f + expf(-zv.y));
    float s2 = zv.z / (1.f + expf(-zv.z));
    float s3 = zv.w / (1.f + expf(-zv.w));

    x.x = f2tf_f(x.x * r * nw.x * s0);
    x.y = f2tf_f(x.y * r * nw.y * s1);
    x.z = f2tf_f(x.z * r * nw.z * s2);
    x.w = f2tf_f(x.w * r * nw.w * s3);
    orow[lane] = x;
}

// ---------------------------------------------------------------------------
// Launch
// ---------------------------------------------------------------------------
extern "C" void kernel_launch(void* const* d_in, const int* in_sizes, int n_in,
                              void* d_out, int out_size)
{
    const float* hs      = (const float*)d_in[0];
    const float* W_qkv   = (const float*)d_in[1];
    const float* W_z     = (const float*)d_in[2];
    const float* W_b     = (const float*)d_in[3];
    const float* W_a     = (const float*)d_in[4];
    const float* conv_w  = (const float*)d_in[5];
    const float* dt_bias = (const float*)d_in[6];
    const float* A_log   = (const float*)d_in[7];
    const float* norm_w  = (const float*)d_in[8];
    const float* W_out   = (const float*)d_in[9];
    float* out = (float*)d_out;

    float *proj, *q, *k, *v, *beta, *decay, *o;
    float *hs_t, *wproj, *wout_t;
    cudaGetSymbolAddress((void**)&proj,   g_proj);
    cudaGetSymbolAddress((void**)&q,      g_q);
    cudaGetSymbolAddress((void**)&k,      g_k);
    cudaGetSymbolAddress((void**)&v,      g_v);
    cudaGetSymbolAddress((void**)&beta,   g_beta);
    cudaGetSymbolAddress((void**)&decay,  g_decay);
    cudaGetSymbolAddress((void**)&o,      g_o);
    cudaGetSymbolAddress((void**)&hs_t,   g_hs_t);
    cudaGetSymbolAddress((void**)&wproj,  g_wproj);
    cudaGetSymbolAddress((void**)&wout_t, g_wout_t);

    cudaFuncSetAttribute(gemm_tf32_kernel,
                         cudaFuncAttributeMaxDynamicSharedMemorySize, GEMM_SMEM);

    // 0) tf32 rounding pre-passes
    {
        size_t n4 = (size_t)BT * DMODEL / 4;
        cvt_tf32_kernel<<<(unsigned)((n4 + 255) / 256), 256>>>(hs, hs_t, n4);
        n4 = (size_t)VALDIM * DMODEL / 4;
        cvt_tf32_kernel<<<(unsigned)((n4 + 255) / 256), 256>>>(W_out, wout_t, n4);
        size_t n = (size_t)DMODEL * PROJ_N;
        pack_wproj_kernel<<<(unsigned)((n + 255) / 256), 256>>>(W_qkv, W_z, W_b, W_a, wproj);
    }

    // 1) fused projection GEMM (qkv | z | b | a)
    launch_gemm(hs_t, wproj, proj, BT, PROJ_N, DMODEL);

    // 2) conv + silu + split
    {
        size_t n = (size_t)BT * CONVDIM;
        conv_silu_split_kernel<<<(unsigned)((n + 255) / 256), 256>>>(proj, conv_w, q, k, v);
    }

    // 3) l2 norm q/k
    {
        int rows = 2 * BT * NKH;
        l2norm_qk_kernel<<<(rows + 7) / 8, 256>>>(q, k);
    }

    // 4) beta/decay
    beta_decay_kernel<<<(BT * NVH + 255) / 256, 256>>>(proj, dt_bias, A_log, beta, decay);

    // 5) gated delta scan
    scan_kernel<<<BATCH * NVH * 2, 128>>>(q, k, v, decay, beta, o);

    // 6) gated rmsnorm (rounds o to tf32)
    {
        int rows = BT * NVH;
        gate_kernel<<<(rows + 7) / 8, 256>>>(o, proj, norm_w);
    }

    // 7) output projection
    launch_gemm(o, wout_t, out, BT, DMODEL, VALDIM);
}

// round 8
// speedup vs baseline: 1.4301x; 1.0063x over previous
#include <cuda_runtime.h>
#include <math.h>
#include <stdint.h>

// ---------------------------------------------------------------------------
// Problem constants (Qwen3.5 GatedDeltaNet): B=2, T=4096, D=2048
// ---------------------------------------------------------------------------
#define BATCH   2
#define TLEN    4096
#define BT      8192
#define DMODEL  2048
#define NVH     32
#define NKH     16
#define DK      128
#define DV      128
#define KEYDIM  (NKH*DK)                 // 2048
#define VALDIM  (NVH*DV)                 // 4096
#define CONVDIM (2*KEYDIM + VALDIM)      // 8192
#define QB_N    (CONVDIM + 64)           // 8256 : [qkv | b | a]
#define B2_OFF  CONVDIM                  // 8192
#define A2_OFF  (CONVDIM + 32)           // 8224

// ---------------------------------------------------------------------------
// Scratch (static device globals)
// ---------------------------------------------------------------------------
__device__ float g_qkvba[(size_t)BT * QB_N];
__device__ float g_z[(size_t)BT * VALDIM];
__device__ float g_q[(size_t)BT * KEYDIM];
__device__ float g_k[(size_t)BT * KEYDIM];
__device__ float g_v[(size_t)BT * VALDIM];
__device__ float g_beta[BT * NVH];
__device__ float g_decay[BT * NVH];
__device__ float g_o[(size_t)BT * VALDIM];
// tf32-rounded operands
__device__ float g_hs_t[(size_t)BT * DMODEL];
__device__ float g_wqkvba[(size_t)DMODEL * QB_N];
__device__ float g_wz_t[(size_t)DMODEL * VALDIM];
__device__ float g_wout_t[(size_t)VALDIM * DMODEL];

__device__ __forceinline__ float f2tf_f(float x) {
    uint32_t r; asm("cvt.rna.tf32.f32 %0, %1;" : "=r"(r) : "f"(x));
    return __uint_as_float(r);
}

// ---------------------------------------------------------------------------
// TF32 tensor-core GEMM (mma.sync): C[M,N] = A[M,K] @ B[K,N], row-major.
// Operands pre-rounded to tf32. 128x128x16 tile, 256 thr, 3-stage cp.async.
// A fragments via ldmatrix.x4, B via scalar LDS.
// 1-D grid + grouped rasterization for L2 reuse.
// ---------------------------------------------------------------------------
#define TSTAGES 3
#define TBM 128
#define TBN 128
#define TBK 16
#define LDA_S 20
#define LDB_S 136
#define A_STAGE (TBM*LDA_S) // 2560 floats
#define B_STAGE (TBK*LDB_S) // 2176 floats
#define GEMM_SMEM (TSTAGES*(A_STAGE+B_STAGE)*4)   // 56832 bytes
#define GROUP_M 8

__device__ __forceinline__ void cp16(float* dst, const float* src, bool pred) {
    uint32_t d = (uint32_t)__cvta_generic_to_shared(dst);
    int sz = pred ? 16 : 0;
    asm volatile("cp.async.cg.shared.global [%0], [%1], 16, %2;\n"
                 :: "r"(d), "l"(src), "r"(sz));
}

__device__ __forceinline__ void ldsm_x4(uint32_t* r, uint32_t addr) {
    asm volatile("ldmatrix.sync.aligned.m8n8.x4.shared.b16 {%0,%1,%2,%3}, [%4];"
        : "=r"(r[0]), "=r"(r[1]), "=r"(r[2]), "=r"(r[3]) : "r"(addr));
}

__device__ __forceinline__ void mma_tf32(float* c, const uint32_t* a, const uint32_t* b) {
    asm volatile(
        "mma.sync.aligned.m16n8k8.row.col.f32.tf32.tf32.f32 "
        "{%0,%1,%2,%3}, {%4,%5,%6,%7}, {%8,%9}, {%0,%1,%2,%3};"
        : "+f"(c[0]), "+f"(c[1]), "+f"(c[2]), "+f"(c[3])
        : "r"(a[0]), "r"(a[1]), "r"(a[2]), "r"(a[3]), "r"(b[0]), "r"(b[1]));
}

__global__ __launch_bounds__(256, 2) void gemm_tf32_kernel(
    const float* __restrict__ A, const float* __restrict__ B,
    float* __restrict__ C, int M, int N, int K)
{
    extern __shared__ float smem[];
    float* As = smem;
    float* Bs = smem + TSTAGES * A_STAGE;

    // grouped rasterization: linear pid -> (bm, bn)
    const int num_bm = M / TBM;
    const int num_bn = (N + TBN - 1) / TBN;
    const int pid    = blockIdx.x;
    const int pids_per_group = GROUP_M * num_bn;
    const int group_id  = pid / pids_per_group;
    const int first_bm  = group_id * GROUP_M;
    const int gsz       = min(GROUP_M, num_bm - first_bm);
    const int bm        = first_bm + (pid % pids_per_group) % gsz;
    const int bn        = (pid % pids_per_group) / gsz;

    const int tid  = threadIdx.x;
    const int warp = tid >> 5;
    const int lane = tid & 31;
    const int g    = lane >> 2;
    const int tig  = lane & 3;
    const int wm   = (warp >> 2) * 64;
    const int wn   = (warp & 3) * 32;

    float acc[4][4][4];
#pragma unroll
    for (int i = 0; i < 4; i++)
#pragma unroll
        for (int j = 0; j < 4; j++)
#pragma unroll
            for (int r = 0; r < 4; r++) acc[i][j][r] = 0.f;

    const int KT = K / TBK;

    const uint32_t a_smem_u32 = (uint32_t)__cvta_generic_to_shared(As);
    const uint32_t a_lane_off = (((lane & 15) + wm) * LDA_S + 4 * (lane >> 4)) * 4;

    auto load_stage = [&](int s, int kt) {
        float* as = As + s * A_STAGE;
        float* bs = Bs + s * B_STAGE;
#pragma unroll
        for (int h = 0; h < 2; h++) {           // A: 128 rows x 4 float4
            int id  = tid + h * 256;
            int row = id >> 2, c = id & 3;
            const float* src = A + (size_t)(bm * TBM + row) * K + kt * TBK + c * 4;
            cp16(as + row * LDA_S + c * 4, src, true);
        }
#pragma unroll
        for (int h = 0; h < 2; h++) {           // B: 16 rows x 32 float4
            int id  = tid + h * 256;
            int row = id >> 5, c = id & 31;
            int col = bn * TBN + c * 4;
            bool ok = col < N;
            const float* src = B + (size_t)(kt * TBK + row) * N + (ok ? col : 0);
            cp16(bs + row * LDB_S + c * 4, src, ok);
        }
        asm volatile("cp.async.commit_group;");
    };

    load_stage(0, 0);
    load_stage(1, 1);

    for (int kt = 0; kt < KT; kt++) {
        asm volatile("cp.async.wait_group 1;");
        __syncthreads();

        if (kt + 2 < KT) load_stage((kt + 2) % TSTAGES, kt + 2);
        else             asm volatile("cp.async.commit_group;");

        const int st = kt % TSTAGES;
        const uint32_t as_u = a_smem_u32 + (uint32_t)(st * A_STAGE * 4) + a_lane_off;
        const float* bs = Bs + st * B_STAGE;

#pragma unroll
        for (int kk = 0; kk < 2; kk++) {
            const int k0 = kk * 8;
            uint32_t af[4][4], bf[4][2];
#pragma unroll
            for (int i = 0; i < 4; i++)
                ldsm_x4(af[i], as_u + (uint32_t)((k0 + 16 * i * LDA_S) * 4));
#pragma unroll
            for (int j = 0; j < 4; j++) {
                int cn = wn + 8 * j + g;
                bf[j][0] = *(const uint32_t*)&bs[(k0 + tig    ) * LDB_S + cn];
                bf[j][1] = *(const uint32_t*)&bs[(k0 + tig + 4) * LDB_S + cn];
            }
#pragma unroll
            for (int i = 0; i < 4; i++)
#pragma unroll
                for (int j = 0; j < 4; j++)
                    mma_tf32(acc[i][j], af[i], bf[j]);
        }
    }

#pragma unroll
    for (int i = 0; i < 4; i++) {
        int r0 = bm * TBM + wm + 16 * i + g;
#pragma unroll
        for (int j = 0; j < 4; j++) {
            int cn = bn * TBN + wn + 8 * j + 2 * tig;
            if (cn < N) {
                *(float2*)(C + (size_t)r0 * N + cn)       = make_float2(acc[i][j][0], acc[i][j][1]);
                *(float2*)(C + (size_t)(r0 + 8) * N + cn) = make_float2(acc[i][j][2], acc[i][j][3]);
            }
        }
    }
}

static inline void launch_gemm(const float* A, const float* B, float* C,
                               int M, int N, int K, cudaStream_t st)
{
    int num_bm = M / TBM;
    int num_bn = (N + TBN - 1) / TBN;
    gemm_tf32_kernel<<<num_bm * num_bn, 256, GEMM_SMEM, st>>>(A, B, C, M, N, K);
}

// ---------------------------------------------------------------------------
// Elementwise tf32 rounding pre-pass (float4 vectorized)
// ---------------------------------------------------------------------------
__global__ void cvt_tf32_kernel(const float* __restrict__ src,
                                float* __restrict__ dst, size_t n4)
{
    size_t i = (size_t)blockIdx.x * blockDim.x + threadIdx.x;
    if (i >= n4) return;
    float4 x = ((const float4*)src)[i];
    x.x = f2tf_f(x.x); x.y = f2tf_f(x.y); x.z = f2tf_f(x.z); x.w = f2tf_f(x.w);
    ((float4*)dst)[i] = x;
}

// Pack [W_qkv | W_b | W_a] into [DMODEL, QB_N], tf32-rounded
__global__ void pack_wqkvba_kernel(const float* __restrict__ Wqkv,
                                   const float* __restrict__ Wb,
                                   const float* __restrict__ Wa,
                                   float* __restrict__ Wp)
{
    size_t idx = (size_t)blockIdx.x * blockDim.x + threadIdx.x;
    if (idx >= (size_t)DMODEL * QB_N) return;
    int k = (int)(idx / QB_N);
    int j = (int)(idx - (size_t)k * QB_N);
    float val;
    if      (j < B2_OFF) val = Wqkv[(size_t)k * CONVDIM + j];
    else if (j < A2_OFF) val = Wb[k * 32 + (j - B2_OFF)];
    else                 val = Wa[k * 32 + (j - A2_OFF)];
    Wp[idx] = f2tf_f(val);
}

// ---------------------------------------------------------------------------
// Causal depthwise conv (KC=4) + SiLU + split into q/k/v (row stride QB_N)
// ---------------------------------------------------------------------------
__global__ void conv_silu_split_kernel(const float* __restrict__ proj,
                                       const float* __restrict__ conv_w,
                                       float* __restrict__ q,
                                       float* __restrict__ k,
                                       float* __restrict__ v)
{
    size_t idx = (size_t)blockIdx.x * blockDim.x + threadIdx.x;
    if (idx >= (size_t)BT * CONVDIM) return;
    int c = (int)(idx & (CONVDIM - 1));
    size_t bt = idx >> 13;
    int t = (int)(bt & (TLEN - 1));

    float4 w = *(const float4*)(conv_w + (size_t)c * 4);
    const float* base = proj + c;
    float x0 = (t >= 3) ? base[(bt - 3) * QB_N] : 0.f;
    float x1 = (t >= 2) ? base[(bt - 2) * QB_N] : 0.f;
    float x2 = (t >= 1) ? base[(bt - 1) * QB_N] : 0.f;
    float x3 = base[bt * QB_N];

    float acc = x0 * w.x + x1 * w.y + x2 * w.z + x3 * w.w;
    float s = acc / (1.f + expf(-acc));

    if (c < KEYDIM)           q[bt * KEYDIM + c] = s;
    else if (c < 2 * KEYDIM)  k[bt * KEYDIM + (c - KEYDIM)] = s;
    else                      v[bt * VALDIM + (c - 2 * KEYDIM)] = s;
}

// ---------------------------------------------------------------------------
// L2 norm over DK=128 (one warp per row); q gets extra DK^-0.5
// ---------------------------------------------------------------------------
__global__ void l2norm_qk_kernel(float* __restrict__ q, float* __restrict__ k)
{
    int wg   = (blockIdx.x * blockDim.x + threadIdx.x) >> 5;
    int lane = threadIdx.x & 31;
    const int nrows = BT * NKH;
    if (wg >= 2 * nrows) return;

    float* base;
    float extra;
    if (wg < nrows) { base = q + (size_t)wg * DK; extra = 0.08838834764831845f; }
    else            { base = k + (size_t)(wg - nrows) * DK; extra = 1.f; }

    float4 x = ((float4*)base)[lane];
    float ss = x.x*x.x + x.y*x.y + x.z*x.z + x.w*x.w;
#pragma unroll
    for (int off = 16; off > 0; off >>= 1)
        ss += __shfl_xor_sync(0xffffffffu, ss, off);
    float inv = rsqrtf(ss + 1e-6f) * extra;
    x.x *= inv; x.y *= inv; x.z *= inv; x.w *= inv;
    ((float4*)base)[lane] = x;
}

// ---------------------------------------------------------------------------
// beta = sigmoid(b); decay = exp(-exp(A_log)*softplus(a + dt_bias))
// ---------------------------------------------------------------------------
__global__ void beta_decay_kernel(const float* __restrict__ proj,
                                  const float* __restrict__ dt_bias,
                                  const float* __restrict__ A_log,
                                  float* __restrict__ beta,
                                  float* __restrict__ decay)
{
    int idx = blockIdx.x * blockDim.x + threadIdx.x;
    if (idx >= BT * NVH) return;
    int h = idx & (NVH - 1);
    size_t bt = (size_t)(idx >> 5);
    float b = proj[bt * QB_N + B2_OFF + h];
    beta[idx] = 1.f / (1.f + expf(-b));
    float a = proj[bt * QB_N + A2_OFF + h] + dt_bias[h];
    float sp = (a > 20.f) ? a : log1pf(expf(a));
    decay[idx] = expf(-expf(A_log[h]) * sp);
}

// ---------------------------------------------------------------------------
// Gated delta rule scan (128 blocks x 128 threads, 64 state regs/thread)
// ---------------------------------------------------------------------------
__global__ void __launch_bounds__(128) scan_kernel(
    const float* __restrict__ qn, const float* __restrict__ kn,
    const float* __restrict__ v,  const float* __restrict__ decay,
    const float* __restrict__ beta, float* __restrict__ o)
{
    const int blk = blockIdx.x;
    const int b   = blk >> 6;
    const int rem = blk & 63;
    const int h   = rem >> 1;
    const int seg = rem & 1;
    const int h2  = h >> 1;
    const int tid = threadIdx.x;
    const int col  = tid >> 1;
    const int half = tid & 1;
    const int gcol = seg * 64 + col;
    const int koff = half * 64;

    __shared__ float sq[128];
    __shared__ float sk[128];

    float S[64];
#pragma unroll
    for (int i = 0; i < 64; i++) S[i] = 0.f;

    const size_t bt0 = (size_t)b * TLEN;

    float pq = qn[((bt0)*NKH + h2) * DK + tid];
    float pk = kn[((bt0)*NKH + h2) * DK + tid];
    float pv = v [((bt0)*NVH + h ) * DV + gcol];
    float pd = decay[bt0 * NVH + h];
    float pb = beta [bt0 * NVH + h];

    for (int t = 0; t < TLEN; t++) {
        __syncthreads();
        sq[tid] = pq;
        sk[tid] = pk;
        float cv = pv, cd = pd, cb = pb;
        __syncthreads();

        if (t + 1 < TLEN) {
            size_t bt = bt0 + t + 1;
            pq = qn[(bt*NKH + h2) * DK + tid];
            pk = kn[(bt*NKH + h2) * DK + tid];
            pv = v [(bt*NVH + h ) * DV + gcol];
            pd = decay[bt * NVH + h];
            pb = beta [bt * NVH + h];
        }

        float a0 = 0.f, a1 = 0.f, a2 = 0.f, a3 = 0.f;
#pragma unroll
        for (int i = 0; i < 64; i += 4) {
            S[i+0] *= cd; a0 = fmaf(sk[koff+i+0], S[i+0], a0);
            S[i+1] *= cd; a1 = fmaf(sk[koff+i+1], S[i+1], a1);
            S[i+2] *= cd; a2 = fmaf(sk[koff+i+2], S[i+2], a2);
            S[i+3] *= cd; a3 = fmaf(sk[koff+i+3], S[i+3], a3);
        }
        float kS = (a0 + a1) + (a2 + a3);
        kS += __shfl_xor_sync(0xffffffffu, kS, 1);

        float upd = cb * (cv - kS);

        float o0 = 0.f, o1 = 0.f, o2 = 0.f, o3 = 0.f;
#pragma unroll
        for (int i = 0; i < 64; i += 4) {
            S[i+0] = fmaf(sk[koff+i+0], upd, S[i+0]); o0 = fmaf(sq[koff+i+0], S[i+0], o0);
            S[i+1] = fmaf(sk[koff+i+1], upd, S[i+1]); o1 = fmaf(sq[koff+i+1], S[i+1], o1);
            S[i+2] = fmaf(sk[koff+i+2], upd, S[i+2]); o2 = fmaf(sq[koff+i+2], S[i+2], o2);
            S[i+3] = fmaf(sk[koff+i+3], upd, S[i+3]); o3 = fmaf(sq[koff+i+3], S[i+3], o3);
        }
        float oa = (o0 + o1) + (o2 + o3);
        oa += __shfl_xor_sync(0xffffffffu, oa, 1);
        if (!half)
            o[((bt0 + t)*NVH + h) * DV + gcol] = oa;
    }
}

// ---------------------------------------------------------------------------
// Gated RMSNorm; z from dedicated buffer; output rounded to tf32
// ---------------------------------------------------------------------------
__global__ void gate_kernel(float* __restrict__ o, const float* __restrict__ z,
                            const float* __restrict__ norm_w)
{
    int wg   = (blockIdx.x * blockDim.x + threadIdx.x) >> 5;
    int lane = threadIdx.x & 31;
    if (wg >= BT * NVH) return;

    float4* orow = (float4*)(o + (size_t)wg * DV);
    float4 x = orow[lane];
    float ss = x.x*x.x + x.y*x.y + x.z*x.z + x.w*x.w;
#pragma unroll
    for (int off = 16; off > 0; off >>= 1)
        ss += __shfl_xor_sync(0xffffffffu, ss, off);
    float r = rsqrtf(ss * (1.f / DV) + 1e-6f);

    float4 zv = ((const float4*)(z + (size_t)wg * DV))[lane];
    float4 nw = ((const float4*)norm_w)[lane];

    float s0 = zv.x / (1.f + expf(-zv.x));
    float s1 = zv.y / (1.f + expf(-zv.y));
    float s2 = zv.z / (1.f + expf(-zv.z));
    float s3 = zv.w / (1.f + expf(-zv.w));

    x.x = f2tf_f(x.x * r * nw.x * s0);
    x.y = f2tf_f(x.y * r * nw.y * s1);
    x.z = f2tf_f(x.z * r * nw.z * s2);
    x.w = f2tf_f(x.w * r * nw.w * s3);
    orow[lane] = x;
}

// ---------------------------------------------------------------------------
// Launch: fork z-projection onto a second stream, overlapped with the
// conv -> l2norm -> beta/decay -> scan chain; join before gate.
// ---------------------------------------------------------------------------
extern "C" void kernel_launch(void* const* d_in, const int* in_sizes, int n_in,
                              void* d_out, int out_size)
{
    const float* hs      = (const float*)d_in[0];
    const float* W_qkv   = (const float*)d_in[1];
    const float* W_z     = (const float*)d_in[2];
    const float* W_b     = (const float*)d_in[3];
    const float* W_a     = (const float*)d_in[4];
    const float* conv_w  = (const float*)d_in[5];
    const float* dt_bias = (const float*)d_in[6];
    const float* A_log   = (const float*)d_in[7];
    const float* norm_w  = (const float*)d_in[8];
    const float* W_out   = (const float*)d_in[9];
    float* out = (float*)d_out;

    float *qkvba, *z, *q, *k, *v, *beta, *decay, *o;
    float *hs_t, *wqkvba, *wz_t, *wout_t;
    cudaGetSymbolAddress((void**)&qkvba,  g_qkvba);
    cudaGetSymbolAddress((void**)&z,      g_z);
    cudaGetSymbolAddress((void**)&q,      g_q);
    cudaGetSymbolAddress((void**)&k,      g_k);
    cudaGetSymbolAddress((void**)&v,      g_v);
    cudaGetSymbolAddress((void**)&beta,   g_beta);
    cudaGetSymbolAddress((void**)&decay,  g_decay);
    cudaGetSymbolAddress((void**)&o,      g_o);
    cudaGetSymbolAddress((void**)&hs_t,   g_hs_t);
    cudaGetSymbolAddress((void**)&wqkvba, g_wqkvba);
    cudaGetSymbolAddress((void**)&wz_t,   g_wz_t);
    cudaGetSymbolAddress((void**)&wout_t, g_wout_t);

    // one-time infra (streams/events are not device allocations)
    static cudaStream_t s1 = nullptr;
    static cudaEvent_t ev_hs = nullptr, ev_z = nullptr;
    static bool init_done = false;
    if (!init_done) {
        cudaStreamCreateWithFlags(&s1, cudaStreamNonBlocking);
        cudaEventCreateWithFlags(&ev_hs, cudaEventDisableTiming);
        cudaEventCreateWithFlags(&ev_z,  cudaEventDisableTiming);
        cudaFuncSetAttribute(gemm_tf32_kernel,
                             cudaFuncAttributeMaxDynamicSharedMemorySize, GEMM_SMEM);
        init_done = true;
    }

    const cudaStream_t s0 = 0;

    // 0) tf32 rounding pre-passes
    {
        size_t n4 = (size_t)BT * DMODEL / 4;
        cvt_tf32_kernel<<<(unsigned)((n4 + 255) / 256), 256, 0, s0>>>(hs, hs_t, n4);
        cudaEventRecord(ev_hs, s0);

        size_t n = (size_t)DMODEL * QB_N;
        pack_wqkvba_kernel<<<(unsigned)((n + 255) / 256), 256, 0, s0>>>(W_qkv, W_b, W_a, wqkvba);
    }

    // ---- stream1: z projection (+ wout rounding), joined before gate ----
    cudaStreamWaitEvent(s1, ev_hs, 0);
    {
        size_t n4 = (size_t)DMODEL * VALDIM / 4;
        cvt_tf32_kernel<<<(unsigned)((n4 + 255) / 256), 256, 0, s1>>>(W_z, wz_t, n4);
        n4 = (size_t)VALDIM * DMODEL / 4;
        cvt_tf32_kernel<<<(unsigned)((n4 + 255) / 256), 256, 0, s1>>>(W_out, wout_t, n4);
        launch_gemm(hs_t, wz_t, z, BT, VALDIM, DMODEL, s1);
        cudaEventRecord(ev_z, s1);
    }

    // ---- stream0: qkv|b|a projection + scan chain ----
    launch_gemm(hs_t, wqkvba, qkvba, BT, QB_N, DMODEL, s0);

    {
        size_t n = (size_t)BT * CONVDIM;
        conv_silu_split_kernel<<<(unsigned)((n + 255) / 256), 256, 0, s0>>>(qkvba, conv_w, q, k, v);
    }
    {
        int rows = 2 * BT * NKH;
        l2norm_qk_kernel<<<(rows + 7) / 8, 256, 0, s0>>>(q, k);
    }
    beta_decay_kernel<<<(BT * NVH + 255) / 256, 256, 0, s0>>>(qkvba, dt_bias, A_log, beta, decay);

    scan_kernel<<<BATCH * NVH * 2, 128, 0, s0>>>(q, k, v, decay, beta, o);

    // join: gate needs z (stream1)
    cudaStreamWaitEvent(s0, ev_z, 0);
    {
        int rows = BT * NVH;
        gate_kernel<<<(rows + 7) / 8, 256, 0, s0>>>(o, z, norm_w);
    }

    // output projection
    launch_gemm(o, wout_t, out, BT, DMODEL, VALDIM, s0);
}

// round 9
// speedup vs baseline: 1.4863x; 1.0393x over previous
#include <cuda_runtime.h>
#include <math.h>
#include <stdint.h>

// ---------------------------------------------------------------------------
// Problem constants (Qwen3.5 GatedDeltaNet): B=2, T=4096, D=2048
// ---------------------------------------------------------------------------
#define BATCH   2
#define TLEN    4096
#define BT      8192
#define DMODEL  2048
#define NVH     32
#define NKH     16
#define DK      128
#define DV      128
#define KEYDIM  (NKH*DK)                 // 2048
#define VALDIM  (NVH*DV)                 // 4096
#define CONVDIM (2*KEYDIM + VALDIM)      // 8192
#define QB_N    (CONVDIM + 64)           // 8256 : [qkv | b | a]
#define B2_OFF  CONVDIM                  // 8192
#define A2_OFF  (CONVDIM + 32)           // 8224

// ---------------------------------------------------------------------------
// Scratch (static device globals)
// ---------------------------------------------------------------------------
__device__ float g_qkvba[(size_t)BT * QB_N];
__device__ float g_z[(size_t)BT * VALDIM];
__device__ float g_q[(size_t)BT * KEYDIM];
__device__ float g_k[(size_t)BT * KEYDIM];
__device__ float g_v[(size_t)BT * VALDIM];
__device__ float g_beta[BT * NVH];
__device__ float g_decay[BT * NVH];
__device__ float g_o[(size_t)BT * VALDIM];
// tf32-rounded operands
__device__ float g_hs_t[(size_t)BT * DMODEL];
__device__ float g_wqkvba[(size_t)DMODEL * QB_N];
__device__ float g_wz_t[(size_t)DMODEL * VALDIM];
__device__ float g_wout_t[(size_t)VALDIM * DMODEL];

__device__ __forceinline__ float f2tf_f(float x) {
    uint32_t r; asm("cvt.rna.tf32.f32 %0, %1;" : "=r"(r) : "f"(x));
    return __uint_as_float(r);
}

// ---------------------------------------------------------------------------
// TF32 tensor-core GEMM (mma.sync): C[M,N] = A[M,K] @ B[K,N], row-major.
// Operands pre-rounded to tf32. 128x128x16 tile, 256 thr, 3-stage cp.async.
// A fragments via ldmatrix.x4, B via scalar LDS.
// 1-D grid + grouped rasterization for L2 reuse.
// ---------------------------------------------------------------------------
#define TSTAGES 3
#define TBM 128
#define TBN 128
#define TBK 16
#define LDA_S 20
#define LDB_S 136
#define A_STAGE (TBM*LDA_S) // 2560 floats
#define B_STAGE (TBK*LDB_S) // 2176 floats
#define GEMM_SMEM (TSTAGES*(A_STAGE+B_STAGE)*4)   // 56832 bytes
#define GROUP_M 8

__device__ __forceinline__ void cp16(float* dst, const float* src, bool pred) {
    uint32_t d = (uint32_t)__cvta_generic_to_shared(dst);
    int sz = pred ? 16 : 0;
    asm volatile("cp.async.cg.shared.global [%0], [%1], 16, %2;\n"
                 :: "r"(d), "l"(src), "r"(sz));
}

__device__ __forceinline__ void ldsm_x4(uint32_t* r, uint32_t addr) {
    asm volatile("ldmatrix.sync.aligned.m8n8.x4.shared.b16 {%0,%1,%2,%3}, [%4];"
        : "=r"(r[0]), "=r"(r[1]), "=r"(r[2]), "=r"(r[3]) : "r"(addr));
}

__device__ __forceinline__ void mma_tf32(float* c, const uint32_t* a, const uint32_t* b) {
    asm volatile(
        "mma.sync.aligned.m16n8k8.row.col.f32.tf32.tf32.f32 "
        "{%0,%1,%2,%3}, {%4,%5,%6,%7}, {%8,%9}, {%0,%1,%2,%3};"
        : "+f"(c[0]), "+f"(c[1]), "+f"(c[2]), "+f"(c[3])
        : "r"(a[0]), "r"(a[1]), "r"(a[2]), "r"(a[3]), "r"(b[0]), "r"(b[1]));
}

__global__ __launch_bounds__(256, 2) void gemm_tf32_kernel(
    const float* __restrict__ A, const float* __restrict__ B,
    float* __restrict__ C, int M, int N, int K)
{
    extern __shared__ float smem[];
    float* As = smem;
    float* Bs = smem + TSTAGES * A_STAGE;

    // grouped rasterization: linear pid -> (bm, bn)
    const int num_bm = M / TBM;
    const int num_bn = (N + TBN - 1) / TBN;
    const int pid    = blockIdx.x;
    const int pids_per_group = GROUP_M * num_bn;
    const int group_id  = pid / pids_per_group;
    const int first_bm  = group_id * GROUP_M;
    const int gsz       = min(GROUP_M, num_bm - first_bm);
    const int bm        = first_bm + (pid % pids_per_group) % gsz;
    const int bn        = (pid % pids_per_group) / gsz;

    const int tid  = threadIdx.x;
    const int warp = tid >> 5;
    const int lane = tid & 31;
    const int g    = lane >> 2;
    const int tig  = lane & 3;
    const int wm   = (warp >> 2) * 64;
    const int wn   = (warp & 3) * 32;

    float acc[4][4][4];
#pragma unroll
    for (int i = 0; i < 4; i++)
#pragma unroll
        for (int j = 0; j < 4; j++)
#pragma unroll
            for (int r = 0; r < 4; r++) acc[i][j][r] = 0.f;

    const int KT = K / TBK;

    const uint32_t a_smem_u32 = (uint32_t)__cvta_generic_to_shared(As);
    const uint32_t a_lane_off = (((lane & 15) + wm) * LDA_S + 4 * (lane >> 4)) * 4;

    auto load_stage = [&](int s, int kt) {
        float* as = As + s * A_STAGE;
        float* bs = Bs + s * B_STAGE;
#pragma unroll
        for (int h = 0; h < 2; h++) {           // A: 128 rows x 4 float4
            int id  = tid + h * 256;
            int row = id >> 2, c = id & 3;
            const float* src = A + (size_t)(bm * TBM + row) * K + kt * TBK + c * 4;
            cp16(as + row * LDA_S + c * 4, src, true);
        }
#pragma unroll
        for (int h = 0; h < 2; h++) {           // B: 16 rows x 32 float4
            int id  = tid + h * 256;
            int row = id >> 5, c = id & 31;
            int col = bn * TBN + c * 4;
            bool ok = col < N;
            const float* src = B + (size_t)(kt * TBK + row) * N + (ok ? col : 0);
            cp16(bs + row * LDB_S + c * 4, src, ok);
        }
        asm volatile("cp.async.commit_group;");
    };

    load_stage(0, 0);
    load_stage(1, 1);

    for (int kt = 0; kt < KT; kt++) {
        asm volatile("cp.async.wait_group 1;");
        __syncthreads();

        if (kt + 2 < KT) load_stage((kt + 2) % TSTAGES, kt + 2);
        else             asm volatile("cp.async.commit_group;");

        const int st = kt % TSTAGES;
        const uint32_t as_u = a_smem_u32 + (uint32_t)(st * A_STAGE * 4) + a_lane_off;
        const float* bs = Bs + st * B_STAGE;

#pragma unroll
        for (int kk = 0; kk < 2; kk++) {
            const int k0 = kk * 8;
            uint32_t af[4][4], bf[4][2];
#pragma unroll
            for (int i = 0; i < 4; i++)
                ldsm_x4(af[i], as_u + (uint32_t)((k0 + 16 * i * LDA_S) * 4));
#pragma unroll
            for (int j = 0; j < 4; j++) {
                int cn = wn + 8 * j + g;
                bf[j][0] = *(const uint32_t*)&bs[(k0 + tig    ) * LDB_S + cn];
                bf[j][1] = *(const uint32_t*)&bs[(k0 + tig + 4) * LDB_S + cn];
            }
#pragma unroll
            for (int i = 0; i < 4; i++)
#pragma unroll
                for (int j = 0; j < 4; j++)
                    mma_tf32(acc[i][j], af[i], bf[j]);
        }
    }

#pragma unroll
    for (int i = 0; i < 4; i++) {
        int r0 = bm * TBM + wm + 16 * i + g;
#pragma unroll
        for (int j = 0; j < 4; j++) {
            int cn = bn * TBN + wn + 8 * j + 2 * tig;
            if (cn < N) {
                *(float2*)(C + (size_t)r0 * N + cn)       = make_float2(acc[i][j][0], acc[i][j][1]);
                *(float2*)(C + (size_t)(r0 + 8) * N + cn) = make_float2(acc[i][j][2], acc[i][j][3]);
            }
        }
    }
}

static inline void launch_gemm(const float* A, const float* B, float* C,
                               int M, int N, int K, cudaStream_t st)
{
    int num_bm = M / TBM;
    int num_bn = (N + TBN - 1) / TBN;
    gemm_tf32_kernel<<<num_bm * num_bn, 256, GEMM_SMEM, st>>>(A, B, C, M, N, K);
}

// ---------------------------------------------------------------------------
// Elementwise tf32 rounding pre-pass (float4 vectorized)
// ---------------------------------------------------------------------------
__global__ void cvt_tf32_kernel(const float* __restrict__ src,
                                float* __restrict__ dst, size_t n4)
{
    size_t i = (size_t)blockIdx.x * blockDim.x + threadIdx.x;
    if (i >= n4) return;
    float4 x = ((const float4*)src)[i];
    x.x = f2tf_f(x.x); x.y = f2tf_f(x.y); x.z = f2tf_f(x.z); x.w = f2tf_f(x.w);
    ((float4*)dst)[i] = x;
}

// Pack [W_qkv | W_b | W_a] into [DMODEL, QB_N], tf32-rounded
__global__ void pack_wqkvba_kernel(const float* __restrict__ Wqkv,
                                   const float* __restrict__ Wb,
                                   const float* __restrict__ Wa,
                                   float* __restrict__ Wp)
{
    size_t idx = (size_t)blockIdx.x * blockDim.x + threadIdx.x;
    if (idx >= (size_t)DMODEL * QB_N) return;
    int k = (int)(idx / QB_N);
    int j = (int)(idx - (size_t)k * QB_N);
    float val;
    if      (j < B2_OFF) val = Wqkv[(size_t)k * CONVDIM + j];
    else if (j < A2_OFF) val = Wb[k * 32 + (j - B2_OFF)];
    else                 val = Wa[k * 32 + (j - A2_OFF)];
    Wp[idx] = f2tf_f(val);
}

// ---------------------------------------------------------------------------
// Causal depthwise conv (KC=4) + SiLU + split into q/k/v (row stride QB_N)
// ---------------------------------------------------------------------------
__global__ void conv_silu_split_kernel(const float* __restrict__ proj,
                                       const float* __restrict__ conv_w,
                                       float* __restrict__ q,
                                       float* __restrict__ k,
                                       float* __restrict__ v)
{
    size_t idx = (size_t)blockIdx.x * blockDim.x + threadIdx.x;
    if (idx >= (size_t)BT * CONVDIM) return;
    int c = (int)(idx & (CONVDIM - 1));
    size_t bt = idx >> 13;
    int t = (int)(bt & (TLEN - 1));

    float4 w = *(const float4*)(conv_w + (size_t)c * 4);
    const float* base = proj + c;
    float x0 = (t >= 3) ? base[(bt - 3) * QB_N] : 0.f;
    float x1 = (t >= 2) ? base[(bt - 2) * QB_N] : 0.f;
    float x2 = (t >= 1) ? base[(bt - 1) * QB_N] : 0.f;
    float x3 = base[bt * QB_N];

    float acc = x0 * w.x + x1 * w.y + x2 * w.z + x3 * w.w;
    float s = acc / (1.f + expf(-acc));

    if (c < KEYDIM)           q[bt * KEYDIM + c] = s;
    else if (c < 2 * KEYDIM)  k[bt * KEYDIM + (c - KEYDIM)] = s;
    else                      v[bt * VALDIM + (c - 2 * KEYDIM)] = s;
}

// ---------------------------------------------------------------------------
// L2 norm over DK=128 (one warp per row); q gets extra DK^-0.5
// ---------------------------------------------------------------------------
__global__ void l2norm_qk_kernel(float* __restrict__ q, float* __restrict__ k)
{
    int wg   = (blockIdx.x * blockDim.x + threadIdx.x) >> 5;
    int lane = threadIdx.x & 31;
    const int nrows = BT * NKH;
    if (wg >= 2 * nrows) return;

    float* base;
    float extra;
    if (wg < nrows) { base = q + (size_t)wg * DK; extra = 0.08838834764831845f; }
    else            { base = k + (size_t)(wg - nrows) * DK; extra = 1.f; }

    float4 x = ((float4*)base)[lane];
    float ss = x.x*x.x + x.y*x.y + x.z*x.z + x.w*x.w;
#pragma unroll
    for (int off = 16; off > 0; off >>= 1)
        ss += __shfl_xor_sync(0xffffffffu, ss, off);
    float inv = rsqrtf(ss + 1e-6f) * extra;
    x.x *= inv; x.y *= inv; x.z *= inv; x.w *= inv;
    ((float4*)base)[lane] = x;
}

// ---------------------------------------------------------------------------
// beta = sigmoid(b); decay = exp(-exp(A_log)*softplus(a + dt_bias))
// ---------------------------------------------------------------------------
__global__ void beta_decay_kernel(const float* __restrict__ proj,
                                  const float* __restrict__ dt_bias,
                                  const float* __restrict__ A_log,
                                  float* __restrict__ beta,
                                  float* __restrict__ decay)
{
    int idx = blockIdx.x * blockDim.x + threadIdx.x;
    if (idx >= BT * NVH) return;
    int h = idx & (NVH - 1);
    size_t bt = (size_t)(idx >> 5);
    float b = proj[bt * QB_N + B2_OFF + h];
    beta[idx] = 1.f / (1.f + expf(-b));
    float a = proj[bt * QB_N + A2_OFF + h] + dt_bias[h];
    float sp = (a > 20.f) ? a : log1pf(expf(a));
    decay[idx] = expf(-expf(A_log[h]) * sp);
}

// ---------------------------------------------------------------------------
// Gated delta rule scan (128 blocks x 128 threads, 64 state regs/thread)
// ---------------------------------------------------------------------------
__global__ void __launch_bounds__(128) scan_kernel(
    const float* __restrict__ qn, const float* __restrict__ kn,
    const float* __restrict__ v,  const float* __restrict__ decay,
    const float* __restrict__ beta, float* __restrict__ o)
{
    const int blk = blockIdx.x;
    const int b   = blk >> 6;
    const int rem = blk & 63;
    const int h   = rem >> 1;
    const int seg = rem & 1;
    const int h2  = h >> 1;
    const int tid = threadIdx.x;
    const int col  = tid >> 1;
    const int half = tid & 1;
    const int gcol = seg * 64 + col;
    const int koff = half * 64;

    __shared__ float sq[128];
    __shared__ float sk[128];

    float S[64];
#pragma unroll
    for (int i = 0; i < 64; i++) S[i] = 0.f;

    const size_t bt0 = (size_t)b * TLEN;

    float pq = qn[((bt0)*NKH + h2) * DK + tid];
    float pk = kn[((bt0)*NKH + h2) * DK + tid];
    float pv = v [((bt0)*NVH + h ) * DV + gcol];
    float pd = decay[bt0 * NVH + h];
    float pb = beta [bt0 * NVH + h];

    for (int t = 0; t < TLEN; t++) {
        __syncthreads();
        sq[tid] = pq;
        sk[tid] = pk;
        float cv = pv, cd = pd, cb = pb;
        __syncthreads();

        if (t + 1 < TLEN) {
            size_t bt = bt0 + t + 1;
            pq = qn[(bt*NKH + h2) * DK + tid];
            pk = kn[(bt*NKH + h2) * DK + tid];
            pv = v [(bt*NVH + h ) * DV + gcol];
            pd = decay[bt * NVH + h];
            pb = beta [bt * NVH + h];
        }

        float a0 = 0.f, a1 = 0.f, a2 = 0.f, a3 = 0.f;
#pragma unroll
        for (int i = 0; i < 64; i += 4) {
            S[i+0] *= cd; a0 = fmaf(sk[koff+i+0], S[i+0], a0);
            S[i+1] *= cd; a1 = fmaf(sk[koff+i+1], S[i+1], a1);
            S[i+2] *= cd; a2 = fmaf(sk[koff+i+2], S[i+2], a2);
            S[i+3] *= cd; a3 = fmaf(sk[koff+i+3], S[i+3], a3);
        }
        float kS = (a0 + a1) + (a2 + a3);
        kS += __shfl_xor_sync(0xffffffffu, kS, 1);

        float upd = cb * (cv - kS);

        float o0 = 0.f, o1 = 0.f, o2 = 0.f, o3 = 0.f;
#pragma unroll
        for (int i = 0; i < 64; i += 4) {
            S[i+0] = fmaf(sk[koff+i+0], upd, S[i+0]); o0 = fmaf(sq[koff+i+0], S[i+0], o0);
            S[i+1] = fmaf(sk[koff+i+1], upd, S[i+1]); o1 = fmaf(sq[koff+i+1], S[i+1], o1);
            S[i+2] = fmaf(sk[koff+i+2], upd, S[i+2]); o2 = fmaf(sq[koff+i+2], S[i+2], o2);
            S[i+3] = fmaf(sk[koff+i+3], upd, S[i+3]); o3 = fmaf(sq[koff+i+3], S[i+3], o3);
        }
        float oa = (o0 + o1) + (o2 + o3);
        oa += __shfl_xor_sync(0xffffffffu, oa, 1);
        if (!half)
            o[((bt0 + t)*NVH + h) * DV + gcol] = oa;
    }
}

// ---------------------------------------------------------------------------
// Gated RMSNorm; z from dedicated buffer; output rounded to tf32
// ---------------------------------------------------------------------------
__global__ void gate_kernel(float* __restrict__ o, const float* __restrict__ z,
                            const float* __restrict__ norm_w)
{
    int wg   = (blockIdx.x * blockDim.x + threadIdx.x) >> 5;
    int lane = threadIdx.x & 31;
    if (wg >= BT * NVH) return;

    float4* orow = (float4*)(o + (size_t)wg * DV);
    float4 x = orow[lane];
    float ss = x.x*x.x + x.y*x.y + x.z*x.z + x.w*x.w;
#pragma unroll
    for (int off = 16; off > 0; off >>= 1)
        ss += __shfl_xor_sync(0xffffffffu, ss, off);
    float r = rsqrtf(ss * (1.f / DV) + 1e-6f);

    float4 zv = ((const float4*)(z + (size_t)wg * DV))[lane];
    float4 nw = ((const float4*)norm_w)[lane];

    float s0 = zv.x / (1.f + expf(-zv.x));
    float s1 = zv.y / (1.f + expf(-zv.y));
    float s2 = zv.z / (1.f + expf(-zv.z));
    float s3 = zv.w / (1.f + expf(-zv.w));

    x.x = f2tf_f(x.x * r * nw.x * s0);
    x.y = f2tf_f(x.y * r * nw.y * s1);
    x.z = f2tf_f(x.z * r * nw.z * s2);
    x.w = f2tf_f(x.w * r * nw.w * s3);
    orow[lane] = x;
}

// ---------------------------------------------------------------------------
// Launch: z-projection deferred onto stream1 until the scan is runnable,
// so it executes inside the scan's low-occupancy window. Join before gate.
// ---------------------------------------------------------------------------
extern "C" void kernel_launch(void* const* d_in, const int* in_sizes, int n_in,
                              void* d_out, int out_size)
{
    const float* hs      = (const float*)d_in[0];
    const float* W_qkv   = (const float*)d_in[1];
    const float* W_z     = (const float*)d_in[2];
    const float* W_b     = (const float*)d_in[3];
    const float* W_a     = (const float*)d_in[4];
    const float* conv_w  = (const float*)d_in[5];
    const float* dt_bias = (const float*)d_in[6];
    const float* A_log   = (const float*)d_in[7];
    const float* norm_w  = (const float*)d_in[8];
    const float* W_out   = (const float*)d_in[9];
    float* out = (float*)d_out;

    float *qkvba, *z, *q, *k, *v, *beta, *decay, *o;
    float *hs_t, *wqkvba, *wz_t, *wout_t;
    cudaGetSymbolAddress((void**)&qkvba,  g_qkvba);
    cudaGetSymbolAddress((void**)&z,      g_z);
    cudaGetSymbolAddress((void**)&q,      g_q);
    cudaGetSymbolAddress((void**)&k,      g_k);
    cudaGetSymbolAddress((void**)&v,      g_v);
    cudaGetSymbolAddress((void**)&beta,   g_beta);
    cudaGetSymbolAddress((void**)&decay,  g_decay);
    cudaGetSymbolAddress((void**)&o,      g_o);
    cudaGetSymbolAddress((void**)&hs_t,   g_hs_t);
    cudaGetSymbolAddress((void**)&wqkvba, g_wqkvba);
    cudaGetSymbolAddress((void**)&wz_t,   g_wz_t);
    cudaGetSymbolAddress((void**)&wout_t, g_wout_t);

    // one-time infra (streams/events are not device allocations)
    static cudaStream_t s1 = nullptr;
    static cudaEvent_t ev_hs = nullptr, ev_fork = nullptr, ev_z = nullptr;
    static bool init_done = false;
    if (!init_done) {
        cudaStreamCreateWithFlags(&s1, cudaStreamNonBlocking);
        cudaEventCreateWithFlags(&ev_hs,   cudaEventDisableTiming);
        cudaEventCreateWithFlags(&ev_fork, cudaEventDisableTiming);
        cudaEventCreateWithFlags(&ev_z,    cudaEventDisableTiming);
        cudaFuncSetAttribute(gemm_tf32_kernel,
                             cudaFuncAttributeMaxDynamicSharedMemorySize, GEMM_SMEM);
        init_done = true;
    }

    const cudaStream_t s0 = 0;

    // 0) tf32 rounding pre-passes (s0); weight cvts for z/out on s1 (no deps)
    {
        size_t n4 = (size_t)DMODEL * VALDIM / 4;
        cvt_tf32_kernel<<<(unsigned)((n4 + 255) / 256), 256, 0, s1>>>(W_z, wz_t, n4);
        n4 = (size_t)VALDIM * DMODEL / 4;
        cvt_tf32_kernel<<<(unsigned)((n4 + 255) / 256), 256, 0, s1>>>(W_out, wout_t, n4);
    }
    {
        size_t n4 = (size_t)BT * DMODEL / 4;
        cvt_tf32_kernel<<<(unsigned)((n4 + 255) / 256), 256, 0, s0>>>(hs, hs_t, n4);
        cudaEventRecord(ev_hs, s0);

        size_t n = (size_t)DMODEL * QB_N;
        pack_wqkvba_kernel<<<(unsigned)((n + 255) / 256), 256, 0, s0>>>(W_qkv, W_b, W_a, wqkvba);
    }

    // ---- stream0: qkv|b|a projection + scan chain ----
    launch_gemm(hs_t, wqkvba, qkvba, BT, QB_N, DMODEL, s0);

    {
        size_t n = (size_t)BT * CONVDIM;
        conv_silu_split_kernel<<<(unsigned)((n + 255) / 256), 256, 0, s0>>>(qkvba, conv_w, q, k, v);
    }
    {
        int rows = 2 * BT * NKH;
        l2norm_qk_kernel<<<(rows + 7) / 8, 256, 0, s0>>>(q, k);
    }
    beta_decay_kernel<<<(BT * NVH + 255) / 256, 256, 0, s0>>>(qkvba, dt_bias, A_log, beta, decay);
    cudaEventRecord(ev_fork, s0);   // scan becomes runnable after this point

    scan_kernel<<<BATCH * NVH * 2, 128, 0, s0>>>(q, k, v, decay, beta, o);

    // ---- stream1: z projection co-scheduled with the scan window ----
    cudaStreamWaitEvent(s1, ev_hs, 0);
    cudaStreamWaitEvent(s1, ev_fork, 0);
    launch_gemm(hs_t, wz_t, z, BT, VALDIM, DMODEL, s1);
    cudaEventRecord(ev_z, s1);

    // join: gate needs z (stream1) and scan output (stream0)
    cudaStreamWaitEvent(s0, ev_z, 0);
    {
        int rows = BT * NVH;
        gate_kernel<<<(rows + 7) / 8, 256, 0, s0>>>(o, z, norm_w);
    }

    // output projection
    launch_gemm(o, wout_t, out, BT, DMODEL, VALDIM, s0);
}

// round 10
// speedup vs baseline: 1.8329x; 1.2332x over previous
#include <cuda_runtime.h>
#include <cuda_fp16.h>
#include <math.h>
#include <stdint.h>

// ---------------------------------------------------------------------------
// Problem constants (Qwen3.5 GatedDeltaNet): B=2, T=4096, D=2048
// ---------------------------------------------------------------------------
#define BATCH   2
#define TLEN    4096
#define BT      8192
#define DMODEL  2048
#define NVH     32
#define NKH     16
#define DK      128
#define DV      128
#define KEYDIM  (NKH*DK)                 // 2048
#define VALDIM  (NVH*DV)                 // 4096
#define CONVDIM (2*KEYDIM + VALDIM)      // 8192
#define QB_N    (CONVDIM + 64)           // 8256 : [qkv | b | a]
#define QBT_NP  8320                     // padded to 65*128 for B tiles
#define B2_OFF  CONVDIM                  // 8192
#define A2_OFF  (CONVDIM + 32)           // 8224

// ---------------------------------------------------------------------------
// Scratch (static device globals)
// ---------------------------------------------------------------------------
__device__ float  g_qkvba[(size_t)BT * QB_N];
__device__ float  g_z[(size_t)BT * VALDIM];
__device__ float  g_q[(size_t)BT * KEYDIM];
__device__ float  g_k[(size_t)BT * KEYDIM];
__device__ float  g_v[(size_t)BT * VALDIM];
__device__ float  g_beta[BT * NVH];
__device__ float  g_decay[BT * NVH];
__device__ float  g_o[(size_t)BT * VALDIM];
// half-precision GEMM operands
__device__ __half g_hs_h[(size_t)BT * DMODEL];
__device__ __half g_wqkvbaT[(size_t)QBT_NP * DMODEL];   // [N,K]
__device__ __half g_wzT[(size_t)VALDIM * DMODEL];       // [N,K]
__device__ __half g_woutT[(size_t)DMODEL * VALDIM];     // [N,K]
__device__ __half g_oh[(size_t)BT * VALDIM];            // gated o, half

// ---------------------------------------------------------------------------
// FP16 tensor-core GEMM (mma.sync m16n8k16, fp32 accum):
// C[M,N] = A[M,K] @ BT[N,K]^T ; A,BT half, C fp32.
// 128x128x32 tile, 256 thr (8 warps of 64x32), 3-stage cp.async.
// A frags via ldmatrix.x4; B via conflict-free scalar LDS.
// 1-D grid + grouped rasterization for L2 reuse.
// ---------------------------------------------------------------------------
#define TSTAGES 3
#define TBM 128
#define TBN 128
#define TBK 32
#define LDA_H 40                       // halves per smem row (80 B)
#define TILE_H (128*LDA_H)             // 5120 halves = 10240 B per operand
#define STAGE_B (2*TILE_H*2)           // 20480 B per stage (A+B)
#define GEMM_SMEM (TSTAGES*STAGE_B)    // 61440 B
#define GROUP_M 8

__device__ __forceinline__ void cp16h(uint32_t dst, const __half* src) {
    asm volatile("cp.async.cg.shared.global [%0], [%1], 16;" :: "r"(dst), "l"(src));
}

__device__ __forceinline__ void ldsm_x4(uint32_t* r, uint32_t addr) {
    asm volatile("ldmatrix.sync.aligned.m8n8.x4.shared.b16 {%0,%1,%2,%3}, [%4];"
        : "=r"(r[0]), "=r"(r[1]), "=r"(r[2]), "=r"(r[3]) : "r"(addr));
}

__device__ __forceinline__ void mma_f16(float* c, const uint32_t* a, const uint32_t* b) {
    asm volatile(
        "mma.sync.aligned.m16n8k16.row.col.f32.f16.f16.f32 "
        "{%0,%1,%2,%3}, {%4,%5,%6,%7}, {%8,%9}, {%0,%1,%2,%3};"
        : "+f"(c[0]), "+f"(c[1]), "+f"(c[2]), "+f"(c[3])
        : "r"(a[0]), "r"(a[1]), "r"(a[2]), "r"(a[3]), "r"(b[0]), "r"(b[1]));
}

__global__ __launch_bounds__(256, 2) void gemm_f16_kernel(
    const __half* __restrict__ A, const __half* __restrict__ BTm,
    float* __restrict__ C, int M, int N, int K)
{
    extern __shared__ char smem[];
    const uint32_t sbase = (uint32_t)__cvta_generic_to_shared(smem);

    // grouped rasterization: linear pid -> (bm, bn)
    const int num_bm = M / TBM;
    const int num_bn = (N + TBN - 1) / TBN;
    const int pid    = blockIdx.x;
    const int ppg    = GROUP_M * num_bn;
    const int gid    = pid / ppg;
    const int fbm    = gid * GROUP_M;
    const int gsz    = min(GROUP_M, num_bm - fbm);
    const int bm     = fbm + (pid % ppg) % gsz;
    const int bn     = (pid % ppg) / gsz;

    const int tid  = threadIdx.x;
    const int warp = tid >> 5;
    const int lane = tid & 31;
    const int g    = lane >> 2;
    const int tig  = lane & 3;
    const int wm   = (warp >> 2) * 64;   // 0 or 64
    const int wn   = (warp & 3) * 32;    // 0,32,64,96

    float acc[4][4][4];
#pragma unroll
    for (int i = 0; i < 4; i++)
#pragma unroll
        for (int j = 0; j < 4; j++)
#pragma unroll
            for (int r = 0; r < 4; r++) acc[i][j][r] = 0.f;

    const int KT = K / TBK;

    // ldmatrix per-lane byte offset within A tile:
    // lanes 0-7: rows 0-7 k0-7 | 8-15: rows 8-15 k0-7 | 16-23: rows 0-7 k8-15 | 24-31: rows 8-15 k8-15
    const uint32_t a_lm_off =
        (uint32_t)(((wm + (lane & 7) + 8 * ((lane >> 3) & 1)) * LDA_H + (lane >> 4) * 8) * 2);

    auto load_stage = [&](int s, int kt) {
        uint32_t abase = sbase + (uint32_t)(s * STAGE_B);
        uint32_t bbase = abase + (uint32_t)(TILE_H * 2);
        const __half* Asrc = A   + (size_t)(bm * TBM) * K + kt * TBK;
        const __half* Bsrc = BTm + (size_t)(bn * TBN) * K + kt * TBK;
#pragma unroll
        for (int h = 0; h < 2; h++) {
            int id  = tid + h * 256;
            int row = id >> 2, c = id & 3;     // 128 rows x 4 chunks of 8 halves
            cp16h(abase + (uint32_t)(row * (LDA_H * 2) + c * 16), Asrc + (size_t)row * K + c * 8);
            cp16h(bbase + (uint32_t)(row * (LDA_H * 2) + c * 16), Bsrc + (size_t)row * K + c * 8);
        }
        asm volatile("cp.async.commit_group;");
    };

    load_stage(0, 0);
    load_stage(1, 1);

    for (int kt = 0; kt < KT; kt++) {
        asm volatile("cp.async.wait_group 1;");
        __syncthreads();

        if (kt + 2 < KT) load_stage((kt + 2) % TSTAGES, kt + 2);
        else             asm volatile("cp.async.commit_group;");

        const int st = kt % TSTAGES;
        const uint32_t a_u = sbase + (uint32_t)(st * STAGE_B) + a_lm_off;
        const char* bs = smem + st * STAGE_B + TILE_H * 2;

#pragma unroll
        for (int kk = 0; kk < 2; kk++) {       // two k16 halves of the 32-k slab
            uint32_t af[4][4], bf[4][2];
#pragma unroll
            for (int i = 0; i < 4; i++)
                ldsm_x4(af[i], a_u + (uint32_t)(i * 16 * LDA_H * 2 + kk * 32));
#pragma unroll
            for (int j = 0; j < 4; j++) {
                int n = wn + 8 * j + g;
                const char* brow = bs + n * (LDA_H * 2) + kk * 32;
                bf[j][0] = *(const uint32_t*)(brow + 4 * tig);        // k = 2tig, 2tig+1
                bf[j][1] = *(const uint32_t*)(brow + 4 * tig + 16);   // k = 2tig+8, +9
            }
#pragma unroll
            for (int i = 0; i < 4; i++)
#pragma unroll
                for (int j = 0; j < 4; j++)
                    mma_f16(acc[i][j], af[i], bf[j]);
        }
    }

#pragma unroll
    for (int i = 0; i < 4; i++) {
        int r0 = bm * TBM + wm + 16 * i + g;
#pragma unroll
        for (int j = 0; j < 4; j++) {
            int cn = bn * TBN + wn + 8 * j + 2 * tig;
            if (cn < N) {
                *(float2*)(C + (size_t)r0 * N + cn)       = make_float2(acc[i][j][0], acc[i][j][1]);
                *(float2*)(C + (size_t)(r0 + 8) * N + cn) = make_float2(acc[i][j][2], acc[i][j][3]);
            }
        }
    }
}

static inline void launch_gemm(const __half* A, const __half* BTm, float* C,
                               int M, int N, int K, cudaStream_t st)
{
    int num_bm = M / TBM;
    int num_bn = (N + TBN - 1) / TBN;
    gemm_f16_kernel<<<num_bm * num_bn, 256, GEMM_SMEM, st>>>(A, BTm, C, M, N, K);
}

// ---------------------------------------------------------------------------
// fp32 -> fp16 elementwise (float4 in, 4 halves out)
// ---------------------------------------------------------------------------
__global__ void cvt_f16_kernel(const float* __restrict__ src,
                               __half* __restrict__ dst, size_t n4)
{
    size_t i = (size_t)blockIdx.x * blockDim.x + threadIdx.x;
    if (i >= n4) return;
    float4 x = ((const float4*)src)[i];
    __half2* d = (__half2*)dst + 2 * i;
    d[0] = __floats2half2_rn(x.x, x.y);
    d[1] = __floats2half2_rn(x.z, x.w);
}

// Fused pack: [W_qkv | W_b | W_a] -> transposed [QBT_NP, DMODEL] half (zero pad)
__global__ void pack_wqkvbaT_kernel(const float* __restrict__ Wqkv,
                                    const float* __restrict__ Wb,
                                    const float* __restrict__ Wa,
                                    __half* __restrict__ Wt)
{
    __shared__ float t[32][33];
    int nx = blockIdx.x * 32;    // n
    int ky = blockIdx.y * 32;    // k
    int tx = threadIdx.x, ty = threadIdx.y;
#pragma unroll
    for (int i = 0; i < 32; i += 8) {
        int n = nx + tx, k = ky + ty + i;
        float v;
        if      (n < B2_OFF) v = Wqkv[(size_t)k * CONVDIM + n];
        else if (n < A2_OFF) v = Wb[k * 32 + (n - B2_OFF)];
        else if (n < QB_N)   v = Wa[k * 32 + (n - A2_OFF)];
        else                 v = 0.f;
        t[ty + i][tx] = v;
    }
    __syncthreads();
#pragma unroll
    for (int i = 0; i < 32; i += 8) {
        int n = nx + ty + i, k = ky + tx;
        Wt[(size_t)n * DMODEL + k] = __float2half_rn(t[tx][ty + i]);
    }
}

// generic transpose+cvt: src[R][C] fp32 -> dst[C][R] half
__global__ void packT_f16_kernel(const float* __restrict__ src,
                                 __half* __restrict__ dst, int R, int C)
{
    __shared__ float t[32][33];
    int cx = blockIdx.x * 32;
    int ry = blockIdx.y * 32;
    int tx = threadIdx.x, ty = threadIdx.y;
#pragma unroll
    for (int i = 0; i < 32; i += 8)
        t[ty + i][tx] = src[(size_t)(ry + ty + i) * C + cx + tx];
    __syncthreads();
#pragma unroll
    for (int i = 0; i < 32; i += 8)
        dst[(size_t)(cx + ty + i) * R + ry + tx] = __float2half_rn(t[tx][ty + i]);
}

// ---------------------------------------------------------------------------
// Causal depthwise conv (KC=4) + SiLU + split into q/k/v (row stride QB_N)
// ---------------------------------------------------------------------------
__global__ void conv_silu_split_kernel(const float* __restrict__ proj,
                                       const float* __restrict__ conv_w,
                                       float* __restrict__ q,
                                       float* __restrict__ k,
                                       float* __restrict__ v)
{
    size_t idx = (size_t)blockIdx.x * blockDim.x + threadIdx.x;
    if (idx >= (size_t)BT * CONVDIM) return;
    int c = (int)(idx & (CONVDIM - 1));
    size_t bt = idx >> 13;
    int t = (int)(bt & (TLEN - 1));

    float4 w = *(const float4*)(conv_w + (size_t)c * 4);
    const float* base = proj + c;
    float x0 = (t >= 3) ? base[(bt - 3) * QB_N] : 0.f;
    float x1 = (t >= 2) ? base[(bt - 2) * QB_N] : 0.f;
    float x2 = (t >= 1) ? base[(bt - 1) * QB_N] : 0.f;
    float x3 = base[bt * QB_N];

    float acc = x0 * w.x + x1 * w.y + x2 * w.z + x3 * w.w;
    float s = acc / (1.f + expf(-acc));

    if (c < KEYDIM)           q[bt * KEYDIM + c] = s;
    else if (c < 2 * KEYDIM)  k[bt * KEYDIM + (c - KEYDIM)] = s;
    else                      v[bt * VALDIM + (c - 2 * KEYDIM)] = s;
}

// ---------------------------------------------------------------------------
// L2 norm over DK=128 (one warp per row); q gets extra DK^-0.5
// ---------------------------------------------------------------------------
__global__ void l2norm_qk_kernel(float* __restrict__ q, float* __restrict__ k)
{
    int wg   = (blockIdx.x * blockDim.x + threadIdx.x) >> 5;
    int lane = threadIdx.x & 31;
    const int nrows = BT * NKH;
    if (wg >= 2 * nrows) return;

    float* base;
    float extra;
    if (wg < nrows) { base = q + (size_t)wg * DK; extra = 0.08838834764831845f; }
    else            { base = k + (size_t)(wg - nrows) * DK; extra = 1.f; }

    float4 x = ((float4*)base)[lane];
    float ss = x.x*x.x + x.y*x.y + x.z*x.z + x.w*x.w;
#pragma unroll
    for (int off = 16; off > 0; off >>= 1)
        ss += __shfl_xor_sync(0xffffffffu, ss, off);
    float inv = rsqrtf(ss + 1e-6f) * extra;
    x.x *= inv; x.y *= inv; x.z *= inv; x.w *= inv;
    ((float4*)base)[lane] = x;
}

// ---------------------------------------------------------------------------
// beta = sigmoid(b); decay = exp(-exp(A_log)*softplus(a + dt_bias))
// ---------------------------------------------------------------------------
__global__ void beta_decay_kernel(const float* __restrict__ proj,
                                  const float* __restrict__ dt_bias,
                                  const float* __restrict__ A_log,
                                  float* __restrict__ beta,
                                  float* __restrict__ decay)
{
    int idx = blockIdx.x * blockDim.x + threadIdx.x;
    if (idx >= BT * NVH) return;
    int h = idx & (NVH - 1);
    size_t bt = (size_t)(idx >> 5);
    float b = proj[bt * QB_N + B2_OFF + h];
    beta[idx] = 1.f / (1.f + expf(-b));
    float a = proj[bt * QB_N + A2_OFF + h] + dt_bias[h];
    float sp = (a > 20.f) ? a : log1pf(expf(a));
    decay[idx] = expf(-expf(A_log[h]) * sp);
}

// ---------------------------------------------------------------------------
// Gated delta rule scan (128 blocks x 128 threads, 64 state regs/thread)
// ---------------------------------------------------------------------------
__global__ void __launch_bounds__(128) scan_kernel(
    const float* __restrict__ qn, const float* __restrict__ kn,
    const float* __restrict__ v,  const float* __restrict__ decay,
    const float* __restrict__ beta, float* __restrict__ o)
{
    const int blk = blockIdx.x;
    const int b   = blk >> 6;
    const int rem = blk & 63;
    const int h   = rem >> 1;
    const int seg = rem & 1;
    const int h2  = h >> 1;
    const int tid = threadIdx.x;
    const int col  = tid >> 1;
    const int half = tid & 1;
    const int gcol = seg * 64 + col;
    const int koff = half * 64;

    __shared__ float sq[128];
    __shared__ float sk[128];

    float S[64];
#pragma unroll
    for (int i = 0; i < 64; i++) S[i] = 0.f;

    const size_t bt0 = (size_t)b * TLEN;

    float pq = qn[((bt0)*NKH + h2) * DK + tid];
    float pk = kn[((bt0)*NKH + h2) * DK + tid];
    float pv = v [((bt0)*NVH + h ) * DV + gcol];
    float pd = decay[bt0 * NVH + h];
    float pb = beta [bt0 * NVH + h];

    for (int t = 0; t < TLEN; t++) {
        __syncthreads();
        sq[tid] = pq;
        sk[tid] = pk;
        float cv = pv, cd = pd, cb = pb;
        __syncthreads();

        if (t + 1 < TLEN) {
            size_t bt = bt0 + t + 1;
            pq = qn[(bt*NKH + h2) * DK + tid];
            pk = kn[(bt*NKH + h2) * DK + tid];
            pv = v [(bt*NVH + h ) * DV + gcol];
            pd = decay[bt * NVH + h];
            pb = beta [bt * NVH + h];
        }

        float a0 = 0.f, a1 = 0.f, a2 = 0.f, a3 = 0.f;
#pragma unroll
        for (int i = 0; i < 64; i += 4) {
            S[i+0] *= cd; a0 = fmaf(sk[koff+i+0], S[i+0], a0);
            S[i+1] *= cd; a1 = fmaf(sk[koff+i+1], S[i+1], a1);
            S[i+2] *= cd; a2 = fmaf(sk[koff+i+2], S[i+2], a2);
            S[i+3] *= cd; a3 = fmaf(sk[koff+i+3], S[i+3], a3);
        }
        float kS = (a0 + a1) + (a2 + a3);
        kS += __shfl_xor_sync(0xffffffffu, kS, 1);

        float upd = cb * (cv - kS);

        float o0 = 0.f, o1 = 0.f, o2 = 0.f, o3 = 0.f;
#pragma unroll
        for (int i = 0; i < 64; i += 4) {
            S[i+0] = fmaf(sk[koff+i+0], upd, S[i+0]); o0 = fmaf(sq[koff+i+0], S[i+0], o0);
            S[i+1] = fmaf(sk[koff+i+1], upd, S[i+1]); o1 = fmaf(sq[koff+i+1], S[i+1], o1);
            S[i+2] = fmaf(sk[koff+i+2], upd, S[i+2]); o2 = fmaf(sq[koff+i+2], S[i+2], o2);
            S[i+3] = fmaf(sk[koff+i+3], upd, S[i+3]); o3 = fmaf(sq[koff+i+3], S[i+3], o3);
        }
        float oa = (o0 + o1) + (o2 + o3);
        oa += __shfl_xor_sync(0xffffffffu, oa, 1);
        if (!half)
            o[((bt0 + t)*NVH + h) * DV + gcol] = oa;
    }
}

// ---------------------------------------------------------------------------
// Gated RMSNorm; emits half directly for the out-projection GEMM
// ---------------------------------------------------------------------------
__global__ void gate_kernel(const float* __restrict__ o, const float* __restrict__ z,
                            const float* __restrict__ norm_w, __half* __restrict__ oh)
{
    int wg   = (blockIdx.x * blockDim.x + threadIdx.x) >> 5;
    int lane = threadIdx.x & 31;
    if (wg >= BT * NVH) return;

    float4 x = ((const float4*)(o + (size_t)wg * DV))[lane];
    float ss = x.x*x.x + x.y*x.y + x.z*x.z + x.w*x.w;
#pragma unroll
    for (int off = 16; off > 0; off >>= 1)
        ss += __shfl_xor_sync(0xffffffffu, ss, off);
    float r = rsqrtf(ss * (1.f / DV) + 1e-6f);

    float4 zv = ((const float4*)(z + (size_t)wg * DV))[lane];
    float4 nw = ((const float4*)norm_w)[lane];

    float s0 = zv.x / (1.f + expf(-zv.x));
    float s1 = zv.y / (1.f + expf(-zv.y));
    float s2 = zv.z / (1.f + expf(-zv.z));
    float s3 = zv.w / (1.f + expf(-zv.w));

    __half2* dst = (__half2*)(oh + (size_t)wg * DV) + 2 * lane;
    dst[0] = __floats2half2_rn(x.x * r * nw.x * s0, x.y * r * nw.y * s1);
    dst[1] = __floats2half2_rn(x.z * r * nw.z * s2, x.w * r * nw.w * s3);
}

// ---------------------------------------------------------------------------
// Launch: z-projection deferred onto stream1 into the scan window.
// ---------------------------------------------------------------------------
extern "C" void kernel_launch(void* const* d_in, const int* in_sizes, int n_in,
                              void* d_out, int out_size)
{
    const float* hs      = (const float*)d_in[0];
    const float* W_qkv   = (const float*)d_in[1];
    const float* W_z     = (const float*)d_in[2];
    const float* W_b     = (const float*)d_in[3];
    const float* W_a     = (const float*)d_in[4];
    const float* conv_w  = (const float*)d_in[5];
    const float* dt_bias = (const float*)d_in[6];
    const float* A_log   = (const float*)d_in[7];
    const float* norm_w  = (const float*)d_in[8];
    const float* W_out   = (const float*)d_in[9];
    float* out = (float*)d_out;

    float *qkvba, *z, *q, *k, *v, *beta, *decay, *o;
    __half *hs_h, *wqkvbaT, *wzT, *woutT, *oh;
    cudaGetSymbolAddress((void**)&qkvba,   g_qkvba);
    cudaGetSymbolAddress((void**)&z,       g_z);
    cudaGetSymbolAddress((void**)&q,       g_q);
    cudaGetSymbolAddress((void**)&k,       g_k);
    cudaGetSymbolAddress((void**)&v,       g_v);
    cudaGetSymbolAddress((void**)&beta,    g_beta);
    cudaGetSymbolAddress((void**)&decay,   g_decay);
    cudaGetSymbolAddress((void**)&o,       g_o);
    cudaGetSymbolAddress((void**)&hs_h,    g_hs_h);
    cudaGetSymbolAddress((void**)&wqkvbaT, g_wqkvbaT);
    cudaGetSymbolAddress((void**)&wzT,     g_wzT);
    cudaGetSymbolAddress((void**)&woutT,   g_woutT);
    cudaGetSymbolAddress((void**)&oh,      g_oh);

    static cudaStream_t s1 = nullptr;
    static cudaEvent_t ev_hs = nullptr, ev_fork = nullptr, ev_z = nullptr;
    static bool init_done = false;
    if (!init_done) {
        cudaStreamCreateWithFlags(&s1, cudaStreamNonBlocking);
        cudaEventCreateWithFlags(&ev_hs,   cudaEventDisableTiming);
        cudaEventCreateWithFlags(&ev_fork, cudaEventDisableTiming);
        cudaEventCreateWithFlags(&ev_z,    cudaEventDisableTiming);
        cudaFuncSetAttribute(gemm_f16_kernel,
                             cudaFuncAttributeMaxDynamicSharedMemorySize, GEMM_SMEM);
        init_done = true;
    }

    const cudaStream_t s0 = 0;
    dim3 tb32(32, 8);

    // 0) operand conversion: z/out weights on s1 (independent), rest on s0
    {
        dim3 gz(VALDIM / 32, DMODEL / 32);    // W_z [2048,4096] -> [4096,2048]
        packT_f16_kernel<<<gz, tb32, 0, s1>>>(W_z, wzT, DMODEL, VALDIM);
        dim3 go(DMODEL / 32, VALDIM / 32);    // W_out [4096,2048] -> [2048,4096]
        packT_f16_kernel<<<go, tb32, 0, s1>>>(W_out, woutT, VALDIM, DMODEL);
    }
    {
        size_t n4 = (size_t)BT * DMODEL / 4;
        cvt_f16_kernel<<<(unsigned)((n4 + 255) / 256), 256, 0, s0>>>(hs, hs_h, n4);
        cudaEventRecord(ev_hs, s0);

        dim3 gq(QBT_NP / 32, DMODEL / 32);
        pack_wqkvbaT_kernel<<<gq, tb32, 0, s0>>>(W_qkv, W_b, W_a, wqkvbaT);
    }

    // ---- stream0: qkv|b|a projection + scan chain ----
    launch_gemm(hs_h, wqkvbaT, qkvba, BT, QB_N, DMODEL, s0);

    {
        size_t n = (size_t)BT * CONVDIM;
        conv_silu_split_kernel<<<(unsigned)((n + 255) / 256), 256, 0, s0>>>(qkvba, conv_w, q, k, v);
    }
    {
        int rows = 2 * BT * NKH;
        l2norm_qk_kernel<<<(rows + 7) / 8, 256, 0, s0>>>(q, k);
    }
    beta_decay_kernel<<<(BT * NVH + 255) / 256, 256, 0, s0>>>(qkvba, dt_bias, A_log, beta, decay);
    cudaEventRecord(ev_fork, s0);

    scan_kernel<<<BATCH * NVH * 2, 128, 0, s0>>>(q, k, v, decay, beta, o);

    // ---- stream1: z projection co-scheduled with the scan window ----
    cudaStreamWaitEvent(s1, ev_hs, 0);
    cudaStreamWaitEvent(s1, ev_fork, 0);
    launch_gemm(hs_h, wzT, z, BT, VALDIM, DMODEL, s1);
    cudaEventRecord(ev_z, s1);

    // join: gate needs z and scan output
    cudaStreamWaitEvent(s0, ev_z, 0);
    {
        int rows = BT * NVH;
        gate_kernel<<<(rows + 7) / 8, 256, 0, s0>>>(o, z, norm_w, oh);
    }

    // output projection
    launch_gemm(oh, woutT, out, BT, DMODEL, VALDIM, s0);
}

// round 12
// speedup vs baseline: 2.2092x; 1.2053x over previous
#include <cuda_runtime.h>
#include <cuda_fp16.h>
#include <math.h>
#include <stdint.h>

// ---------------------------------------------------------------------------
// Problem constants (Qwen3.5 GatedDeltaNet): B=2, T=4096, D=2048
// ---------------------------------------------------------------------------
#define BATCH   2
#define TLEN    4096
#define BT      8192
#define DMODEL  2048
#define NVH     32
#define NKH     16
#define DK      128
#define DV      128
#define KEYDIM  (NKH*DK)                 // 2048
#define VALDIM  (NVH*DV)                 // 4096
#define CONVDIM (2*KEYDIM + VALDIM)      // 8192
#define QB_N    (CONVDIM + 64)           // 8256 : [qkv | b | a]
#define QBT_NP  8320                     // padded for B tiles
#define B2_OFF  CONVDIM
#define A2_OFF  (CONVDIM + 32)
#define NCHUNK  4
#define TC      (TLEN/NCHUNK)            // 1024

// ---------------------------------------------------------------------------
// Scratch (static device globals)
// ---------------------------------------------------------------------------
__device__ float  g_qkvba[(size_t)BT * QB_N];
__device__ float  g_z[(size_t)BT * VALDIM];
__device__ float  g_q[(size_t)BT * KEYDIM];
__device__ float  g_k[(size_t)BT * KEYDIM];
__device__ float  g_v[(size_t)BT * VALDIM];
__device__ float  g_beta[BT * NVH];
__device__ float  g_decay[BT * NVH];
__device__ float  g_o[(size_t)BT * VALDIM];
__device__ float  g_S[(size_t)128 * 64 * 128];          // scan state checkpoints
// half-precision GEMM operands
__device__ __half g_hs_h[(size_t)BT * DMODEL];
__device__ __half g_wqkvbaT[(size_t)QBT_NP * DMODEL];   // [N,K]
__device__ __half g_wzT[(size_t)VALDIM * DMODEL];       // [N,K]
__device__ __half g_woutT[(size_t)DMODEL * VALDIM];     // [N,K]
__device__ __half g_oh[(size_t)BT * VALDIM];            // gated o, half

// ---------------------------------------------------------------------------
// FP16 tensor-core GEMM (mma.sync m16n8k16, fp32 accum)
// ---------------------------------------------------------------------------
#define TSTAGES 3
#define TBM 128
#define TBN 128
#define TBK 32
#define LDA_H 40
#define TILE_H (128*LDA_H)
#define STAGE_B (2*TILE_H*2)
#define GEMM_SMEM (TSTAGES*STAGE_B)
#define GROUP_M 8

__device__ __forceinline__ void cp16h(uint32_t dst, const __half* src) {
    asm volatile("cp.async.cg.shared.global [%0], [%1], 16;" :: "r"(dst), "l"(src));
}

__device__ __forceinline__ void ldsm_x4(uint32_t* r, uint32_t addr) {
    asm volatile("ldmatrix.sync.aligned.m8n8.x4.shared.b16 {%0,%1,%2,%3}, [%4];"
        : "=r"(r[0]), "=r"(r[1]), "=r"(r[2]), "=r"(r[3]) : "r"(addr));
}

__device__ __forceinline__ void mma_f16(float* c, const uint32_t* a, const uint32_t* b) {
    asm volatile(
        "mma.sync.aligned.m16n8k16.row.col.f32.f16.f16.f32 "
        "{%0,%1,%2,%3}, {%4,%5,%6,%7}, {%8,%9}, {%0,%1,%2,%3};"
        : "+f"(c[0]), "+f"(c[1]), "+f"(c[2]), "+f"(c[3])
        : "r"(a[0]), "r"(a[1]), "r"(a[2]), "r"(a[3]), "r"(b[0]), "r"(b[1]));
}

__global__ __launch_bounds__(256, 2) void gemm_f16_kernel(
    const __half* __restrict__ A, const __half* __restrict__ BTm,
    float* __restrict__ C, int M, int N, int K)
{
    extern __shared__ char smem[];
    const uint32_t sbase = (uint32_t)__cvta_generic_to_shared(smem);

    const int num_bm = M / TBM;
    const int num_bn = (N + TBN - 1) / TBN;
    const int pid    = blockIdx.x;
    const int ppg    = GROUP_M * num_bn;
    const int gid    = pid / ppg;
    const int fbm    = gid * GROUP_M;
    const int gsz    = min(GROUP_M, num_bm - fbm);
    const int bm     = fbm + (pid % ppg) % gsz;
    const int bn     = (pid % ppg) / gsz;

    const int tid  = threadIdx.x;
    const int warp = tid >> 5;
    const int lane = tid & 31;
    const int g    = lane >> 2;
    const int tig  = lane & 3;
    const int wm   = (warp >> 2) * 64;
    const int wn   = (warp & 3) * 32;

    float acc[4][4][4];
#pragma unroll
    for (int i = 0; i < 4; i++)
#pragma unroll
        for (int j = 0; j < 4; j++)
#pragma unroll
            for (int r = 0; r < 4; r++) acc[i][j][r] = 0.f;

    const int KT = K / TBK;

    const uint32_t a_lm_off =
        (uint32_t)(((wm + (lane & 7) + 8 * ((lane >> 3) & 1)) * LDA_H + (lane >> 4) * 8) * 2);

    auto load_stage = [&](int s, int kt) {
        uint32_t abase = sbase + (uint32_t)(s * STAGE_B);
        uint32_t bbase = abase + (uint32_t)(TILE_H * 2);
        const __half* Asrc = A   + (size_t)(bm * TBM) * K + kt * TBK;
        const __half* Bsrc = BTm + (size_t)(bn * TBN) * K + kt * TBK;
#pragma unroll
        for (int h = 0; h < 2; h++) {
            int id  = tid + h * 256;
            int row = id >> 2, c = id & 3;
            cp16h(abase + (uint32_t)(row * (LDA_H * 2) + c * 16), Asrc + (size_t)row * K + c * 8);
            cp16h(bbase + (uint32_t)(row * (LDA_H * 2) + c * 16), Bsrc + (size_t)row * K + c * 8);
        }
        asm volatile("cp.async.commit_group;");
    };

    load_stage(0, 0);
    load_stage(1, 1);

    for (int kt = 0; kt < KT; kt++) {
        asm volatile("cp.async.wait_group 1;");
        __syncthreads();

        if (kt + 2 < KT) load_stage((kt + 2) % TSTAGES, kt + 2);
        else             asm volatile("cp.async.commit_group;");

        const int st = kt % TSTAGES;
        const uint32_t a_u = sbase + (uint32_t)(st * STAGE_B) + a_lm_off;
        const char* bs = smem + st * STAGE_B + TILE_H * 2;

#pragma unroll
        for (int kk = 0; kk < 2; kk++) {
            uint32_t af[4][4], bf[4][2];
#pragma unroll
            for (int i = 0; i < 4; i++)
                ldsm_x4(af[i], a_u + (uint32_t)(i * 16 * LDA_H * 2 + kk * 32));
#pragma unroll
            for (int j = 0; j < 4; j++) {
                int n = wn + 8 * j + g;
                const char* brow = bs + n * (LDA_H * 2) + kk * 32;
                bf[j][0] = *(const uint32_t*)(brow + 4 * tig);
                bf[j][1] = *(const uint32_t*)(brow + 4 * tig + 16);
            }
#pragma unroll
            for (int i = 0; i < 4; i++)
#pragma unroll
                for (int j = 0; j < 4; j++)
                    mma_f16(acc[i][j], af[i], bf[j]);
        }
    }

#pragma unroll
    for (int i = 0; i < 4; i++) {
        int r0 = bm * TBM + wm + 16 * i + g;
#pragma unroll
        for (int j = 0; j < 4; j++) {
            int cn = bn * TBN + wn + 8 * j + 2 * tig;
            if (cn < N) {
                *(float2*)(C + (size_t)r0 * N + cn)       = make_float2(acc[i][j][0], acc[i][j][1]);
                *(float2*)(C + (size_t)(r0 + 8) * N + cn) = make_float2(acc[i][j][2], acc[i][j][3]);
            }
        }
    }
}

static inline void launch_gemm(const __half* A, const __half* BTm, float* C,
                               int M, int N, int K, cudaStream_t st)
{
    int num_bm = M / TBM;
    int num_bn = (N + TBN - 1) / TBN;
    gemm_f16_kernel<<<num_bm * num_bn, 256, GEMM_SMEM, st>>>(A, BTm, C, M, N, K);
}

// ---------------------------------------------------------------------------
// fp32 -> fp16 elementwise
// ---------------------------------------------------------------------------
__global__ void cvt_f16_kernel(const float* __restrict__ src,
                               __half* __restrict__ dst, size_t n4)
{
    size_t i = (size_t)blockIdx.x * blockDim.x + threadIdx.x;
    if (i >= n4) return;
    float4 x = ((const float4*)src)[i];
    __half2* d = (__half2*)dst + 2 * i;
    d[0] = __floats2half2_rn(x.x, x.y);
    d[1] = __floats2half2_rn(x.z, x.w);
}

// Fused pack: [W_qkv | W_b | W_a] -> transposed [QBT_NP, DMODEL] half (zero pad)
__global__ void pack_wqkvbaT_kernel(const float* __restrict__ Wqkv,
                                    const float* __restrict__ Wb,
                                    const float* __restrict__ Wa,
                                    __half* __restrict__ Wt)
{
    __shared__ float t[32][33];
    int nx = blockIdx.x * 32;
    int ky = blockIdx.y * 32;
    int tx = threadIdx.x, ty = threadIdx.y;
#pragma unroll
    for (int i = 0; i < 32; i += 8) {
        int n = nx + tx, k = ky + ty + i;
        float v;
        if      (n < B2_OFF) v = Wqkv[(size_t)k * CONVDIM + n];
        else if (n < A2_OFF) v = Wb[k * 32 + (n - B2_OFF)];
        else if (n < QB_N)   v = Wa[k * 32 + (n - A2_OFF)];
        else                 v = 0.f;
        t[ty + i][tx] = v;
    }
    __syncthreads();
#pragma unroll
    for (int i = 0; i < 32; i += 8) {
        int n = nx + ty + i, k = ky + tx;
        Wt[(size_t)n * DMODEL + k] = __float2half_rn(t[tx][ty + i]);
    }
}

// generic transpose+cvt: src[R][C] fp32 -> dst[C][R] half
__global__ void packT_f16_kernel(const float* __restrict__ src,
                                 __half* __restrict__ dst, int R, int C)
{
    __shared__ float t[32][33];
    int cx = blockIdx.x * 32;
    int ry = blockIdx.y * 32;
    int tx = threadIdx.x, ty = threadIdx.y;
#pragma unroll
    for (int i = 0; i < 32; i += 8)
        t[ty + i][tx] = src[(size_t)(ry + ty + i) * C + cx + tx];
    __syncthreads();
#pragma unroll
    for (int i = 0; i < 32; i += 8)
        dst[(size_t)(cx + ty + i) * R + ry + tx] = __float2half_rn(t[tx][ty + i]);
}

// ---------------------------------------------------------------------------
// Causal depthwise conv (KC=4) + SiLU + split into q/k/v (row stride QB_N)
// ---------------------------------------------------------------------------
__global__ void conv_silu_split_kernel(const float* __restrict__ proj,
                                       const float* __restrict__ conv_w,
                                       float* __restrict__ q,
                                       float* __restrict__ k,
                                       float* __restrict__ v)
{
    size_t idx = (size_t)blockIdx.x * blockDim.x + threadIdx.x;
    if (idx >= (size_t)BT * CONVDIM) return;
    int c = (int)(idx & (CONVDIM - 1));
    size_t bt = idx >> 13;
    int t = (int)(bt & (TLEN - 1));

    float4 w = *(const float4*)(conv_w + (size_t)c * 4);
    const float* base = proj + c;
    float x0 = (t >= 3) ? base[(bt - 3) * QB_N] : 0.f;
    float x1 = (t >= 2) ? base[(bt - 2) * QB_N] : 0.f;
    float x2 = (t >= 1) ? base[(bt - 1) * QB_N] : 0.f;
    float x3 = base[bt * QB_N];

    float acc = x0 * w.x + x1 * w.y + x2 * w.z + x3 * w.w;
    float s = acc / (1.f + expf(-acc));

    if (c < KEYDIM)           q[bt * KEYDIM + c] = s;
    else if (c < 2 * KEYDIM)  k[bt * KEYDIM + (c - KEYDIM)] = s;
    else                      v[bt * VALDIM + (c - 2 * KEYDIM)] = s;
}

// ---------------------------------------------------------------------------
// L2 norm over DK=128 (one warp per row); q gets extra DK^-0.5
// ---------------------------------------------------------------------------
__global__ void l2norm_qk_kernel(float* __restrict__ q, float* __restrict__ k)
{
    int wg   = (blockIdx.x * blockDim.x + threadIdx.x) >> 5;
    int lane = threadIdx.x & 31;
    const int nrows = BT * NKH;
    if (wg >= 2 * nrows) return;

    float* base;
    float extra;
    if (wg < nrows) { base = q + (size_t)wg * DK; extra = 0.08838834764831845f; }
    else            { base = k + (size_t)(wg - nrows) * DK; extra = 1.f; }

    float4 x = ((float4*)base)[lane];
    float ss = x.x*x.x + x.y*x.y + x.z*x.z + x.w*x.w;
#pragma unroll
    for (int off = 16; off > 0; off >>= 1)
        ss += __shfl_xor_sync(0xffffffffu, ss, off);
    float inv = rsqrtf(ss + 1e-6f) * extra;
    x.x *= inv; x.y *= inv; x.z *= inv; x.w *= inv;
    ((float4*)base)[lane] = x;
}

// ---------------------------------------------------------------------------
// beta = sigmoid(b); decay = exp(-exp(A_log)*softplus(a + dt_bias))
// ---------------------------------------------------------------------------
__global__ void beta_decay_kernel(const float* __restrict__ proj,
                                  const float* __restrict__ dt_bias,
                                  const float* __restrict__ A_log,
                                  float* __restrict__ beta,
                                  float* __restrict__ decay)
{
    int idx = blockIdx.x * blockDim.x + threadIdx.x;
    if (idx >= BT * NVH) return;
    int h = idx & (NVH - 1);
    size_t bt = (size_t)(idx >> 5);
    float b = proj[bt * QB_N + B2_OFF + h];
    beta[idx] = 1.f / (1.f + expf(-b));
    float a = proj[bt * QB_N + A2_OFF + h] + dt_bias[h];
    float sp = (a > 20.f) ? a : log1pf(expf(a));
    decay[idx] = expf(-expf(A_log[h]) * sp);
}

// ---------------------------------------------------------------------------
// Gated delta rule scan — chunked over [t0, t1) with state checkpointed in
// global memory ([i][tid]-coalesced). Arithmetic identical to monolithic scan.
// ---------------------------------------------------------------------------
__global__ void __launch_bounds__(128) scan_kernel(
    const float* __restrict__ qn, const float* __restrict__ kn,
    const float* __restrict__ v,  const float* __restrict__ decay,
    const float* __restrict__ beta, float* __restrict__ o,
    float* __restrict__ Sst, int t0, int t1)
{
    const int blk = blockIdx.x;
    const int b   = blk >> 6;
    const int rem = blk & 63;
    const int h   = rem >> 1;
    const int seg = rem & 1;
    const int h2  = h >> 1;
    const int tid = threadIdx.x;
    const int col  = tid >> 1;
    const int half = tid & 1;
    const int gcol = seg * 64 + col;
    const int koff = half * 64;

    __shared__ float sq[128];
    __shared__ float sk[128];

    float* Sg = Sst + (size_t)blk * (64 * 128);

    float S[64];
    if (t0 == 0) {
#pragma unroll
        for (int i = 0; i < 64; i++) S[i] = 0.f;
    } else {
#pragma unroll
        for (int i = 0; i < 64; i++) S[i] = Sg[i * 128 + tid];
    }

    const size_t bt0 = (size_t)b * TLEN;

    float pq = qn[((bt0 + t0)*NKH + h2) * DK + tid];
    float pk = kn[((bt0 + t0)*NKH + h2) * DK + tid];
    float pv = v [((bt0 + t0)*NVH + h ) * DV + gcol];
    float pd = decay[(bt0 + t0) * NVH + h];
    float pb = beta [(bt0 + t0) * NVH + h];

    for (int t = t0; t < t1; t++) {
        __syncthreads();
        sq[tid] = pq;
        sk[tid] = pk;
        float cv = pv, cd = pd, cb = pb;
        __syncthreads();

        if (t + 1 < t1) {
            size_t bt = bt0 + t + 1;
            pq = qn[(bt*NKH + h2) * DK + tid];
            pk = kn[(bt*NKH + h2) * DK + tid];
            pv = v [(bt*NVH + h ) * DV + gcol];
            pd = decay[bt * NVH + h];
            pb = beta [bt * NVH + h];
        }

        float a0 = 0.f, a1 = 0.f, a2 = 0.f, a3 = 0.f;
#pragma unroll
        for (int i = 0; i < 64; i += 4) {
            S[i+0] *= cd; a0 = fmaf(sk[koff+i+0], S[i+0], a0);
            S[i+1] *= cd; a1 = fmaf(sk[koff+i+1], S[i+1], a1);
            S[i+2] *= cd; a2 = fmaf(sk[koff+i+2], S[i+2], a2);
            S[i+3] *= cd; a3 = fmaf(sk[koff+i+3], S[i+3], a3);
        }
        float kS = (a0 + a1) + (a2 + a3);
        kS += __shfl_xor_sync(0xffffffffu, kS, 1);

        float upd = cb * (cv - kS);

        float o0 = 0.f, o1 = 0.f, o2 = 0.f, o3 = 0.f;
#pragma unroll
        for (int i = 0; i < 64; i += 4) {
            S[i+0] = fmaf(sk[koff+i+0], upd, S[i+0]); o0 = fmaf(sq[koff+i+0], S[i+0], o0);
            S[i+1] = fmaf(sk[koff+i+1], upd, S[i+1]); o1 = fmaf(sq[koff+i+1], S[i+1], o1);
            S[i+2] = fmaf(sk[koff+i+2], upd, S[i+2]); o2 = fmaf(sq[koff+i+2], S[i+2], o2);
            S[i+3] = fmaf(sk[koff+i+3], upd, S[i+3]); o3 = fmaf(sq[koff+i+3], S[i+3], o3);
        }
        float oa = (o0 + o1) + (o2 + o3);
        oa += __shfl_xor_sync(0xffffffffu, oa, 1);
        if (!half)
            o[((bt0 + t)*NVH + h) * DV + gcol] = oa;
    }

    if (t1 < TLEN) {
#pragma unroll
        for (int i = 0; i < 64; i++) Sg[i * 128 + tid] = S[i];
    }
}

// ---------------------------------------------------------------------------
// Gated RMSNorm over nrows rows (pointers pre-offset); emits half
// ---------------------------------------------------------------------------
__global__ void gate_kernel(const float* __restrict__ o, const float* __restrict__ z,
                            const float* __restrict__ norm_w, __half* __restrict__ oh,
                            int nrows)
{
    int wg   = (blockIdx.x * blockDim.x + threadIdx.x) >> 5;
    int lane = threadIdx.x & 31;
    if (wg >= nrows) return;

    float4 x = ((const float4*)(o + (size_t)wg * DV))[lane];
    float ss = x.x*x.x + x.y*x.y + x.z*x.z + x.w*x.w;
#pragma unroll
    for (int off = 16; off > 0; off >>= 1)
        ss += __shfl_xor_sync(0xffffffffu, ss, off);
    float r = rsqrtf(ss * (1.f / DV) + 1e-6f);

    float4 zv = ((const float4*)(z + (size_t)wg * DV))[lane];
    float4 nw = ((const float4*)norm_w)[lane];

    float s0 = zv.x / (1.f + expf(-zv.x));
    float s1 = zv.y / (1.f + expf(-zv.y));
    float s2 = zv.z / (1.f + expf(-zv.z));
    float s3 = zv.w / (1.f + expf(-zv.w));

    __half2* dst = (__half2*)(oh + (size_t)wg * DV) + 2 * lane;
    dst[0] = __floats2half2_rn(x.x * r * nw.x * s0, x.y * r * nw.y * s1);
    dst[1] = __floats2half2_rn(x.z * r * nw.z * s2, x.w * r * nw.w * s3);
}

// ---------------------------------------------------------------------------
// Launch: chunked scan on s0; z-GEMM + per-chunk gate/out-GEMM on s1.
// ---------------------------------------------------------------------------
extern "C" void kernel_launch(void* const* d_in, const int* in_sizes, int n_in,
                              void* d_out, int out_size)
{
    const float* hs      = (const float*)d_in[0];
    const float* W_qkv   = (const float*)d_in[1];
    const float* W_z     = (const float*)d_in[2];
    const float* W_b     = (const float*)d_in[3];
    const float* W_a     = (const float*)d_in[4];
    const float* conv_w  = (const float*)d_in[5];
    const float* dt_bias = (const float*)d_in[6];
    const float* A_log   = (const float*)d_in[7];
    const float* norm_w  = (const float*)d_in[8];
    const float* W_out   = (const float*)d_in[9];
    float* out = (float*)d_out;

    float *qkvba, *z, *q, *k, *v, *beta, *decay, *o, *Sst;
    __half *hs_h, *wqkvbaT, *wzT, *woutT, *oh;
    cudaGetSymbolAddress((void**)&qkvba,   g_qkvba);
    cudaGetSymbolAddress((void**)&z,       g_z);
    cudaGetSymbolAddress((void**)&q,       g_q);
    cudaGetSymbolAddress((void**)&k,       g_k);
    cudaGetSymbolAddress((void**)&v,       g_v);
    cudaGetSymbolAddress((void**)&beta,    g_beta);
    cudaGetSymbolAddress((void**)&decay,   g_decay);
    cudaGetSymbolAddress((void**)&o,       g_o);
    cudaGetSymbolAddress((void**)&Sst,     g_S);
    cudaGetSymbolAddress((void**)&hs_h,    g_hs_h);
    cudaGetSymbolAddress((void**)&wqkvbaT, g_wqkvbaT);
    cudaGetSymbolAddress((void**)&wzT,     g_wzT);
    cudaGetSymbolAddress((void**)&woutT,   g_woutT);
    cudaGetSymbolAddress((void**)&oh,      g_oh);

    static cudaStream_t s1 = nullptr;
    static cudaEvent_t ev_hs = nullptr, ev_fork = nullptr;
    static cudaEvent_t ev_scan[NCHUNK] = {};
    static cudaEvent_t ev_done = nullptr;
    static bool init_done = false;
    if (!init_done) {
        cudaStreamCreateWithFlags(&s1, cudaStreamNonBlocking);
        cudaEventCreateWithFlags(&ev_hs,   cudaEventDisableTiming);
        cudaEventCreateWithFlags(&ev_fork, cudaEventDisableTiming);
        for (int c = 0; c < NCHUNK; c++)
            cudaEventCreateWithFlags(&ev_scan[c], cudaEventDisableTiming);
        cudaEventCreateWithFlags(&ev_done, cudaEventDisableTiming);
        cudaFuncSetAttribute(gemm_f16_kernel,
                             cudaFuncAttributeMaxDynamicSharedMemorySize, GEMM_SMEM);
        init_done = true;
    }

    const cudaStream_t s0 = 0;
    dim3 tb32(32, 8);

    // 0) operand conversion: z/out weight transposes on s1 (independent)
    {
        dim3 gz(VALDIM / 32, DMODEL / 32);
        packT_f16_kernel<<<gz, tb32, 0, s1>>>(W_z, wzT, DMODEL, VALDIM);
        dim3 go(DMODEL / 32, VALDIM / 32);
        packT_f16_kernel<<<go, tb32, 0, s1>>>(W_out, woutT, VALDIM, DMODEL);
    }
    {
        size_t n4 = (size_t)BT * DMODEL / 4;
        cvt_f16_kernel<<<(unsigned)((n4 + 255) / 256), 256, 0, s0>>>(hs, hs_h, n4);
        cudaEventRecord(ev_hs, s0);

        dim3 gq(QBT_NP / 32, DMODEL / 32);
        pack_wqkvbaT_kernel<<<gq, tb32, 0, s0>>>(W_qkv, W_b, W_a, wqkvbaT);
    }

    // ---- stream0: qkv|b|a projection ----
    launch_gemm(hs_h, wqkvbaT, qkvba, BT, QB_N, DMODEL, s0);
    cudaEventRecord(ev_fork, s0);   // z-GEMM may start once the big GEMM drains

    // ---- stream1: z projection overlapped with conv/l2norm/beta/scan ----
    cudaStreamWaitEvent(s1, ev_hs, 0);
    cudaStreamWaitEvent(s1, ev_fork, 0);
    launch_gemm(hs_h, wzT, z, BT, VALDIM, DMODEL, s1);

    // ---- stream0: elementwise chain ----
    {
        size_t n = (size_t)BT * CONVDIM;
        conv_silu_split_kernel<<<(unsigned)((n + 255) / 256), 256, 0, s0>>>(qkvba, conv_w, q, k, v);
    }
    {
        int rows = 2 * BT * NKH;
        l2norm_qk_kernel<<<(rows + 7) / 8, 256, 0, s0>>>(q, k);
    }
    beta_decay_kernel<<<(BT * NVH + 255) / 256, 256, 0, s0>>>(qkvba, dt_bias, A_log, beta, decay);

    // ---- chunked scan (s0) with overlapped gate + out-GEMM (s1) ----
    for (int c = 0; c < NCHUNK; c++) {
        const int t0 = c * TC, t1 = t0 + TC;
        scan_kernel<<<BATCH * NVH * 2, 128, 0, s0>>>(q, k, v, decay, beta, o, Sst, t0, t1);
        cudaEventRecord(ev_scan[c], s0);

        cudaStreamWaitEvent(s1, ev_scan[c], 0);   // s1 already ordered after z-GEMM
        for (int b = 0; b < BATCH; b++) {
            const size_t bt0 = (size_t)b * TLEN + t0;
            const int rows = TC * NVH;            // 32768 gate rows
            gate_kernel<<<(rows + 7) / 8, 256, 0, s1>>>(
                o + bt0 * VALDIM, z + bt0 * VALDIM, norm_w, oh + bt0 * VALDIM, rows);
            launch_gemm(oh + bt0 * VALDIM, woutT, out + bt0 * DMODEL,
                        TC, DMODEL, VALDIM, s1);
        }
    }

    // join all s1 work back to s0 for graph-capture completeness
    cudaEventRecord(ev_done, s1);
    cudaStreamWaitEvent(s0, ev_done, 0);
}

// round 14
// speedup vs baseline: 2.3984x; 1.0856x over previous
#include <cuda_runtime.h>
#include <cuda_fp16.h>
#include <math.h>
#include <stdint.h>

// ---------------------------------------------------------------------------
// Problem constants (Qwen3.5 GatedDeltaNet): B=2, T=4096, D=2048
// ---------------------------------------------------------------------------
#define BATCH   2
#define TLEN    4096
#define BT      8192
#define DMODEL  2048
#define NVH     32
#define NKH     16
#define DK      128
#define DV      128
#define KEYDIM  (NKH*DK)                 // 2048
#define VALDIM  (NVH*DV)                 // 4096
#define CONVDIM (2*KEYDIM + VALDIM)      // 8192
#define QB_N    (CONVDIM + 64)           // 8256 : [qkv | b | a]
#define QBT_NP  8320                     // padded for B tiles
#define B2_OFF  CONVDIM
#define A2_OFF  (CONVDIM + 32)
#define NCHUNK  4
#define TC      (TLEN/NCHUNK)            // 1024 t-steps per chunk

// ---------------------------------------------------------------------------
// Scratch (static device globals)
// ---------------------------------------------------------------------------
__device__ float  g_qkvba[(size_t)BT * QB_N];
__device__ float  g_z[(size_t)BT * VALDIM];
__device__ float  g_q[(size_t)BT * KEYDIM];
__device__ float  g_k[(size_t)BT * KEYDIM];
__device__ float  g_v[(size_t)BT * VALDIM];
__device__ float  g_beta[BT * NVH];
__device__ float  g_decay[BT * NVH];
__device__ float  g_o[(size_t)BT * VALDIM];
__device__ float  g_S[(size_t)128 * 64 * 128];          // scan state checkpoints
// half-precision GEMM operands
__device__ __half g_hs_h[(size_t)BT * DMODEL];
__device__ __half g_wqkvbaT[(size_t)QBT_NP * DMODEL];   // [N,K]
__device__ __half g_wzT[(size_t)VALDIM * DMODEL];       // [N,K]
__device__ __half g_woutT[(size_t)DMODEL * VALDIM];     // [N,K]
__device__ __half g_oh[(size_t)BT * VALDIM];            // gated o, half

// ---------------------------------------------------------------------------
// FP16 tensor-core GEMM (mma.sync m16n8k16, fp32 accum)
// ---------------------------------------------------------------------------
#define TSTAGES 3
#define TBM 128
#define TBN 128
#define TBK 32
#define LDA_H 40
#define TILE_H (128*LDA_H)
#define STAGE_B (2*TILE_H*2)
#define GEMM_SMEM (TSTAGES*STAGE_B)
#define GROUP_M 8

__device__ __forceinline__ void cp16h(uint32_t dst, const __half* src) {
    asm volatile("cp.async.cg.shared.global [%0], [%1], 16;" :: "r"(dst), "l"(src));
}

__device__ __forceinline__ void ldsm_x4(uint32_t* r, uint32_t addr) {
    asm volatile("ldmatrix.sync.aligned.m8n8.x4.shared.b16 {%0,%1,%2,%3}, [%4];"
        : "=r"(r[0]), "=r"(r[1]), "=r"(r[2]), "=r"(r[3]) : "r"(addr));
}

__device__ __forceinline__ void mma_f16(float* c, const uint32_t* a, const uint32_t* b) {
    asm volatile(
        "mma.sync.aligned.m16n8k16.row.col.f32.f16.f16.f32 "
        "{%0,%1,%2,%3}, {%4,%5,%6,%7}, {%8,%9}, {%0,%1,%2,%3};"
        : "+f"(c[0]), "+f"(c[1]), "+f"(c[2]), "+f"(c[3])
        : "r"(a[0]), "r"(a[1]), "r"(a[2]), "r"(a[3]), "r"(b[0]), "r"(b[1]));
}

__global__ __launch_bounds__(256, 2) void gemm_f16_kernel(
    const __half* __restrict__ A, const __half* __restrict__ BTm,
    float* __restrict__ C, int M, int N, int K)
{
    extern __shared__ char smem[];
    const uint32_t sbase = (uint32_t)__cvta_generic_to_shared(smem);

    const int num_bm = M / TBM;
    const int num_bn = (N + TBN - 1) / TBN;
    const int pid    = blockIdx.x;
    const int ppg    = GROUP_M * num_bn;
    const int gid    = pid / ppg;
    const int fbm    = gid * GROUP_M;
    const int gsz    = min(GROUP_M, num_bm - fbm);
    const int bm     = fbm + (pid % ppg) % gsz;
    const int bn     = (pid % ppg) / gsz;

    const int tid  = threadIdx.x;
    const int warp = tid >> 5;
    const int lane = tid & 31;
    const int g    = lane >> 2;
    const int tig  = lane & 3;
    const int wm   = (warp >> 2) * 64;
    const int wn   = (warp & 3) * 32;

    float acc[4][4][4];
#pragma unroll
    for (int i = 0; i < 4; i++)
#pragma unroll
        for (int j = 0; j < 4; j++)
#pragma unroll
            for (int r = 0; r < 4; r++) acc[i][j][r] = 0.f;

    const int KT = K / TBK;

    const uint32_t a_lm_off =
        (uint32_t)(((wm + (lane & 7) + 8 * ((lane >> 3) & 1)) * LDA_H + (lane >> 4) * 8) * 2);

    auto load_stage = [&](int s, int kt) {
        uint32_t abase = sbase + (uint32_t)(s * STAGE_B);
        uint32_t bbase = abase + (uint32_t)(TILE_H * 2);
        const __half* Asrc = A   + (size_t)(bm * TBM) * K + kt * TBK;
        const __half* Bsrc = BTm + (size_t)(bn * TBN) * K + kt * TBK;
#pragma unroll
        for (int h = 0; h < 2; h++) {
            int id  = tid + h * 256;
            int row = id >> 2, c = id & 3;
            cp16h(abase + (uint32_t)(row * (LDA_H * 2) + c * 16), Asrc + (size_t)row * K + c * 8);
            cp16h(bbase + (uint32_t)(row * (LDA_H * 2) + c * 16), Bsrc + (size_t)row * K + c * 8);
        }
        asm volatile("cp.async.commit_group;");
    };

    load_stage(0, 0);
    load_stage(1, 1);

    for (int kt = 0; kt < KT; kt++) {
        asm volatile("cp.async.wait_group 1;");
        __syncthreads();

        if (kt + 2 < KT) load_stage((kt + 2) % TSTAGES, kt + 2);
        else             asm volatile("cp.async.commit_group;");

        const int st = kt % TSTAGES;
        const uint32_t a_u = sbase + (uint32_t)(st * STAGE_B) + a_lm_off;
        const char* bs = smem + st * STAGE_B + TILE_H * 2;

#pragma unroll
        for (int kk = 0; kk < 2; kk++) {
            uint32_t af[4][4], bf[4][2];
#pragma unroll
            for (int i = 0; i < 4; i++)
                ldsm_x4(af[i], a_u + (uint32_t)(i * 16 * LDA_H * 2 + kk * 32));
#pragma unroll
            for (int j = 0; j < 4; j++) {
                int n = wn + 8 * j + g;
                const char* brow = bs + n * (LDA_H * 2) + kk * 32;
                bf[j][0] = *(const uint32_t*)(brow + 4 * tig);
                bf[j][1] = *(const uint32_t*)(brow + 4 * tig + 16);
            }
#pragma unroll
            for (int i = 0; i < 4; i++)
#pragma unroll
                for (int j = 0; j < 4; j++)
                    mma_f16(acc[i][j], af[i], bf[j]);
        }
    }

#pragma unroll
    for (int i = 0; i < 4; i++) {
        int r0 = bm * TBM + wm + 16 * i + g;
#pragma unroll
        for (int j = 0; j < 4; j++) {
            int cn = bn * TBN + wn + 8 * j + 2 * tig;
            if (cn < N) {
                *(float2*)(C + (size_t)r0 * N + cn)       = make_float2(acc[i][j][0], acc[i][j][1]);
                *(float2*)(C + (size_t)(r0 + 8) * N + cn) = make_float2(acc[i][j][2], acc[i][j][3]);
            }
        }
    }
}

static inline void launch_gemm(const __half* A, const __half* BTm, float* C,
                               int M, int N, int K, cudaStream_t st)
{
    int num_bm = M / TBM;
    int num_bn = (N + TBN - 1) / TBN;
    gemm_f16_kernel<<<num_bm * num_bn, 256, GEMM_SMEM, st>>>(A, BTm, C, M, N, K);
}

// ---------------------------------------------------------------------------
// fp32 -> fp16 elementwise
// ---------------------------------------------------------------------------
__global__ void cvt_f16_kernel(const float* __restrict__ src,
                               __half* __restrict__ dst, size_t n4)
{
    size_t i = (size_t)blockIdx.x * blockDim.x + threadIdx.x;
    if (i >= n4) return;
    float4 x = ((const float4*)src)[i];
    __half2* d = (__half2*)dst + 2 * i;
    d[0] = __floats2half2_rn(x.x, x.y);
    d[1] = __floats2half2_rn(x.z, x.w);
}

// Fused pack: [W_qkv | W_b | W_a] -> transposed [QBT_NP, DMODEL] half (zero pad)
__global__ void pack_wqkvbaT_kernel(const float* __restrict__ Wqkv,
                                    const float* __restrict__ Wb,
                                    const float* __restrict__ Wa,
                                    __half* __restrict__ Wt)
{
    __shared__ float t[32][33];
    int nx = blockIdx.x * 32;
    int ky = blockIdx.y * 32;
    int tx = threadIdx.x, ty = threadIdx.y;
#pragma unroll
    for (int i = 0; i < 32; i += 8) {
        int n = nx + tx, k = ky + ty + i;
        float v;
        if      (n < B2_OFF) v = Wqkv[(size_t)k * CONVDIM + n];
        else if (n < A2_OFF) v = Wb[k * 32 + (n - B2_OFF)];
        else if (n < QB_N)   v = Wa[k * 32 + (n - A2_OFF)];
        else                 v = 0.f;
        t[ty + i][tx] = v;
    }
    __syncthreads();
#pragma unroll
    for (int i = 0; i < 32; i += 8) {
        int n = nx + ty + i, k = ky + tx;
        Wt[(size_t)n * DMODEL + k] = __float2half_rn(t[tx][ty + i]);
    }
}

// generic transpose+cvt: src[R][C] fp32 -> dst[C][R] half
__global__ void packT_f16_kernel(const float* __restrict__ src,
                                 __half* __restrict__ dst, int R, int C)
{
    __shared__ float t[32][33];
    int cx = blockIdx.x * 32;
    int ry = blockIdx.y * 32;
    int tx = threadIdx.x, ty = threadIdx.y;
#pragma unroll
    for (int i = 0; i < 32; i += 8)
        t[ty + i][tx] = src[(size_t)(ry + ty + i) * C + cx + tx];
    __syncthreads();
#pragma unroll
    for (int i = 0; i < 32; i += 8)
        dst[(size_t)(cx + ty + i) * R + ry + tx] = __float2half_rn(t[tx][ty + i]);
}

// ---------------------------------------------------------------------------
// Causal depthwise conv (KC=4) + SiLU + split, chunked over rows.
// ---------------------------------------------------------------------------
__global__ void conv_silu_split_kernel(const float* __restrict__ proj,
                                       const float* __restrict__ conv_w,
                                       float* __restrict__ q,
                                       float* __restrict__ k,
                                       float* __restrict__ v,
                                       long row0, int t0, int nrows)
{
    size_t idx = (size_t)blockIdx.x * blockDim.x + threadIdx.x;
    if (idx >= (size_t)nrows * CONVDIM) return;
    int c = (int)(idx & (CONVDIM - 1));
    int r = (int)(idx >> 13);
    size_t bt = (size_t)row0 + r;
    int t = t0 + r;

    float4 w = *(const float4*)(conv_w + (size_t)c * 4);
    const float* base = proj + c;
    float x0 = (t >= 3) ? base[(bt - 3) * QB_N] : 0.f;
    float x1 = (t >= 2) ? base[(bt - 2) * QB_N] : 0.f;
    float x2 = (t >= 1) ? base[(bt - 1) * QB_N] : 0.f;
    float x3 = base[bt * QB_N];

    float acc = x0 * w.x + x1 * w.y + x2 * w.z + x3 * w.w;
    float s = acc / (1.f + expf(-acc));

    if (c < KEYDIM)           q[bt * KEYDIM + c] = s;
    else if (c < 2 * KEYDIM)  k[bt * KEYDIM + (c - KEYDIM)] = s;
    else                      v[bt * VALDIM + (c - 2 * KEYDIM)] = s;
}

// ---------------------------------------------------------------------------
// L2 norm over DK=128 (one warp per row); q gets extra DK^-0.5 (chunked)
// ---------------------------------------------------------------------------
__global__ void l2norm_qk_kernel(float* __restrict__ q, float* __restrict__ k,
                                 int nrows)
{
    int wg   = (blockIdx.x * blockDim.x + threadIdx.x) >> 5;
    int lane = threadIdx.x & 31;
    if (wg >= 2 * nrows) return;

    float* base;
    float extra;
    if (wg < nrows) { base = q + (size_t)wg * DK; extra = 0.08838834764831845f; }
    else            { base = k + (size_t)(wg - nrows) * DK; extra = 1.f; }

    float4 x = ((float4*)base)[lane];
    float ss = x.x*x.x + x.y*x.y + x.z*x.z + x.w*x.w;
#pragma unroll
    for (int off = 16; off > 0; off >>= 1)
        ss += __shfl_xor_sync(0xffffffffu, ss, off);
    float inv = rsqrtf(ss + 1e-6f) * extra;
    x.x *= inv; x.y *= inv; x.z *= inv; x.w *= inv;
    ((float4*)base)[lane] = x;
}

// ---------------------------------------------------------------------------
// beta/decay (chunked)
// ---------------------------------------------------------------------------
__global__ void beta_decay_kernel(const float* __restrict__ proj,
                                  const float* __restrict__ dt_bias,
                                  const float* __restrict__ A_log,
                                  float* __restrict__ beta,
                                  float* __restrict__ decay,
                                  long row0, int nrows)
{
    int idx = blockIdx.x * blockDim.x + threadIdx.x;
    if (idx >= nrows * NVH) return;
    int h = idx & (NVH - 1);
    size_t bt = (size_t)row0 + (idx >> 5);
    float b = proj[bt * QB_N + B2_OFF + h];
    beta[bt * NVH + h] = 1.f / (1.f + expf(-b));
    float a = proj[bt * QB_N + A2_OFF + h] + dt_bias[h];
    float sp = (a > 20.f) ? a : log1pf(expf(a));
    decay[bt * NVH + h] = expf(-expf(A_log[h]) * sp);
}

// ---------------------------------------------------------------------------
// Gated delta rule scan — chunked over [t0, t1), state checkpointed globally.
// ---------------------------------------------------------------------------
__global__ void __launch_bounds__(128) scan_kernel(
    const float* __restrict__ qn, const float* __restrict__ kn,
    const float* __restrict__ v,  const float* __restrict__ decay,
    const float* __restrict__ beta, float* __restrict__ o,
    float* __restrict__ Sst, int t0, int t1)
{
    const int blk = blockIdx.x;
    const int b   = blk >> 6;
    const int rem = blk & 63;
    const int h   = rem >> 1;
    const int seg = rem & 1;
    const int h2  = h >> 1;
    const int tid = threadIdx.x;
    const int col  = tid >> 1;
    const int half = tid & 1;
    const int gcol = seg * 64 + col;
    const int koff = half * 64;

    __shared__ float sq[128];
    __shared__ float sk[128];

    float* Sg = Sst + (size_t)blk * (64 * 128);

    float S[64];
    if (t0 == 0) {
#pragma unroll
        for (int i = 0; i < 64; i++) S[i] = 0.f;
    } else {
#pragma unroll
        for (int i = 0; i < 64; i++) S[i] = Sg[i * 128 + tid];
    }

    const size_t bt0 = (size_t)b * TLEN;

    float pq = qn[((bt0 + t0)*NKH + h2) * DK + tid];
    float pk = kn[((bt0 + t0)*NKH + h2) * DK + tid];
    float pv = v [((bt0 + t0)*NVH + h ) * DV + gcol];
    float pd = decay[(bt0 + t0) * NVH + h];
    float pb = beta [(bt0 + t0) * NVH + h];

    for (int t = t0; t < t1; t++) {
        __syncthreads();
        sq[tid] = pq;
        sk[tid] = pk;
        float cv = pv, cd = pd, cb = pb;
        __syncthreads();

        if (t + 1 < t1) {
            size_t bt = bt0 + t + 1;
            pq = qn[(bt*NKH + h2) * DK + tid];
            pk = kn[(bt*NKH + h2) * DK + tid];
            pv = v [(bt*NVH + h ) * DV + gcol];
            pd = decay[bt * NVH + h];
            pb = beta [bt * NVH + h];
        }

        float a0 = 0.f, a1 = 0.f, a2 = 0.f, a3 = 0.f;
#pragma unroll
        for (int i = 0; i < 64; i += 4) {
            S[i+0] *= cd; a0 = fmaf(sk[koff+i+0], S[i+0], a0);
            S[i+1] *= cd; a1 = fmaf(sk[koff+i+1], S[i+1], a1);
            S[i+2] *= cd; a2 = fmaf(sk[koff+i+2], S[i+2], a2);
            S[i+3] *= cd; a3 = fmaf(sk[koff+i+3], S[i+3], a3);
        }
        float kS = (a0 + a1) + (a2 + a3);
        kS += __shfl_xor_sync(0xffffffffu, kS, 1);

        float upd = cb * (cv - kS);

        float o0 = 0.f, o1 = 0.f, o2 = 0.f, o3 = 0.f;
#pragma unroll
        for (int i = 0; i < 64; i += 4) {
            S[i+0] = fmaf(sk[koff+i+0], upd, S[i+0]); o0 = fmaf(sq[koff+i+0], S[i+0], o0);
            S[i+1] = fmaf(sk[koff+i+1], upd, S[i+1]); o1 = fmaf(sq[koff+i+1], S[i+1], o1);
            S[i+2] = fmaf(sk[koff+i+2], upd, S[i+2]); o2 = fmaf(sq[koff+i+2], S[i+2], o2);
            S[i+3] = fmaf(sk[koff+i+3], upd, S[i+3]); o3 = fmaf(sq[koff+i+3], S[i+3], o3);
        }
        float oa = (o0 + o1) + (o2 + o3);
        oa += __shfl_xor_sync(0xffffffffu, oa, 1);
        if (!half)
            o[((bt0 + t)*NVH + h) * DV + gcol] = oa;
    }

    if (t1 < TLEN) {
#pragma unroll
        for (int i = 0; i < 64; i++) Sg[i * 128 + tid] = S[i];
    }
}

// ---------------------------------------------------------------------------
// Gated RMSNorm over nrows rows (pointers pre-offset); emits half
// ---------------------------------------------------------------------------
__global__ void gate_kernel(const float* __restrict__ o, const float* __restrict__ z,
                            const float* __restrict__ norm_w, __half* __restrict__ oh,
                            int nrows)
{
    int wg   = (blockIdx.x * blockDim.x + threadIdx.x) >> 5;
    int lane = threadIdx.x & 31;
    if (wg >= nrows) return;

    float4 x = ((const float4*)(o + (size_t)wg * DV))[lane];
    float ss = x.x*x.x + x.y*x.y + x.z*x.z + x.w*x.w;
#pragma unroll
    for (int off = 16; off > 0; off >>= 1)
        ss += __shfl_xor_sync(0xffffffffu, ss, off);
    float r = rsqrtf(ss * (1.f / DV) + 1e-6f);

    float4 zv = ((const float4*)(z + (size_t)wg * DV))[lane];
    float4 nw = ((const float4*)norm_w)[lane];

    float s0 = zv.x / (1.f + expf(-zv.x));
    float s1 = zv.y / (1.f + expf(-zv.y));
    float s2 = zv.z / (1.f + expf(-zv.z));
    float s3 = zv.w / (1.f + expf(-zv.w));

    __half2* dst = (__half2*)(oh + (size_t)wg * DV) + 2 * lane;
    dst[0] = __floats2half2_rn(x.x * r * nw.x * s0, x.y * r * nw.y * s1);
    dst[1] = __floats2half2_rn(x.z * r * nw.z * s2, x.w * r * nw.w * s3);
}

// ---------------------------------------------------------------------------
// Launch: fully chunked pipeline with capture-clean fork/join.
//   s0: root fork -> prepasses -> scan chunks
//   s1: feed chunks (GEMM+conv+l2norm+beta) + z chunk each iteration
//   s2: wz/wout packs -> per-chunk gate + out-GEMM
// ---------------------------------------------------------------------------
extern "C" void kernel_launch(void* const* d_in, const int* in_sizes, int n_in,
                              void* d_out, int out_size)
{
    const float* hs      = (const float*)d_in[0];
    const float* W_qkv   = (const float*)d_in[1];
    const float* W_z     = (const float*)d_in[2];
    const float* W_b     = (const float*)d_in[3];
    const float* W_a     = (const float*)d_in[4];
    const float* conv_w  = (const float*)d_in[5];
    const float* dt_bias = (const float*)d_in[6];
    const float* A_log   = (const float*)d_in[7];
    const float* norm_w  = (const float*)d_in[8];
    const float* W_out   = (const float*)d_in[9];
    float* out = (float*)d_out;

    float *qkvba, *z, *q, *k, *v, *beta, *decay, *o, *Sst;
    __half *hs_h, *wqkvbaT, *wzT, *woutT, *oh;
    cudaGetSymbolAddress((void**)&qkvba,   g_qkvba);
    cudaGetSymbolAddress((void**)&z,       g_z);
    cudaGetSymbolAddress((void**)&q,       g_q);
    cudaGetSymbolAddress((void**)&k,       g_k);
    cudaGetSymbolAddress((void**)&v,       g_v);
    cudaGetSymbolAddress((void**)&beta,    g_beta);
    cudaGetSymbolAddress((void**)&decay,   g_decay);
    cudaGetSymbolAddress((void**)&o,       g_o);
    cudaGetSymbolAddress((void**)&Sst,     g_S);
    cudaGetSymbolAddress((void**)&hs_h,    g_hs_h);
    cudaGetSymbolAddress((void**)&wqkvbaT, g_wqkvbaT);
    cudaGetSymbolAddress((void**)&wzT,     g_wzT);
    cudaGetSymbolAddress((void**)&woutT,   g_woutT);
    cudaGetSymbolAddress((void**)&oh,      g_oh);

    static cudaStream_t s1 = nullptr, s2 = nullptr;
    static cudaEvent_t ev_root = nullptr, ev_in = nullptr, ev_wz = nullptr;
    static cudaEvent_t ev_feed[NCHUNK] = {}, ev_scan[NCHUNK] = {}, ev_z[NCHUNK] = {};
    static cudaEvent_t ev_done = nullptr, ev_s1done = nullptr;
    static bool init_done = false;
    if (!init_done) {
        cudaStreamCreateWithFlags(&s1, cudaStreamNonBlocking);
        cudaStreamCreateWithFlags(&s2, cudaStreamNonBlocking);
        cudaEventCreateWithFlags(&ev_root, cudaEventDisableTiming);
        cudaEventCreateWithFlags(&ev_in,   cudaEventDisableTiming);
        cudaEventCreateWithFlags(&ev_wz,   cudaEventDisableTiming);
        for (int c = 0; c < NCHUNK; c++) {
            cudaEventCreateWithFlags(&ev_feed[c], cudaEventDisableTiming);
            cudaEventCreateWithFlags(&ev_scan[c], cudaEventDisableTiming);
            cudaEventCreateWithFlags(&ev_z[c],    cudaEventDisableTiming);
        }
        cudaEventCreateWithFlags(&ev_done,   cudaEventDisableTiming);
        cudaEventCreateWithFlags(&ev_s1done, cudaEventDisableTiming);
        cudaFuncSetAttribute(gemm_f16_kernel,
                             cudaFuncAttributeMaxDynamicSharedMemorySize, GEMM_SMEM);
        init_done = true;
    }

    const cudaStream_t s0 = 0;
    dim3 tb32(32, 8);

    // ---- capture-clean fork: side streams join the graph FIRST ----
    cudaEventRecord(ev_root, s0);
    cudaStreamWaitEvent(s1, ev_root, 0);
    cudaStreamWaitEvent(s2, ev_root, 0);

    // ---- s2: wz / wout weight packs ----
    {
        dim3 gz(VALDIM / 32, DMODEL / 32);
        packT_f16_kernel<<<gz, tb32, 0, s2>>>(W_z, wzT, DMODEL, VALDIM);
        cudaEventRecord(ev_wz, s2);
        dim3 go(DMODEL / 32, VALDIM / 32);
        packT_f16_kernel<<<go, tb32, 0, s2>>>(W_out, woutT, VALDIM, DMODEL);
    }

    // ---- s0: input prepasses ----
    {
        size_t n4 = (size_t)BT * DMODEL / 4;
        cvt_f16_kernel<<<(unsigned)((n4 + 255) / 256), 256, 0, s0>>>(hs, hs_h, n4);
        dim3 gq(QBT_NP / 32, DMODEL / 32);
        pack_wqkvbaT_kernel<<<gq, tb32, 0, s0>>>(W_qkv, W_b, W_a, wqkvbaT);
        cudaEventRecord(ev_in, s0);
    }

    // ---- s1: chunked feed pipeline (+ z chunk each iteration) ----
    cudaStreamWaitEvent(s1, ev_in, 0);
    cudaStreamWaitEvent(s1, ev_wz, 0);
    for (int c = 0; c < NCHUNK; c++) {
        const int t0 = c * TC;
        for (int b = 0; b < BATCH; b++) {
            const long row0 = (long)b * TLEN + t0;
            launch_gemm(hs_h + (size_t)row0 * DMODEL, wqkvbaT,
                        qkvba + (size_t)row0 * QB_N, TC, QB_N, DMODEL, s1);
        }
        for (int b = 0; b < BATCH; b++) {
            const long row0 = (long)b * TLEN + t0;
            size_t n = (size_t)TC * CONVDIM;
            conv_silu_split_kernel<<<(unsigned)((n + 255) / 256), 256, 0, s1>>>(
                qkvba, conv_w, q, k, v, row0, t0, TC);
        }
        for (int b = 0; b < BATCH; b++) {
            const long row0 = (long)b * TLEN + t0;
            int hr = TC * NKH;
            l2norm_qk_kernel<<<(2 * hr + 7) / 8, 256, 0, s1>>>(
                q + (size_t)row0 * KEYDIM, k + (size_t)row0 * KEYDIM, hr);
        }
        for (int b = 0; b < BATCH; b++) {
            const long row0 = (long)b * TLEN + t0;
            beta_decay_kernel<<<(TC * NVH + 255) / 256, 256, 0, s1>>>(
                qkvba, dt_bias, A_log, beta, decay, row0, TC);
        }
        cudaEventRecord(ev_feed[c], s1);

        for (int b = 0; b < BATCH; b++) {
            const long row0 = (long)b * TLEN + t0;
            launch_gemm(hs_h + (size_t)row0 * DMODEL, wzT,
                        z + (size_t)row0 * VALDIM, TC, VALDIM, DMODEL, s1);
        }
        cudaEventRecord(ev_z[c], s1);
    }
    cudaEventRecord(ev_s1done, s1);

    // ---- s0: scan chunks ----
    for (int c = 0; c < NCHUNK; c++) {
        cudaStreamWaitEvent(s0, ev_feed[c], 0);
        scan_kernel<<<BATCH * NVH * 2, 128, 0, s0>>>(
            q, k, v, decay, beta, o, Sst, c * TC, (c + 1) * TC);
        cudaEventRecord(ev_scan[c], s0);
    }

    // ---- s2: gate + out-projection per chunk ----
    for (int c = 0; c < NCHUNK; c++) {
        cudaStreamWaitEvent(s2, ev_scan[c], 0);
        cudaStreamWaitEvent(s2, ev_z[c], 0);
        for (int b = 0; b < BATCH; b++) {
            const size_t row0 = (size_t)b * TLEN + c * TC;
            const int rows = TC * NVH;
            gate_kernel<<<(rows + 7) / 8, 256, 0, s2>>>(
                o + row0 * VALDIM, z + row0 * VALDIM, norm_w, oh + row0 * VALDIM, rows);
            launch_gemm(oh + row0 * VALDIM, woutT, out + row0 * DMODEL,
                        TC, DMODEL, VALDIM, s2);
        }
    }

    // ---- join everything back to s0 ----
    cudaEventRecord(ev_done, s2);
    cudaStreamWaitEvent(s0, ev_done, 0);
    cudaStreamWaitEvent(s0, ev_s1done, 0);
}